// round 3
// baseline (speedup 1.0000x reference)
#include <cuda_runtime.h>
#include <math.h>

#define NT 128
#define NB 256
#define NC 512
#define HID 256
#define EMB 128
#define NCLS 37
#define NSTEPS 25
#define POSE 256
#define RNN_IN 1472
#define GRU3 768
#define NCTA 592
#define NWARP (NCTA * 8)

// ---------------- scratch ----------------
__device__ float g_fp[NT * NB * HID];
__device__ float g_poseT[NT * NB * POSE];
__device__ float g_hp[NB * HID];
__device__ float g_gh[NB * GRU3];
__device__ float g_e[NB * NT];
__device__ float g_x[NB * RNN_IN];
__device__ float g_gipart[3][NB * GRU3];
__device__ float g_hidden[NB * HID];
__device__ float g_hs[NSTEPS * NB * HID];
__device__ unsigned g_arrive;
__device__ volatile unsigned g_release;

// ---------------- grid barrier ----------------
__device__ __forceinline__ void gbar() {
    __threadfence();
    __syncthreads();
    if (threadIdx.x == 0) {
        unsigned gen = g_release;
        unsigned a = atomicAdd(&g_arrive, 1u);
        if (a == NCTA - 1u) {
            g_arrive = 0u;
            __threadfence();
            g_release = gen + 1u;
        } else {
            while (g_release == gen) { }
        }
        __threadfence();
    }
    __syncthreads();
}

// ---------------- f32x2 helpers ----------------
__device__ __forceinline__ unsigned long long pk2(float lo, float hi) {
    unsigned long long r;
    asm("mov.b64 %0,{%1,%2};" : "=l"(r) : "f"(lo), "f"(hi));
    return r;
}
__device__ __forceinline__ void fma2(unsigned long long& d, unsigned long long a,
                                     unsigned long long b) {
    asm("fma.rn.f32x2 %0,%1,%2,%0;" : "+l"(d) : "l"(a), "l"(b));
}
__device__ __forceinline__ void up2(unsigned long long v, float& a, float& b) {
    asm("mov.b64 {%0,%1},%2;" : "=f"(a), "=f"(b) : "l"(v));
}

// ---------------- fast transcendentals ----------------
__device__ __forceinline__ float ftanh(float x) {
    float e = __expf(2.f * x);
    return 1.f - __fdividef(2.f, e + 1.f);
}
__device__ __forceinline__ float fsig(float x) {
    return __fdividef(1.f, 1.f + __expf(-x));
}

// ---------------- 32x32 tile GEMM (C = A@B^T + bias), packed f32x2 ----------------
__device__ __forceinline__ void gemm_t32(const float* __restrict__ A, int lda,
                                         const float* __restrict__ B, int ldb,
                                         const float* __restrict__ bias,
                                         float* __restrict__ C, int ldc,
                                         int m0, int n0, int kbase, int kiters,
                                         float* sm, int tid)
{
    float* As = sm;            // [32][34]
    float* Bs = sm + 32 * 34;  // [32][34]
    const int ty = tid >> 4, tx = tid & 15;
    unsigned long long acc0 = 0ull, acc1 = 0ull;
    const int row = tid >> 3, kk = (tid & 7) * 4;
    const float* Ag = A + (size_t)(m0 + row) * lda + kbase + kk;
    const float* Bg = B + (size_t)(n0 + row) * ldb + kbase + kk;
    for (int kc = 0; kc < kiters; kc++) {
        float4 av = *(const float4*)(Ag + kc * 32);
        float4 bv = *(const float4*)(Bg + kc * 32);
        As[(kk + 0) * 34 + row] = av.x; As[(kk + 1) * 34 + row] = av.y;
        As[(kk + 2) * 34 + row] = av.z; As[(kk + 3) * 34 + row] = av.w;
        Bs[(kk + 0) * 34 + row] = bv.x; Bs[(kk + 1) * 34 + row] = bv.y;
        Bs[(kk + 2) * 34 + row] = bv.z; Bs[(kk + 3) * 34 + row] = bv.w;
        __syncthreads();
#pragma unroll
        for (int k = 0; k < 32; k++) {
            float2 a = *(const float2*)&As[k * 34 + ty * 2];
            unsigned long long pb = *(const unsigned long long*)&Bs[k * 34 + tx * 2];
            fma2(acc0, pk2(a.x, a.x), pb);
            fma2(acc1, pk2(a.y, a.y), pb);
        }
        __syncthreads();
    }
    float c00, c01, c10, c11;
    up2(acc0, c00, c01); up2(acc1, c10, c11);
    int gm = m0 + ty * 2, gn = n0 + tx * 2;
    float b0 = bias ? bias[gn] : 0.f, b1 = bias ? bias[gn + 1] : 0.f;
    C[(size_t)gm * ldc + gn]           = c00 + b0;
    C[(size_t)gm * ldc + gn + 1]       = c01 + b1;
    C[(size_t)(gm + 1) * ldc + gn]     = c10 + b0;
    C[(size_t)(gm + 1) * ldc + gn + 1] = c11 + b1;
}

// ---------------- 32x64 tile GEMM (no bias), packed f32x2 ----------------
__device__ __forceinline__ void gemm_t32x64(const float* __restrict__ A, int lda,
                                            const float* __restrict__ B, int ldb,
                                            float* __restrict__ C, int ldc,
                                            int m0, int n0, int kbase, int kiters,
                                            float* sm, int tid)
{
    float* As = sm;            // [32][34]
    float* Bs = sm + 32 * 34;  // [32][68]
    const int ty = tid >> 4, tx = tid & 15;
    unsigned long long a00 = 0ull, a01 = 0ull, a10 = 0ull, a11 = 0ull;
    const int arow = tid >> 3, akk = (tid & 7) * 4;
    const int brow = tid >> 2, bkk = (tid & 3) * 8;
    const float* Ag = A + (size_t)(m0 + arow) * lda + kbase + akk;
    const float* Bg = B + (size_t)(n0 + brow) * ldb + kbase + bkk;
    for (int kc = 0; kc < kiters; kc++) {
        float4 av = *(const float4*)(Ag + kc * 32);
        float4 b0 = *(const float4*)(Bg + kc * 32);
        float4 b1 = *(const float4*)(Bg + kc * 32 + 4);
        As[(akk + 0) * 34 + arow] = av.x; As[(akk + 1) * 34 + arow] = av.y;
        As[(akk + 2) * 34 + arow] = av.z; As[(akk + 3) * 34 + arow] = av.w;
        Bs[(bkk + 0) * 68 + brow] = b0.x; Bs[(bkk + 1) * 68 + brow] = b0.y;
        Bs[(bkk + 2) * 68 + brow] = b0.z; Bs[(bkk + 3) * 68 + brow] = b0.w;
        Bs[(bkk + 4) * 68 + brow] = b1.x; Bs[(bkk + 5) * 68 + brow] = b1.y;
        Bs[(bkk + 6) * 68 + brow] = b1.z; Bs[(bkk + 7) * 68 + brow] = b1.w;
        __syncthreads();
#pragma unroll
        for (int k = 0; k < 32; k++) {
            float2 a = *(const float2*)&As[k * 34 + ty * 2];
            ulonglong2 pb = *(const ulonglong2*)&Bs[k * 68 + tx * 4];
            unsigned long long pa0 = pk2(a.x, a.x), pa1 = pk2(a.y, a.y);
            fma2(a00, pa0, pb.x);
            fma2(a01, pa0, pb.y);
            fma2(a10, pa1, pb.x);
            fma2(a11, pa1, pb.y);
        }
        __syncthreads();
    }
    int gm = m0 + ty * 2, gn = n0 + tx * 4;
    float v0, v1;
    up2(a00, v0, v1); C[(size_t)gm * ldc + gn] = v0;     C[(size_t)gm * ldc + gn + 1] = v1;
    up2(a01, v0, v1); C[(size_t)gm * ldc + gn + 2] = v0; C[(size_t)gm * ldc + gn + 3] = v1;
    up2(a10, v0, v1); C[(size_t)(gm+1) * ldc + gn] = v0;     C[(size_t)(gm+1) * ldc + gn + 1] = v1;
    up2(a11, v0, v1); C[(size_t)(gm+1) * ldc + gn + 2] = v0; C[(size_t)(gm+1) * ldc + gn + 3] = v1;
}

// ---------------- feats_proj GEMM: (32768,512)@(256,512)^T, f32x2 ----------------
__global__ __launch_bounds__(256) void fp_gemm(const float* __restrict__ A,
                                               const float* __restrict__ B)
{
    __shared__ __align__(16) float As[16 * 132];
    __shared__ __align__(16) float Bs[16 * 132];
    const int tid = threadIdx.x;
    const int m0 = blockIdx.y * 128;
    const int n0 = blockIdx.x * 128;
    const int ty = tid >> 4, tx = tid & 15;
    unsigned long long acc[8][4];
#pragma unroll
    for (int i = 0; i < 8; i++)
#pragma unroll
        for (int j = 0; j < 4; j++) acc[i][j] = 0ull;

    for (int k0 = 0; k0 < NC; k0 += 16) {
#pragma unroll
        for (int p = 0; p < 8; p++) {
            int i = p * 256 + tid;
            int kk = i & 15, mm = i >> 4;
            As[kk * 132 + mm] = A[(size_t)(m0 + mm) * NC + k0 + kk];
            Bs[kk * 132 + mm] = B[(size_t)(n0 + mm) * NC + k0 + kk];
        }
        __syncthreads();
#pragma unroll
        for (int k = 0; k < 16; k++) {
            float4 x0 = *(const float4*)&As[k * 132 + ty * 8];
            float4 x1 = *(const float4*)&As[k * 132 + ty * 8 + 4];
            ulonglong2 q0 = *(const ulonglong2*)&Bs[k * 132 + tx * 8];
            ulonglong2 q1 = *(const ulonglong2*)&Bs[k * 132 + tx * 8 + 4];
            float av[8] = {x0.x, x0.y, x0.z, x0.w, x1.x, x1.y, x1.z, x1.w};
            unsigned long long pb[4] = {q0.x, q0.y, q1.x, q1.y};
#pragma unroll
            for (int i = 0; i < 8; i++) {
                unsigned long long pa = pk2(av[i], av[i]);
#pragma unroll
                for (int j = 0; j < 4; j++) fma2(acc[i][j], pa, pb[j]);
            }
        }
        __syncthreads();
    }
#pragma unroll
    for (int i = 0; i < 8; i++) {
        int gm = m0 + ty * 8 + i;
#pragma unroll
        for (int j = 0; j < 4; j++) {
            float lo, hi;
            up2(acc[i][j], lo, hi);
            g_fp[(size_t)gm * HID + n0 + tx * 8 + 2 * j]     = lo;
            g_fp[(size_t)gm * HID + n0 + tx * 8 + 2 * j + 1] = hi;
        }
    }
}

// ---------------- persistent decode kernel ----------------
__global__ __launch_bounds__(256, 4) void decode_kernel(
    const float* __restrict__ feats,
    const float* __restrict__ pose,
    const float* __restrict__ pyr0,
    const float* __restrict__ pyr1,
    const float* __restrict__ pyr2,
    const int*   __restrict__ text,
    const float* __restrict__ h2h_w,    const float* __restrict__ h2h_b,
    const float* __restrict__ score_w,
    const float* __restrict__ pose_w,   const float* __restrict__ pose_b,
    const float* __restrict__ gru_w_ih, const float* __restrict__ gru_w_hh,
    const float* __restrict__ gru_b_ih, const float* __restrict__ gru_b_hh,
    const float* __restrict__ char_emb,
    const float* __restrict__ gen_w,    const float* __restrict__ gen_b,
    float* __restrict__ out)
{
    __shared__ __align__(16) float sm[3264];
    __shared__ float s_coord[4];
    __shared__ float s_ly[3][2], s_lx[3][2];
    __shared__ int   s_y0[3][2], s_y1[3][2], s_x0[3][2], s_x1[3][2];
    __shared__ int   s_vy[3][2], s_vx[3][2];

    const int tid = threadIdx.x;
    const int bid = blockIdx.x;
    const int lane = tid & 31;
    const int wid = tid >> 5;

    // ---- prologue: hidden = 0, pose transpose ----
    if (bid < 256) g_hidden[bid * 256 + tid] = 0.f;
    for (int job = bid; job < NB * 32; job += NCTA) {
        int b = job >> 5;
        int r = job & 31;
        int t0 = (r & 3) * 32;
        int p0 = (r >> 2) * 32;
        int y = tid >> 5, x = tid & 31;
#pragma unroll
        for (int q = 0; q < 4; q++) {
            int yy = y + q * 8;
            sm[yy * 33 + x] = pose[((size_t)b * POSE + (p0 + yy)) * NT + (t0 + x)];
        }
        __syncthreads();
#pragma unroll
        for (int q = 0; q < 4; q++) {
            int yy = y + q * 8;
            g_poseT[((size_t)(t0 + yy) * NB + b) * POSE + (p0 + x)] = sm[x * 33 + yy];
        }
        __syncthreads();
    }
    gbar();

    // score_w cached per lane
    float swr[8];
#pragma unroll
    for (int q = 0; q < 8; q++) swr[q] = score_w[lane + 32 * q];

    for (int step = 0; step < NSTEPS; step++) {
        // ===== A: hp = hidden@h2h^T+b (64 tiles) ; gh = hidden@Whh^T+b (192 tiles)
        if (bid < 64) {
            gemm_t32(g_hidden, HID, h2h_w, HID, h2h_b, g_hp, HID,
                     (bid >> 3) * 32, (bid & 7) * 32, 0, 8, sm, tid);
        } else if (bid < 256) {
            int j = bid - 64;
            gemm_t32(g_hidden, HID, gru_w_hh, HID, gru_b_hh, g_gh, GRU3,
                     (j / 24) * 32, (j % 24) * 32, 0, 8, sm, tid);
        }
        gbar();

        // ===== B: energies, full grid (warp per (t,b)) =====
        for (int job = bid * 8 + wid; job < NT * NB; job += NWARP) {
            int b = job & (NB - 1);
            int t = job >> 8;
            const float* fp = g_fp + ((size_t)t * NB + b) * HID;
            const float* hpp = g_hp + (size_t)b * HID;
            float s = 0.f;
#pragma unroll
            for (int q = 0; q < 8; q++) {
                int h = lane + 32 * q;
                s += ftanh(fp[h] + hpp[h]) * swr[q];
            }
#pragma unroll
            for (int o = 16; o; o >>= 1) s += __shfl_xor_sync(~0u, s, o);
            if (!lane) g_e[b * NT + t] = s;
        }
        gbar();

        // ===== C: softmax (redundant) + ctx chunks, full grid =====
        {
            float* e_s = sm;
            float* red = sm + 128;
            float* al  = sm + 256;
            for (int job = bid; job < NB * 3; job += NCTA) {
                int b = job / 3, ch = job % 3;
                if (tid < NT) { float v = g_e[b * NT + tid]; e_s[tid] = v; red[tid] = v; }
                __syncthreads();
                for (int s = 64; s; s >>= 1) { if (tid < s) red[tid] = fmaxf(red[tid], red[tid + s]); __syncthreads(); }
                float mx = red[0];
                __syncthreads();
                if (tid < NT) { float ex = __expf(e_s[tid] - mx); al[tid] = ex; red[tid] = ex; }
                __syncthreads();
                for (int s = 64; s; s >>= 1) { if (tid < s) red[tid] += red[tid + s]; __syncthreads(); }
                float inv = __fdividef(1.f, red[0]);
                __syncthreads();
                int c = ch * 256 + tid;
                const float* src; size_t stride;
                if (c < NC) { src = feats + (size_t)b * NC + c;            stride = (size_t)NB * NC; }
                else        { src = g_poseT + (size_t)b * POSE + (c - NC); stride = (size_t)NB * POSE; }
                float acc = 0.f;
#pragma unroll 8
                for (int t = 0; t < NT; t++) acc += al[t] * src[(size_t)t * stride];
                g_x[(size_t)b * RNN_IN + c] = acc * inv;
                __syncthreads();
            }
        }
        gbar();

        // ===== D: misc (coord/crops/emb) on 256 CTAs + gi K0 GEMM on 96 CTAs =====
        if (bid < 256) {
            int b = bid;
            const float* ctx = g_x + (size_t)b * RNN_IN;
            if (wid < 4) {
                const float* pw = pose_w + wid * 768;
                float s = 0.f;
#pragma unroll
                for (int q = 0; q < 24; q++) { int c = lane + q * 32; s += ctx[c] * pw[c]; }
#pragma unroll
                for (int o = 16; o; o >>= 1) s += __shfl_xor_sync(~0u, s, o);
                if (!lane) s_coord[wid] = fsig(s + pose_b[wid]);
            }
            int tgt = (step == 0) ? 0 : (text[b * NSTEPS + (step - 1)] + 1);
            if (tid < EMB) g_x[(size_t)b * RNN_IN + 768 + tid] = char_emb[(size_t)tgt * EMB + tid];
            __syncthreads();
            if (tid == 0) {
                const int Hs[3] = {16, 8, 4};
                const int Ws[3] = {128, 64, 65};
                float c0 = s_coord[0], c1 = s_coord[1], c2 = s_coord[2], c3 = s_coord[3];
                for (int p = 0; p < 3; p++) {
                    float Hf = (float)Hs[p], Wf = (float)Ws[p];
                    c0 *= Hf; c1 *= Wf; c2 *= Hf; c3 *= Wf;
                    float x1 = c0, y1 = c1, x2 = c2, y2 = c3;
                    float bw = fmaxf(x2 - x1, 1.f) * 0.5f;
                    float bh = fmaxf(y2 - y1, 1.f) * 0.5f;
#pragma unroll
                    for (int i = 0; i < 2; i++) {
                        float ys = y1 + (0.5f + (float)i) * bh;
                        s_vy[p][i] = (ys >= -1.f && ys <= Hf) ? 1 : 0;
                        float y = fminf(fmaxf(ys, 0.f), Hf - 1.f);
                        float y0f = floorf(y);
                        int y0i = (int)y0f;
                        s_y0[p][i] = y0i;
                        s_y1[p][i] = min(y0i + 1, Hs[p] - 1);
                        s_ly[p][i] = y - y0f;
                        float xs = x1 + (0.5f + (float)i) * bw;
                        s_vx[p][i] = (xs >= -1.f && xs <= Wf) ? 1 : 0;
                        float x = fminf(fmaxf(xs, 0.f), Wf - 1.f);
                        float x0f = floorf(x);
                        int x0i = (int)x0f;
                        s_x0[p][i] = x0i;
                        s_x1[p][i] = min(x0i + 1, Ws[p] - 1);
                        s_lx[p][i] = x - x0f;
                    }
                }
            }
            __syncthreads();
            for (int o = tid; o < 576; o += 256) {
                int p, local;
                if (o < 64)       { p = 0; local = o; }
                else if (o < 320) { p = 1; local = o - 64; }
                else              { p = 2; local = o - 320; }
                int c = local >> 2;
                int ij = local & 3;
                int i = ij >> 1, j = ij & 1;
                float val = 0.f;
                if (s_vy[p][i] && s_vx[p][j]) {
                    float ly = s_ly[p][i], lx = s_lx[p][j];
                    float hy = 1.f - ly, hx = 1.f - lx;
                    int y0 = s_y0[p][i], y1 = s_y1[p][i];
                    int x0 = s_x0[p][j], x1 = s_x1[p][j];
                    const float* f; int W, HW;
                    if (p == 0)      { f = pyr0; W = 128; HW = 16 * 128; }
                    else if (p == 1) { f = pyr1; W = 64;  HW = 8 * 64;  }
                    else             { f = pyr2; W = 65;  HW = 4 * 65;  }
                    const float* fc = f + (size_t)c * HW;
                    val = fc[y0 * W + x0] * (hy * hx)
                        + fc[y0 * W + x1] * (hy * lx)
                        + fc[y1 * W + x0] * (ly * hx)
                        + fc[y1 * W + x1] * (ly * lx);
                }
                g_x[(size_t)b * RNN_IN + 896 + o] = val;
            }
        } else if (bid < 352) {
            int j = bid - 256;  // 96 tiles: 8 m x 12 n, K=[0,768)
            gemm_t32x64(g_x, RNN_IN, gru_w_ih, RNN_IN, g_gipart[0], GRU3,
                        (j / 12) * 32, (j % 12) * 64, 0, 24, sm, tid);
        }
        gbar();

        // ===== E: gi K1 (emb+crops region), 2-way split-K =====
        if (bid < 192) {
            int ks = bid / 96, j = bid % 96;
            gemm_t32x64(g_x, RNN_IN, gru_w_ih, RNN_IN, g_gipart[1 + ks], GRU3,
                        (j / 12) * 32, (j % 12) * 64, 768 + ks * 352, 11, sm, tid);
        }
        gbar();

        // ===== F: reduce partials + GRU =====
        if (bid < 256) {
            int g = bid * 256 + tid;
            int b = g >> 8, h = g & 255;
            size_t base = (size_t)b * GRU3;
            float ir = g_gipart[0][base + h] + g_gipart[1][base + h] + g_gipart[2][base + h] + gru_b_ih[h];
            float iz = g_gipart[0][base + HID + h] + g_gipart[1][base + HID + h] + g_gipart[2][base + HID + h] + gru_b_ih[HID + h];
            float in = g_gipart[0][base + 2*HID + h] + g_gipart[1][base + 2*HID + h] + g_gipart[2][base + 2*HID + h] + gru_b_ih[2*HID + h];
            float hr = g_gh[base + h], hz = g_gh[base + HID + h], hn = g_gh[base + 2*HID + h];
            float rr = fsig(ir + hr);
            float zz = fsig(iz + hz);
            float nn = ftanh(in + rr * hn);
            float hold = g_hidden[g];
            float hnew = (1.f - zz) * nn + zz * hold;
            g_hidden[g] = hnew;
            g_hs[((size_t)b * NSTEPS + step) * HID + h] = hnew;
        }
        gbar();
    }

    // ===== final classifier =====
    {
        int gw = bid * 8 + wid;
        for (int m = gw; m < NB * NSTEPS; m += NWARP) {
            const float* hrow = g_hs + (size_t)m * HID;
            float a[8];
#pragma unroll
            for (int q = 0; q < 8; q++) a[q] = hrow[lane + q * 32];
            for (int n = 0; n < NCLS; n++) {
                const float* w = gen_w + (size_t)n * HID;
                float s = 0.f;
#pragma unroll
                for (int q = 0; q < 8; q++) s += a[q] * w[lane + q * 32];
#pragma unroll
                for (int o = 16; o; o >>= 1) s += __shfl_xor_sync(~0u, s, o);
                if (!lane) out[(size_t)m * NCLS + n] = s + gen_b[n];
            }
        }
    }
}

// ---------------- driver ----------------
extern "C" void kernel_launch(void* const* d_in, const int* in_sizes, int n_in,
                              void* d_out, int out_size)
{
    const float* feats    = (const float*)d_in[0];
    const float* pose     = (const float*)d_in[1];
    const float* pyr0     = (const float*)d_in[2];
    const float* pyr1     = (const float*)d_in[3];
    const float* pyr2     = (const float*)d_in[4];
    const int*   text     = (const int*)  d_in[6];
    const float* i2h_w    = (const float*)d_in[7];
    const float* h2h_w    = (const float*)d_in[8];
    const float* h2h_b    = (const float*)d_in[9];
    const float* score_w  = (const float*)d_in[10];
    const float* pose_w   = (const float*)d_in[11];
    const float* pose_b   = (const float*)d_in[12];
    const float* gru_w_ih = (const float*)d_in[13];
    const float* gru_w_hh = (const float*)d_in[14];
    const float* gru_b_ih = (const float*)d_in[15];
    const float* gru_b_hh = (const float*)d_in[16];
    const float* char_emb = (const float*)d_in[17];
    const float* gen_w    = (const float*)d_in[18];
    const float* gen_b    = (const float*)d_in[19];
    float* out = (float*)d_out;

    dim3 g1(2, 256);
    fp_gemm<<<g1, 256>>>(feats, i2h_w);

    decode_kernel<<<NCTA, 256>>>(feats, pose, pyr0, pyr1, pyr2, text,
                                 h2h_w, h2h_b, score_w, pose_w, pose_b,
                                 gru_w_ih, gru_w_hh, gru_b_ih, gru_b_hh,
                                 char_emb, gen_w, gen_b, out);
}

// round 4
// speedup vs baseline: 1.0029x; 1.0029x over previous
#include <cuda_runtime.h>
#include <cuda_fp16.h>
#include <math.h>

#define NT 128
#define NB 256
#define NC 512
#define HID 256
#define EMB 128
#define NCLS 37
#define NSTEPS 25
#define POSE 256
#define RNN_IN 1472
#define GRU3 768
#define NCTA 592
#define NWARP (NCTA * 8)

// ---------------- scratch ----------------
__device__ float g_fp[NT * NB * HID];
__device__ float g_poseT[NT * NB * POSE];
__device__ float g_hp[NB * HID];
__device__ float g_gh[NB * GRU3];
__device__ float g_e[NB * NT];
__device__ float g_x[NB * RNN_IN];
__device__ float g_gip[6][NB * GRU3];
__device__ float g_hidden[NB * HID];
__device__ float g_hs[NSTEPS * NB * HID];
__device__ unsigned g_arrive;
__device__ volatile unsigned g_release;

// ---------------- grid barrier ----------------
__device__ __forceinline__ void gbar() {
    __threadfence();
    __syncthreads();
    if (threadIdx.x == 0) {
        unsigned gen = g_release;
        unsigned a = atomicAdd(&g_arrive, 1u);
        if (a == NCTA - 1u) {
            g_arrive = 0u;
            __threadfence();
            g_release = gen + 1u;
        } else {
            while (g_release == gen) __nanosleep(64);
        }
        __threadfence();
    }
    __syncthreads();
}

// ---------------- f32x2 helpers ----------------
__device__ __forceinline__ unsigned long long pk2(float lo, float hi) {
    unsigned long long r;
    asm("mov.b64 %0,{%1,%2};" : "=l"(r) : "f"(lo), "f"(hi));
    return r;
}
__device__ __forceinline__ void fma2(unsigned long long& d, unsigned long long a,
                                     unsigned long long b) {
    asm("fma.rn.f32x2 %0,%1,%2,%0;" : "+l"(d) : "l"(a), "l"(b));
}
__device__ __forceinline__ void up2(unsigned long long v, float& a, float& b) {
    asm("mov.b64 {%0,%1},%2;" : "=f"(a), "=f"(b) : "l"(v));
}

// ---------------- fast transcendentals ----------------
__device__ __forceinline__ float fsig(float x) {
    return __fdividef(1.f, 1.f + __expf(-x));
}
__device__ __forceinline__ float ftanh(float x) {
    float r;
    asm("tanh.approx.f32 %0,%1;" : "=f"(r) : "f"(x));
    return r;
}
__device__ __forceinline__ unsigned htanh2(unsigned x) {
    unsigned r;
    asm("tanh.approx.f16x2 %0,%1;" : "=r"(r) : "r"(x));
    return r;
}

// ---------------- 32x32 tile GEMM (C = A@B^T + bias), packed f32x2 ----------------
__device__ __forceinline__ void gemm_t32(const float* __restrict__ A, int lda,
                                         const float* __restrict__ B, int ldb,
                                         const float* __restrict__ bias,
                                         float* __restrict__ C, int ldc,
                                         int m0, int n0, int kbase, int kiters,
                                         float* sm, int tid)
{
    float* As = sm;            // [32][34]
    float* Bs = sm + 32 * 34;  // [32][34]
    const int ty = tid >> 4, tx = tid & 15;
    unsigned long long acc0 = 0ull, acc1 = 0ull;
    const int row = tid >> 3, kk = (tid & 7) * 4;
    const float* Ag = A + (size_t)(m0 + row) * lda + kbase + kk;
    const float* Bg = B + (size_t)(n0 + row) * ldb + kbase + kk;
    for (int kc = 0; kc < kiters; kc++) {
        float4 av = *(const float4*)(Ag + kc * 32);
        float4 bv = *(const float4*)(Bg + kc * 32);
        As[(kk + 0) * 34 + row] = av.x; As[(kk + 1) * 34 + row] = av.y;
        As[(kk + 2) * 34 + row] = av.z; As[(kk + 3) * 34 + row] = av.w;
        Bs[(kk + 0) * 34 + row] = bv.x; Bs[(kk + 1) * 34 + row] = bv.y;
        Bs[(kk + 2) * 34 + row] = bv.z; Bs[(kk + 3) * 34 + row] = bv.w;
        __syncthreads();
#pragma unroll
        for (int k = 0; k < 32; k++) {
            float2 a = *(const float2*)&As[k * 34 + ty * 2];
            unsigned long long pb = *(const unsigned long long*)&Bs[k * 34 + tx * 2];
            fma2(acc0, pk2(a.x, a.x), pb);
            fma2(acc1, pk2(a.y, a.y), pb);
        }
        __syncthreads();
    }
    float c00, c01, c10, c11;
    up2(acc0, c00, c01); up2(acc1, c10, c11);
    int gm = m0 + ty * 2, gn = n0 + tx * 2;
    float b0 = bias ? bias[gn] : 0.f, b1 = bias ? bias[gn + 1] : 0.f;
    C[(size_t)gm * ldc + gn]           = c00 + b0;
    C[(size_t)gm * ldc + gn + 1]       = c01 + b1;
    C[(size_t)(gm + 1) * ldc + gn]     = c10 + b0;
    C[(size_t)(gm + 1) * ldc + gn + 1] = c11 + b1;
}

// ---------------- 32x64 tile GEMM (no bias), packed f32x2 ----------------
__device__ __forceinline__ void gemm_t32x64(const float* __restrict__ A, int lda,
                                            const float* __restrict__ B, int ldb,
                                            float* __restrict__ C, int ldc,
                                            int m0, int n0, int kbase, int kiters,
                                            float* sm, int tid)
{
    float* As = sm;            // [32][34]
    float* Bs = sm + 32 * 34;  // [32][68]
    const int ty = tid >> 4, tx = tid & 15;
    unsigned long long a00 = 0ull, a01 = 0ull, a10 = 0ull, a11 = 0ull;
    const int arow = tid >> 3, akk = (tid & 7) * 4;
    const int brow = tid >> 2, bkk = (tid & 3) * 8;
    const float* Ag = A + (size_t)(m0 + arow) * lda + kbase + akk;
    const float* Bg = B + (size_t)(n0 + brow) * ldb + kbase + bkk;
    for (int kc = 0; kc < kiters; kc++) {
        float4 av = *(const float4*)(Ag + kc * 32);
        float4 b0 = *(const float4*)(Bg + kc * 32);
        float4 b1 = *(const float4*)(Bg + kc * 32 + 4);
        As[(akk + 0) * 34 + arow] = av.x; As[(akk + 1) * 34 + arow] = av.y;
        As[(akk + 2) * 34 + arow] = av.z; As[(akk + 3) * 34 + arow] = av.w;
        Bs[(bkk + 0) * 68 + brow] = b0.x; Bs[(bkk + 1) * 68 + brow] = b0.y;
        Bs[(bkk + 2) * 68 + brow] = b0.z; Bs[(bkk + 3) * 68 + brow] = b0.w;
        Bs[(bkk + 4) * 68 + brow] = b1.x; Bs[(bkk + 5) * 68 + brow] = b1.y;
        Bs[(bkk + 6) * 68 + brow] = b1.z; Bs[(bkk + 7) * 68 + brow] = b1.w;
        __syncthreads();
#pragma unroll
        for (int k = 0; k < 32; k++) {
            float2 a = *(const float2*)&As[k * 34 + ty * 2];
            ulonglong2 pb = *(const ulonglong2*)&Bs[k * 68 + tx * 4];
            unsigned long long pa0 = pk2(a.x, a.x), pa1 = pk2(a.y, a.y);
            fma2(a00, pa0, pb.x);
            fma2(a01, pa0, pb.y);
            fma2(a10, pa1, pb.x);
            fma2(a11, pa1, pb.y);
        }
        __syncthreads();
    }
    int gm = m0 + ty * 2, gn = n0 + tx * 4;
    float v0, v1;
    up2(a00, v0, v1); C[(size_t)gm * ldc + gn] = v0;     C[(size_t)gm * ldc + gn + 1] = v1;
    up2(a01, v0, v1); C[(size_t)gm * ldc + gn + 2] = v0; C[(size_t)gm * ldc + gn + 3] = v1;
    up2(a10, v0, v1); C[(size_t)(gm+1) * ldc + gn] = v0;     C[(size_t)(gm+1) * ldc + gn + 1] = v1;
    up2(a11, v0, v1); C[(size_t)(gm+1) * ldc + gn + 2] = v0; C[(size_t)(gm+1) * ldc + gn + 3] = v1;
}

// ---------------- feats_proj GEMM: (32768,512)@(256,512)^T, f32x2 ----------------
__global__ __launch_bounds__(256) void fp_gemm(const float* __restrict__ A,
                                               const float* __restrict__ B)
{
    __shared__ __align__(16) float As[16 * 132];
    __shared__ __align__(16) float Bs[16 * 132];
    const int tid = threadIdx.x;
    const int m0 = blockIdx.y * 128;
    const int n0 = blockIdx.x * 128;
    const int ty = tid >> 4, tx = tid & 15;
    unsigned long long acc[8][4];
#pragma unroll
    for (int i = 0; i < 8; i++)
#pragma unroll
        for (int j = 0; j < 4; j++) acc[i][j] = 0ull;

    for (int k0 = 0; k0 < NC; k0 += 16) {
#pragma unroll
        for (int p = 0; p < 8; p++) {
            int i = p * 256 + tid;
            int kk = i & 15, mm = i >> 4;
            As[kk * 132 + mm] = A[(size_t)(m0 + mm) * NC + k0 + kk];
            Bs[kk * 132 + mm] = B[(size_t)(n0 + mm) * NC + k0 + kk];
        }
        __syncthreads();
#pragma unroll
        for (int k = 0; k < 16; k++) {
            float4 x0 = *(const float4*)&As[k * 132 + ty * 8];
            float4 x1 = *(const float4*)&As[k * 132 + ty * 8 + 4];
            ulonglong2 q0 = *(const ulonglong2*)&Bs[k * 132 + tx * 8];
            ulonglong2 q1 = *(const ulonglong2*)&Bs[k * 132 + tx * 8 + 4];
            float av[8] = {x0.x, x0.y, x0.z, x0.w, x1.x, x1.y, x1.z, x1.w};
            unsigned long long pb[4] = {q0.x, q0.y, q1.x, q1.y};
#pragma unroll
            for (int i = 0; i < 8; i++) {
                unsigned long long pa = pk2(av[i], av[i]);
#pragma unroll
                for (int j = 0; j < 4; j++) fma2(acc[i][j], pa, pb[j]);
            }
        }
        __syncthreads();
    }
#pragma unroll
    for (int i = 0; i < 8; i++) {
        int gm = m0 + ty * 8 + i;
#pragma unroll
        for (int j = 0; j < 4; j++) {
            float lo, hi;
            up2(acc[i][j], lo, hi);
            g_fp[(size_t)gm * HID + n0 + tx * 8 + 2 * j]     = lo;
            g_fp[(size_t)gm * HID + n0 + tx * 8 + 2 * j + 1] = hi;
        }
    }
}

// ---------------- persistent decode kernel ----------------
__global__ __launch_bounds__(256, 4) void decode_kernel(
    const float* __restrict__ feats,
    const float* __restrict__ pose,
    const float* __restrict__ pyr0,
    const float* __restrict__ pyr1,
    const float* __restrict__ pyr2,
    const int*   __restrict__ text,
    const float* __restrict__ h2h_w,    const float* __restrict__ h2h_b,
    const float* __restrict__ score_w,
    const float* __restrict__ pose_w,   const float* __restrict__ pose_b,
    const float* __restrict__ gru_w_ih, const float* __restrict__ gru_w_hh,
    const float* __restrict__ gru_b_ih, const float* __restrict__ gru_b_hh,
    const float* __restrict__ char_emb,
    const float* __restrict__ gen_w,    const float* __restrict__ gen_b,
    float* __restrict__ out)
{
    __shared__ __align__(16) float sm[3264];
    __shared__ float s_coord[4];
    __shared__ float s_ly[3][2], s_lx[3][2];
    __shared__ int   s_y0[3][2], s_y1[3][2], s_x0[3][2], s_x1[3][2];
    __shared__ int   s_vy[3][2], s_vx[3][2];

    const int tid = threadIdx.x;
    const int bid = blockIdx.x;
    const int lane = tid & 31;
    const int wid = tid >> 5;

    // ---- prologue: hidden = 0, step-0 embedding, pose transpose ----
    if (bid < 256) {
        g_hidden[bid * 256 + tid] = 0.f;
        if (tid < EMB) g_x[(size_t)bid * RNN_IN + 768 + tid] = char_emb[tid]; // tgt=0 row
    }
    for (int job = bid; job < NB * 32; job += NCTA) {
        int b = job >> 5;
        int r = job & 31;
        int t0 = (r & 3) * 32;
        int p0 = (r >> 2) * 32;
        int y = tid >> 5, x = tid & 31;
#pragma unroll
        for (int q = 0; q < 4; q++) {
            int yy = y + q * 8;
            sm[yy * 33 + x] = pose[((size_t)b * POSE + (p0 + yy)) * NT + (t0 + x)];
        }
        __syncthreads();
#pragma unroll
        for (int q = 0; q < 4; q++) {
            int yy = y + q * 8;
            g_poseT[((size_t)(t0 + yy) * NB + b) * POSE + (p0 + x)] = sm[x * 33 + yy];
        }
        __syncthreads();
    }
    gbar();

    // per-lane cached score_w pairs
    float2 swc[4];
#pragma unroll
    for (int q = 0; q < 4; q++) swc[q] = ((const float2*)score_w)[lane + 32 * q];

    for (int step = 0; step < NSTEPS; step++) {
        // ===== A: hp GEMM (64) + gh GEMM (192) + gi_emb GEMM (96) =====
        if (bid < 64) {
            gemm_t32(g_hidden, HID, h2h_w, HID, h2h_b, g_hp, HID,
                     (bid >> 3) * 32, (bid & 7) * 32, 0, 8, sm, tid);
        } else if (bid < 256) {
            int j = bid - 64;
            gemm_t32(g_hidden, HID, gru_w_hh, HID, gru_b_hh, g_gh, GRU3,
                     (j / 24) * 32, (j % 24) * 32, 0, 8, sm, tid);
        } else if (bid < 352) {
            int j = bid - 256;
            gemm_t32x64(g_x, RNN_IN, gru_w_ih, RNN_IN, g_gip[3], GRU3,
                        (j / 12) * 32, (j % 12) * 64, 768, 4, sm, tid);
        }
        gbar();

        // ===== B: energies — warp handles 8 t's of one b; f16x2 HW tanh =====
        {
            int gw = bid * 8 + wid;
            if (gw < 4096) {
                int b = gw >> 4;
                int tg = gw & 15;
                float2 hpc[4];
                const float2* hp2 = (const float2*)(g_hp + (size_t)b * HID);
#pragma unroll
                for (int q = 0; q < 4; q++) hpc[q] = hp2[lane + 32 * q];
#pragma unroll
                for (int i = 0; i < 8; i++) {
                    int t = tg * 8 + i;
                    const float2* fp2 = (const float2*)(g_fp + ((size_t)t * NB + b) * HID);
                    float s = 0.f;
#pragma unroll
                    for (int q = 0; q < 4; q++) {
                        float2 a = fp2[lane + 32 * q];
                        float x0 = a.x + hpc[q].x;
                        float x1 = a.y + hpc[q].y;
                        __half2 hx = __floats2half2_rn(x0, x1);
                        unsigned th = htanh2(*(unsigned*)&hx);
                        float2 tf = __half22float2(*(__half2*)&th);
                        s = fmaf(tf.x, swc[q].x, s);
                        s = fmaf(tf.y, swc[q].y, s);
                    }
#pragma unroll
                    for (int o = 16; o; o >>= 1) s += __shfl_xor_sync(~0u, s, o);
                    if (!lane) g_e[b * NT + t] = s;
                }
            }
        }
        gbar();

        // ===== C: per-b softmax + ctx + coord + crops =====
        if (bid < NB) {
            int b = bid;
            float* e_s = sm;
            float* red = sm + 128;
            float* al  = sm + 256;
            float* ctx_s = sm + 384;
            if (tid < NT) { float v = g_e[b * NT + tid]; e_s[tid] = v; red[tid] = v; }
            __syncthreads();
            for (int s = 64; s; s >>= 1) { if (tid < s) red[tid] = fmaxf(red[tid], red[tid + s]); __syncthreads(); }
            float mx = red[0];
            __syncthreads();
            if (tid < NT) { float ex = __expf(e_s[tid] - mx); al[tid] = ex; red[tid] = ex; }
            __syncthreads();
            for (int s = 64; s; s >>= 1) { if (tid < s) red[tid] += red[tid + s]; __syncthreads(); }
            float inv = __fdividef(1.f, red[0]);
            __syncthreads();
            if (tid < NT) al[tid] *= inv;
            __syncthreads();
#pragma unroll
            for (int ch = 0; ch < 3; ch++) {
                int c = ch * 256 + tid;
                const float* src; size_t stride;
                if (c < NC) { src = feats + (size_t)b * NC + c;            stride = (size_t)NB * NC; }
                else        { src = g_poseT + (size_t)b * POSE + (c - NC); stride = (size_t)NB * POSE; }
                float acc = 0.f;
#pragma unroll 8
                for (int t = 0; t < NT; t++) acc += al[t] * src[(size_t)t * stride];
                ctx_s[c] = acc;
                g_x[(size_t)b * RNN_IN + c] = acc;
            }
            __syncthreads();
            if (wid < 4) {
                const float* pw = pose_w + wid * 768;
                float s = 0.f;
#pragma unroll
                for (int q = 0; q < 24; q++) { int c = lane + q * 32; s += ctx_s[c] * pw[c]; }
#pragma unroll
                for (int o = 16; o; o >>= 1) s += __shfl_xor_sync(~0u, s, o);
                if (!lane) s_coord[wid] = fsig(s + pose_b[wid]);
            }
            __syncthreads();
            if (tid == 0) {
                const int Hs[3] = {16, 8, 4};
                const int Ws[3] = {128, 64, 65};
                float c0 = s_coord[0], c1 = s_coord[1], c2 = s_coord[2], c3 = s_coord[3];
                for (int p = 0; p < 3; p++) {
                    float Hf = (float)Hs[p], Wf = (float)Ws[p];
                    c0 *= Hf; c1 *= Wf; c2 *= Hf; c3 *= Wf;
                    float x1 = c0, y1 = c1, x2 = c2, y2 = c3;
                    float bw = fmaxf(x2 - x1, 1.f) * 0.5f;
                    float bh = fmaxf(y2 - y1, 1.f) * 0.5f;
#pragma unroll
                    for (int i = 0; i < 2; i++) {
                        float ys = y1 + (0.5f + (float)i) * bh;
                        s_vy[p][i] = (ys >= -1.f && ys <= Hf) ? 1 : 0;
                        float y = fminf(fmaxf(ys, 0.f), Hf - 1.f);
                        float y0f = floorf(y);
                        int y0i = (int)y0f;
                        s_y0[p][i] = y0i;
                        s_y1[p][i] = min(y0i + 1, Hs[p] - 1);
                        s_ly[p][i] = y - y0f;
                        float xs = x1 + (0.5f + (float)i) * bw;
                        s_vx[p][i] = (xs >= -1.f && xs <= Wf) ? 1 : 0;
                        float x = fminf(fmaxf(xs, 0.f), Wf - 1.f);
                        float x0f = floorf(x);
                        int x0i = (int)x0f;
                        s_x0[p][i] = x0i;
                        s_x1[p][i] = min(x0i + 1, Ws[p] - 1);
                        s_lx[p][i] = x - x0f;
                    }
                }
            }
            __syncthreads();
            for (int o = tid; o < 576; o += 256) {
                int p, local;
                if (o < 64)       { p = 0; local = o; }
                else if (o < 320) { p = 1; local = o - 64; }
                else              { p = 2; local = o - 320; }
                int c = local >> 2;
                int ij = local & 3;
                int i = ij >> 1, j = ij & 1;
                float val = 0.f;
                if (s_vy[p][i] && s_vx[p][j]) {
                    float ly = s_ly[p][i], lx = s_lx[p][j];
                    float hy = 1.f - ly, hx = 1.f - lx;
                    int y0 = s_y0[p][i], y1 = s_y1[p][i];
                    int x0 = s_x0[p][j], x1 = s_x1[p][j];
                    const float* f; int W, HW;
                    if (p == 0)      { f = pyr0; W = 128; HW = 16 * 128; }
                    else if (p == 1) { f = pyr1; W = 64;  HW = 8 * 64;  }
                    else             { f = pyr2; W = 65;  HW = 4 * 65;  }
                    const float* fc = f + (size_t)c * HW;
                    val = fc[y0 * W + x0] * (hy * hx)
                        + fc[y0 * W + x1] * (hy * lx)
                        + fc[y1 * W + x0] * (ly * hx)
                        + fc[y1 * W + x1] * (ly * lx);
                }
                g_x[(size_t)b * RNN_IN + 896 + o] = val;
            }
        }
        gbar();

        // ===== D: gi GEMM — ctx K=[0,768) split3 (288 jobs) + crops K=[896,1472) split2 (192 jobs)
        if (bid < 288) {
            int ks = bid / 96, j = bid % 96;
            gemm_t32x64(g_x, RNN_IN, gru_w_ih, RNN_IN, g_gip[ks], GRU3,
                        (j / 12) * 32, (j % 12) * 64, ks * 256, 8, sm, tid);
        } else if (bid < 480) {
            int jj = bid - 288;
            int ks = jj / 96, j = jj % 96;
            gemm_t32x64(g_x, RNN_IN, gru_w_ih, RNN_IN, g_gip[4 + ks], GRU3,
                        (j / 12) * 32, (j % 12) * 64, 896 + ks * 288, 9, sm, tid);
        }
        gbar();

        // ===== E: reduce + GRU; also write next-step embedding =====
        if (bid < 256) {
            int g = bid * 256 + tid;
            int b = g >> 8, h = g & 255;
            size_t base = (size_t)b * GRU3;
            float ir = gru_b_ih[h], iz = gru_b_ih[HID + h], in = gru_b_ih[2 * HID + h];
#pragma unroll
            for (int p = 0; p < 6; p++) {
                ir += g_gip[p][base + h];
                iz += g_gip[p][base + HID + h];
                in += g_gip[p][base + 2 * HID + h];
            }
            float hr = g_gh[base + h], hz = g_gh[base + HID + h], hn = g_gh[base + 2 * HID + h];
            float rr = fsig(ir + hr);
            float zz = fsig(iz + hz);
            float nn = ftanh(in + rr * hn);
            float hold = g_hidden[g];
            float hnew = (1.f - zz) * nn + zz * hold;
            g_hidden[g] = hnew;
            g_hs[((size_t)b * NSTEPS + step) * HID + h] = hnew;
        } else if (bid < 512) {
            int b = bid - 256;
            if (tid < EMB) {
                int tgt = text[b * NSTEPS + step] + 1;
                g_x[(size_t)b * RNN_IN + 768 + tid] = char_emb[(size_t)tgt * EMB + tid];
            }
        }
        gbar();
    }

    // ===== final classifier =====
    {
        int gw = bid * 8 + wid;
        for (int m = gw; m < NB * NSTEPS; m += NWARP) {
            const float* hrow = g_hs + (size_t)m * HID;
            float a[8];
#pragma unroll
            for (int q = 0; q < 8; q++) a[q] = hrow[lane + q * 32];
            for (int n = 0; n < NCLS; n++) {
                const float* w = gen_w + (size_t)n * HID;
                float s = 0.f;
#pragma unroll
                for (int q = 0; q < 8; q++) s += a[q] * w[lane + q * 32];
#pragma unroll
                for (int o = 16; o; o >>= 1) s += __shfl_xor_sync(~0u, s, o);
                if (!lane) out[(size_t)m * NCLS + n] = s + gen_b[n];
            }
        }
    }
}

// ---------------- driver ----------------
extern "C" void kernel_launch(void* const* d_in, const int* in_sizes, int n_in,
                              void* d_out, int out_size)
{
    const float* feats    = (const float*)d_in[0];
    const float* pose     = (const float*)d_in[1];
    const float* pyr0     = (const float*)d_in[2];
    const float* pyr1     = (const float*)d_in[3];
    const float* pyr2     = (const float*)d_in[4];
    const int*   text     = (const int*)  d_in[6];
    const float* i2h_w    = (const float*)d_in[7];
    const float* h2h_w    = (const float*)d_in[8];
    const float* h2h_b    = (const float*)d_in[9];
    const float* score_w  = (const float*)d_in[10];
    const float* pose_w   = (const float*)d_in[11];
    const float* pose_b   = (const float*)d_in[12];
    const float* gru_w_ih = (const float*)d_in[13];
    const float* gru_w_hh = (const float*)d_in[14];
    const float* gru_b_ih = (const float*)d_in[15];
    const float* gru_b_hh = (const float*)d_in[16];
    const float* char_emb = (const float*)d_in[17];
    const float* gen_w    = (const float*)d_in[18];
    const float* gen_b    = (const float*)d_in[19];
    float* out = (float*)d_out;

    dim3 g1(2, 256);
    fp_gemm<<<g1, 256>>>(feats, i2h_w);

    decode_kernel<<<NCTA, 256>>>(feats, pose, pyr0, pyr1, pyr2, text,
                                 h2h_w, h2h_b, score_w, pose_w, pose_b,
                                 gru_w_ih, gru_w_hh, gru_b_ih, gru_b_hh,
                                 char_emb, gen_w, gen_b, out);
}

// round 5
// speedup vs baseline: 1.3492x; 1.3453x over previous
#include <cuda_runtime.h>
#include <cuda_fp16.h>
#include <math.h>

#define NT 128
#define NB 256
#define NC 512
#define HID 256
#define EMB 128
#define NCLS 37
#define NSTEPS 25
#define POSE 256
#define RNN_IN 1472
#define GRU3 768
#define NCTA 592
#define NWARP (NCTA * 8)

// ---------------- scratch ----------------
__device__ __align__(16) __half g_fp16[NT * NB * HID];     // feats_proj fp16
__device__ __half2 g_feats16[NT * NB * NC / 2];            // feats fp16 copy
__device__ __half  g_pose16T[NT * NB * POSE];              // pose transposed fp16
__device__ float g_hp[NB * HID];
__device__ float g_gh[NB * GRU3];
__device__ float g_e[NB * NT];
__device__ float g_x[NB * RNN_IN];
__device__ float g_gip[6][NB * GRU3];
__device__ float g_hidden[NB * HID];
__device__ float g_hs[NSTEPS * NB * HID];

// barrier state: 16 group counters + root, 128B padded; release words padded
__device__ unsigned g_cnt[17 * 32];
__device__ unsigned g_rel[16 * 32];

// ---------------- barrier primitives ----------------
__device__ __forceinline__ unsigned ld_acq(const unsigned* p) {
    unsigned v;
    asm volatile("ld.acquire.gpu.global.u32 %0,[%1];" : "=r"(v) : "l"(p) : "memory");
    return v;
}
__device__ __forceinline__ unsigned atom_inc_rel(unsigned* p) {
    unsigned v;
    asm volatile("atom.release.gpu.global.add.u32 %0,[%1],1;" : "=r"(v) : "l"(p) : "memory");
    return v;
}
__device__ __forceinline__ void st_rel(unsigned* p, unsigned v) {
    asm volatile("st.release.gpu.global.u32 [%0],%1;" :: "l"(p), "r"(v) : "memory");
}

// hierarchical sense-free grid barrier: 16 groups of 37 CTAs
__device__ __forceinline__ void gbar() {
    __syncthreads();
    if (threadIdx.x == 0) {
        int g = blockIdx.x / 37;
        unsigned* cnt = &g_cnt[g * 32];
        unsigned* rel = &g_rel[g * 32];
        unsigned gen = ld_acq(rel);
        if (atom_inc_rel(cnt) == 36u) {
            *(volatile unsigned*)cnt = 0u;
            if (atom_inc_rel(&g_cnt[16 * 32]) == 15u) {
                *(volatile unsigned*)&g_cnt[16 * 32] = 0u;
#pragma unroll
                for (int i = 0; i < 16; i++) st_rel(&g_rel[i * 32], gen + 1u);
            } else {
                while (ld_acq(rel) == gen) __nanosleep(32);
            }
        } else {
            while (ld_acq(rel) == gen) __nanosleep(32);
        }
    }
    __syncthreads();
}

// ---------------- f32x2 helpers ----------------
__device__ __forceinline__ unsigned long long pk2(float lo, float hi) {
    unsigned long long r;
    asm("mov.b64 %0,{%1,%2};" : "=l"(r) : "f"(lo), "f"(hi));
    return r;
}
__device__ __forceinline__ void fma2(unsigned long long& d, unsigned long long a,
                                     unsigned long long b) {
    asm("fma.rn.f32x2 %0,%1,%2,%0;" : "+l"(d) : "l"(a), "l"(b));
}
__device__ __forceinline__ void up2(unsigned long long v, float& a, float& b) {
    asm("mov.b64 {%0,%1},%2;" : "=f"(a), "=f"(b) : "l"(v));
}

// ---------------- fast transcendentals ----------------
__device__ __forceinline__ float fsig(float x) {
    return __fdividef(1.f, 1.f + __expf(-x));
}
__device__ __forceinline__ float ftanh(float x) {
    float r;
    asm("tanh.approx.f32 %0,%1;" : "=f"(r) : "f"(x));
    return r;
}
__device__ __forceinline__ __half2 htanh2(__half2 x) {
    __half2 r;
    asm("tanh.approx.f16x2 %0,%1;" : "=r"(*(unsigned*)&r) : "r"(*(unsigned*)&x));
    return r;
}

// ---------------- 32x32 tile GEMM (C = A@B^T + bias); A via __ldcg ----------------
__device__ __forceinline__ void gemm_t32(const float* __restrict__ A, int lda,
                                         const float* __restrict__ B, int ldb,
                                         const float* __restrict__ bias,
                                         float* __restrict__ C, int ldc,
                                         int m0, int n0, int kbase, int kiters,
                                         float* sm, int tid)
{
    float* As = sm;
    float* Bs = sm + 32 * 34;
    const int ty = tid >> 4, tx = tid & 15;
    unsigned long long acc0 = 0ull, acc1 = 0ull;
    const int row = tid >> 3, kk = (tid & 7) * 4;
    const float* Ag = A + (size_t)(m0 + row) * lda + kbase + kk;
    const float* Bg = B + (size_t)(n0 + row) * ldb + kbase + kk;
    for (int kc = 0; kc < kiters; kc++) {
        float4 av = __ldcg((const float4*)(Ag + kc * 32));
        float4 bv = __ldg((const float4*)(Bg + kc * 32));
        As[(kk + 0) * 34 + row] = av.x; As[(kk + 1) * 34 + row] = av.y;
        As[(kk + 2) * 34 + row] = av.z; As[(kk + 3) * 34 + row] = av.w;
        Bs[(kk + 0) * 34 + row] = bv.x; Bs[(kk + 1) * 34 + row] = bv.y;
        Bs[(kk + 2) * 34 + row] = bv.z; Bs[(kk + 3) * 34 + row] = bv.w;
        __syncthreads();
#pragma unroll
        for (int k = 0; k < 32; k++) {
            float2 a = *(const float2*)&As[k * 34 + ty * 2];
            unsigned long long pb = *(const unsigned long long*)&Bs[k * 34 + tx * 2];
            fma2(acc0, pk2(a.x, a.x), pb);
            fma2(acc1, pk2(a.y, a.y), pb);
        }
        __syncthreads();
    }
    float c00, c01, c10, c11;
    up2(acc0, c00, c01); up2(acc1, c10, c11);
    int gm = m0 + ty * 2, gn = n0 + tx * 2;
    float b0 = bias ? bias[gn] : 0.f, b1 = bias ? bias[gn + 1] : 0.f;
    C[(size_t)gm * ldc + gn]           = c00 + b0;
    C[(size_t)gm * ldc + gn + 1]       = c01 + b1;
    C[(size_t)(gm + 1) * ldc + gn]     = c10 + b0;
    C[(size_t)(gm + 1) * ldc + gn + 1] = c11 + b1;
}

// ---------------- 32x64 tile GEMM (no bias); A via __ldcg ----------------
__device__ __forceinline__ void gemm_t32x64(const float* __restrict__ A, int lda,
                                            const float* __restrict__ B, int ldb,
                                            float* __restrict__ C, int ldc,
                                            int m0, int n0, int kbase, int kiters,
                                            float* sm, int tid)
{
    float* As = sm;
    float* Bs = sm + 32 * 34;
    const int ty = tid >> 4, tx = tid & 15;
    unsigned long long a00 = 0ull, a01 = 0ull, a10 = 0ull, a11 = 0ull;
    const int arow = tid >> 3, akk = (tid & 7) * 4;
    const int brow = tid >> 2, bkk = (tid & 3) * 8;
    const float* Ag = A + (size_t)(m0 + arow) * lda + kbase + akk;
    const float* Bg = B + (size_t)(n0 + brow) * ldb + kbase + bkk;
    for (int kc = 0; kc < kiters; kc++) {
        float4 av = __ldcg((const float4*)(Ag + kc * 32));
        float4 b0 = __ldg((const float4*)(Bg + kc * 32));
        float4 b1 = __ldg((const float4*)(Bg + kc * 32 + 4));
        As[(akk + 0) * 34 + arow] = av.x; As[(akk + 1) * 34 + arow] = av.y;
        As[(akk + 2) * 34 + arow] = av.z; As[(akk + 3) * 34 + arow] = av.w;
        Bs[(bkk + 0) * 68 + brow] = b0.x; Bs[(bkk + 1) * 68 + brow] = b0.y;
        Bs[(bkk + 2) * 68 + brow] = b0.z; Bs[(bkk + 3) * 68 + brow] = b0.w;
        Bs[(bkk + 4) * 68 + brow] = b1.x; Bs[(bkk + 5) * 68 + brow] = b1.y;
        Bs[(bkk + 6) * 68 + brow] = b1.z; Bs[(bkk + 7) * 68 + brow] = b1.w;
        __syncthreads();
#pragma unroll
        for (int k = 0; k < 32; k++) {
            float2 a = *(const float2*)&As[k * 34 + ty * 2];
            ulonglong2 pb = *(const ulonglong2*)&Bs[k * 68 + tx * 4];
            unsigned long long pa0 = pk2(a.x, a.x), pa1 = pk2(a.y, a.y);
            fma2(a00, pa0, pb.x);
            fma2(a01, pa0, pb.y);
            fma2(a10, pa1, pb.x);
            fma2(a11, pa1, pb.y);
        }
        __syncthreads();
    }
    int gm = m0 + ty * 2, gn = n0 + tx * 4;
    float v0, v1;
    up2(a00, v0, v1); C[(size_t)gm * ldc + gn] = v0;     C[(size_t)gm * ldc + gn + 1] = v1;
    up2(a01, v0, v1); C[(size_t)gm * ldc + gn + 2] = v0; C[(size_t)gm * ldc + gn + 3] = v1;
    up2(a10, v0, v1); C[(size_t)(gm+1) * ldc + gn] = v0;     C[(size_t)(gm+1) * ldc + gn + 1] = v1;
    up2(a11, v0, v1); C[(size_t)(gm+1) * ldc + gn + 2] = v0; C[(size_t)(gm+1) * ldc + gn + 3] = v1;
}

// ---------------- feats_proj GEMM -> fp16 output ----------------
__global__ __launch_bounds__(256) void fp_gemm(const float* __restrict__ A,
                                               const float* __restrict__ B)
{
    __shared__ __align__(16) float As[16 * 132];
    __shared__ __align__(16) float Bs[16 * 132];
    const int tid = threadIdx.x;
    const int m0 = blockIdx.y * 128;
    const int n0 = blockIdx.x * 128;
    const int ty = tid >> 4, tx = tid & 15;
    unsigned long long acc[8][4];
#pragma unroll
    for (int i = 0; i < 8; i++)
#pragma unroll
        for (int j = 0; j < 4; j++) acc[i][j] = 0ull;

    for (int k0 = 0; k0 < NC; k0 += 16) {
#pragma unroll
        for (int p = 0; p < 8; p++) {
            int i = p * 256 + tid;
            int kk = i & 15, mm = i >> 4;
            As[kk * 132 + mm] = A[(size_t)(m0 + mm) * NC + k0 + kk];
            Bs[kk * 132 + mm] = B[(size_t)(n0 + mm) * NC + k0 + kk];
        }
        __syncthreads();
#pragma unroll
        for (int k = 0; k < 16; k++) {
            float4 x0 = *(const float4*)&As[k * 132 + ty * 8];
            float4 x1 = *(const float4*)&As[k * 132 + ty * 8 + 4];
            ulonglong2 q0 = *(const ulonglong2*)&Bs[k * 132 + tx * 8];
            ulonglong2 q1 = *(const ulonglong2*)&Bs[k * 132 + tx * 8 + 4];
            float av[8] = {x0.x, x0.y, x0.z, x0.w, x1.x, x1.y, x1.z, x1.w};
            unsigned long long pb[4] = {q0.x, q0.y, q1.x, q1.y};
#pragma unroll
            for (int i = 0; i < 8; i++) {
                unsigned long long pa = pk2(av[i], av[i]);
#pragma unroll
                for (int j = 0; j < 4; j++) fma2(acc[i][j], pa, pb[j]);
            }
        }
        __syncthreads();
    }
#pragma unroll
    for (int i = 0; i < 8; i++) {
        int gm = m0 + ty * 8 + i;
#pragma unroll
        for (int j = 0; j < 4; j++) {
            float lo, hi;
            up2(acc[i][j], lo, hi);
            *(__half2*)(g_fp16 + (size_t)gm * HID + n0 + tx * 8 + 2 * j) =
                __floats2half2_rn(lo, hi);
        }
    }
}

// ---------------- persistent decode kernel ----------------
__global__ __launch_bounds__(256, 4) void decode_kernel(
    const float* __restrict__ feats,
    const float* __restrict__ pose,
    const float* __restrict__ pyr0,
    const float* __restrict__ pyr1,
    const float* __restrict__ pyr2,
    const int*   __restrict__ text,
    const float* __restrict__ h2h_w,    const float* __restrict__ h2h_b,
    const float* __restrict__ score_w,
    const float* __restrict__ pose_w,   const float* __restrict__ pose_b,
    const float* __restrict__ gru_w_ih, const float* __restrict__ gru_w_hh,
    const float* __restrict__ gru_b_ih, const float* __restrict__ gru_b_hh,
    const float* __restrict__ char_emb,
    const float* __restrict__ gen_w,    const float* __restrict__ gen_b,
    float* __restrict__ out)
{
    __shared__ __align__(16) float sm[3264];
    __shared__ float s_coord[4];
    __shared__ float s_ly[3][2], s_lx[3][2];
    __shared__ int   s_y0[3][2], s_y1[3][2], s_x0[3][2], s_x1[3][2];
    __shared__ int   s_vy[3][2], s_vx[3][2];

    const int tid = threadIdx.x;
    const int bid = blockIdx.x;
    const int lane = tid & 31;
    const int wid = tid >> 5;

    // ---- prologue: hidden=0, step-0 emb, feats->fp16 copy, pose transpose ----
    if (bid < 256) {
        g_hidden[bid * 256 + tid] = 0.f;
        if (tid < EMB) g_x[(size_t)bid * RNN_IN + 768 + tid] = char_emb[tid];
    }
    {
        const float2* fsrc = (const float2*)feats;
        for (int i = bid * 256 + tid; i < NT * NB * NC / 2; i += NCTA * 256) {
            float2 v = __ldg(fsrc + i);
            g_feats16[i] = __floats2half2_rn(v.x, v.y);
        }
    }
    for (int job = bid; job < NB * 32; job += NCTA) {
        int b = job >> 5;
        int r = job & 31;
        int t0 = (r & 3) * 32;
        int p0 = (r >> 2) * 32;
        int y = tid >> 5, x = tid & 31;
#pragma unroll
        for (int q = 0; q < 4; q++) {
            int yy = y + q * 8;
            sm[yy * 33 + x] = __ldg(pose + ((size_t)b * POSE + (p0 + yy)) * NT + (t0 + x));
        }
        __syncthreads();
#pragma unroll
        for (int q = 0; q < 4; q++) {
            int yy = y + q * 8;
            g_pose16T[((size_t)(t0 + yy) * NB + b) * POSE + (p0 + x)] =
                __float2half(sm[x * 33 + yy]);
        }
        __syncthreads();
    }
    gbar();

    for (int step = 0; step < NSTEPS; step++) {
        // ===== A: hp GEMM (64) + gh GEMM (192) + gi_emb GEMM (96) =====
        if (bid < 64) {
            gemm_t32(g_hidden, HID, h2h_w, HID, h2h_b, g_hp, HID,
                     (bid >> 3) * 32, (bid & 7) * 32, 0, 8, sm, tid);
        } else if (bid < 256) {
            int j = bid - 64;
            gemm_t32(g_hidden, HID, gru_w_hh, HID, gru_b_hh, g_gh, GRU3,
                     (j / 24) * 32, (j % 24) * 32, 0, 8, sm, tid);
        } else if (bid < 352) {
            int j = bid - 256;
            gemm_t32x64(g_x, RNN_IN, gru_w_ih, RNN_IN, g_gip[3], GRU3,
                        (j / 12) * 32, (j % 12) * 64, 768, 4, sm, tid);
        }
        gbar();

        // ===== B: energies; fp16 LDG.128, f16x2 HW tanh =====
        {
            int gw = bid * 8 + wid;
            if (gw < 4096) {
                int b = gw >> 4;
                int tg = gw & 15;
                // hp and sw at h = lane*8 .. lane*8+7
                float4 hpa = __ldcg((const float4*)(g_hp + (size_t)b * HID + lane * 8));
                float4 hpb = __ldcg((const float4*)(g_hp + (size_t)b * HID + lane * 8 + 4));
                __half2 hph[4] = {
                    __floats2half2_rn(hpa.x, hpa.y), __floats2half2_rn(hpa.z, hpa.w),
                    __floats2half2_rn(hpb.x, hpb.y), __floats2half2_rn(hpb.z, hpb.w)};
                float4 swa = __ldg((const float4*)(score_w + lane * 8));
                float4 swb = __ldg((const float4*)(score_w + lane * 8 + 4));
                float swf[8] = {swa.x, swa.y, swa.z, swa.w, swb.x, swb.y, swb.z, swb.w};
#pragma unroll
                for (int i = 0; i < 8; i++) {
                    int t = tg * 8 + i;
                    uint4 fv = __ldg((const uint4*)(g_fp16 +
                               ((size_t)t * NB + b) * HID + lane * 8));
                    __half2 v0 = *(__half2*)&fv.x, v1 = *(__half2*)&fv.y;
                    __half2 v2 = *(__half2*)&fv.z, v3 = *(__half2*)&fv.w;
                    float2 t0 = __half22float2(htanh2(__hadd2(v0, hph[0])));
                    float2 t1 = __half22float2(htanh2(__hadd2(v1, hph[1])));
                    float2 t2 = __half22float2(htanh2(__hadd2(v2, hph[2])));
                    float2 t3 = __half22float2(htanh2(__hadd2(v3, hph[3])));
                    float s = t0.x * swf[0] + t0.y * swf[1] + t1.x * swf[2] + t1.y * swf[3]
                            + t2.x * swf[4] + t2.y * swf[5] + t3.x * swf[6] + t3.y * swf[7];
#pragma unroll
                    for (int o = 16; o; o >>= 1) s += __shfl_xor_sync(~0u, s, o);
                    if (!lane) g_e[b * NT + t] = s;
                }
            }
        }
        gbar();

        // ===== C: per-b softmax + ctx (fp16 streams) + coord + crops =====
        if (bid < NB) {
            int b = bid;
            float* e_s = sm;
            float* red = sm + 128;
            float* al  = sm + 256;
            float* ctx_s = sm + 384;
            if (tid < NT) { float v = __ldcg(g_e + b * NT + tid); e_s[tid] = v; red[tid] = v; }
            __syncthreads();
            for (int s = 64; s; s >>= 1) { if (tid < s) red[tid] = fmaxf(red[tid], red[tid + s]); __syncthreads(); }
            float mx = red[0];
            __syncthreads();
            if (tid < NT) { float ex = __expf(e_s[tid] - mx); al[tid] = ex; red[tid] = ex; }
            __syncthreads();
            for (int s = 64; s; s >>= 1) { if (tid < s) red[tid] += red[tid + s]; __syncthreads(); }
            float inv = __fdividef(1.f, red[0]);
            __syncthreads();
            if (tid < NT) al[tid] *= inv;
            __syncthreads();
            // feats part: c = 2*tid, 2*tid+1
            {
                const __half2* f2 = g_feats16 + (size_t)b * (NC / 2) + tid;
                float2 acc = {0.f, 0.f};
#pragma unroll 8
                for (int t = 0; t < NT; t++) {
                    float2 vf = __half22float2(__ldg(f2 + (size_t)t * NB * (NC / 2)));
                    float a = al[t];
                    acc.x = fmaf(a, vf.x, acc.x);
                    acc.y = fmaf(a, vf.y, acc.y);
                }
                ctx_s[2 * tid] = acc.x;
                ctx_s[2 * tid + 1] = acc.y;
                *(float2*)(g_x + (size_t)b * RNN_IN + 2 * tid) = acc;
            }
            // pose part: c = 512 + tid
            {
                const __half* pp = g_pose16T + (size_t)b * POSE + tid;
                float acc = 0.f;
#pragma unroll 8
                for (int t = 0; t < NT; t++)
                    acc = fmaf(al[t], __half2float(__ldg(pp + (size_t)t * NB * POSE)), acc);
                ctx_s[NC + tid] = acc;
                g_x[(size_t)b * RNN_IN + NC + tid] = acc;
            }
            __syncthreads();
            if (wid < 4) {
                const float* pw = pose_w + wid * 768;
                float s = 0.f;
#pragma unroll
                for (int q = 0; q < 24; q++) { int c = lane + q * 32; s += ctx_s[c] * pw[c]; }
#pragma unroll
                for (int o = 16; o; o >>= 1) s += __shfl_xor_sync(~0u, s, o);
                if (!lane) s_coord[wid] = fsig(s + pose_b[wid]);
            }
            __syncthreads();
            if (tid == 0) {
                const int Hs[3] = {16, 8, 4};
                const int Ws[3] = {128, 64, 65};
                float c0 = s_coord[0], c1 = s_coord[1], c2 = s_coord[2], c3 = s_coord[3];
                for (int p = 0; p < 3; p++) {
                    float Hf = (float)Hs[p], Wf = (float)Ws[p];
                    c0 *= Hf; c1 *= Wf; c2 *= Hf; c3 *= Wf;
                    float x1 = c0, y1 = c1, x2 = c2, y2 = c3;
                    float bw = fmaxf(x2 - x1, 1.f) * 0.5f;
                    float bh = fmaxf(y2 - y1, 1.f) * 0.5f;
#pragma unroll
                    for (int i = 0; i < 2; i++) {
                        float ys = y1 + (0.5f + (float)i) * bh;
                        s_vy[p][i] = (ys >= -1.f && ys <= Hf) ? 1 : 0;
                        float y = fminf(fmaxf(ys, 0.f), Hf - 1.f);
                        float y0f = floorf(y);
                        int y0i = (int)y0f;
                        s_y0[p][i] = y0i;
                        s_y1[p][i] = min(y0i + 1, Hs[p] - 1);
                        s_ly[p][i] = y - y0f;
                        float xs = x1 + (0.5f + (float)i) * bw;
                        s_vx[p][i] = (xs >= -1.f && xs <= Wf) ? 1 : 0;
                        float x = fminf(fmaxf(xs, 0.f), Wf - 1.f);
                        float x0f = floorf(x);
                        int x0i = (int)x0f;
                        s_x0[p][i] = x0i;
                        s_x1[p][i] = min(x0i + 1, Ws[p] - 1);
                        s_lx[p][i] = x - x0f;
                    }
                }
            }
            __syncthreads();
            for (int o = tid; o < 576; o += 256) {
                int p, local;
                if (o < 64)       { p = 0; local = o; }
                else if (o < 320) { p = 1; local = o - 64; }
                else              { p = 2; local = o - 320; }
                int c = local >> 2;
                int ij = local & 3;
                int i = ij >> 1, j = ij & 1;
                float val = 0.f;
                if (s_vy[p][i] && s_vx[p][j]) {
                    float ly = s_ly[p][i], lx = s_lx[p][j];
                    float hy = 1.f - ly, hx = 1.f - lx;
                    int y0 = s_y0[p][i], y1 = s_y1[p][i];
                    int x0 = s_x0[p][j], x1 = s_x1[p][j];
                    const float* f; int W, HW;
                    if (p == 0)      { f = pyr0; W = 128; HW = 16 * 128; }
                    else if (p == 1) { f = pyr1; W = 64;  HW = 8 * 64;  }
                    else             { f = pyr2; W = 65;  HW = 4 * 65;  }
                    const float* fc = f + (size_t)c * HW;
                    val = fc[y0 * W + x0] * (hy * hx)
                        + fc[y0 * W + x1] * (hy * lx)
                        + fc[y1 * W + x0] * (ly * hx)
                        + fc[y1 * W + x1] * (ly * lx);
                }
                g_x[(size_t)b * RNN_IN + 896 + o] = val;
            }
        }
        gbar();

        // ===== D: gi GEMM — ctx K split3 (288) + crops K split2 (192) =====
        if (bid < 288) {
            int ks = bid / 96, j = bid % 96;
            gemm_t32x64(g_x, RNN_IN, gru_w_ih, RNN_IN, g_gip[ks], GRU3,
                        (j / 12) * 32, (j % 12) * 64, ks * 256, 8, sm, tid);
        } else if (bid < 480) {
            int jj = bid - 288;
            int ks = jj / 96, j = jj % 96;
            gemm_t32x64(g_x, RNN_IN, gru_w_ih, RNN_IN, g_gip[4 + ks], GRU3,
                        (j / 12) * 32, (j % 12) * 64, 896 + ks * 288, 9, sm, tid);
        }
        gbar();

        // ===== E: reduce + GRU; write next-step embedding =====
        if (bid < 256) {
            int g = bid * 256 + tid;
            int b = g >> 8, h = g & 255;
            size_t base = (size_t)b * GRU3;
            float ir = __ldg(gru_b_ih + h);
            float iz = __ldg(gru_b_ih + HID + h);
            float in = __ldg(gru_b_ih + 2 * HID + h);
#pragma unroll
            for (int p = 0; p < 6; p++) {
                ir += __ldcg(&g_gip[p][base + h]);
                iz += __ldcg(&g_gip[p][base + HID + h]);
                in += __ldcg(&g_gip[p][base + 2 * HID + h]);
            }
            float hr = __ldcg(&g_gh[base + h]);
            float hz = __ldcg(&g_gh[base + HID + h]);
            float hn = __ldcg(&g_gh[base + 2 * HID + h]);
            float rr = fsig(ir + hr);
            float zz = fsig(iz + hz);
            float nn = ftanh(in + rr * hn);
            float hold = __ldcg(&g_hidden[g]);
            float hnew = (1.f - zz) * nn + zz * hold;
            g_hidden[g] = hnew;
            g_hs[((size_t)b * NSTEPS + step) * HID + h] = hnew;
        } else if (bid < 512) {
            int b = bid - 256;
            if (tid < EMB) {
                int tgt = __ldg(text + b * NSTEPS + step) + 1;
                g_x[(size_t)b * RNN_IN + 768 + tid] = __ldg(char_emb + (size_t)tgt * EMB + tid);
            }
        }
        gbar();
    }

    // ===== final classifier =====
    {
        int gw = bid * 8 + wid;
        for (int m = gw; m < NB * NSTEPS; m += NWARP) {
            const float* hrow = g_hs + (size_t)m * HID;
            float a[8];
#pragma unroll
            for (int q = 0; q < 8; q++) a[q] = __ldcg(hrow + lane + q * 32);
            for (int n = 0; n < NCLS; n++) {
                const float* w = gen_w + (size_t)n * HID;
                float s = 0.f;
#pragma unroll
                for (int q = 0; q < 8; q++) s += a[q] * __ldg(w + lane + q * 32);
#pragma unroll
                for (int o = 16; o; o >>= 1) s += __shfl_xor_sync(~0u, s, o);
                if (!lane) out[(size_t)m * NCLS + n] = s + gen_b[n];
            }
        }
    }
}

// ---------------- driver ----------------
extern "C" void kernel_launch(void* const* d_in, const int* in_sizes, int n_in,
                              void* d_out, int out_size)
{
    const float* feats    = (const float*)d_in[0];
    const float* pose     = (const float*)d_in[1];
    const float* pyr0     = (const float*)d_in[2];
    const float* pyr1     = (const float*)d_in[3];
    const float* pyr2     = (const float*)d_in[4];
    const int*   text     = (const int*)  d_in[6];
    const float* i2h_w    = (const float*)d_in[7];
    const float* h2h_w    = (const float*)d_in[8];
    const float* h2h_b    = (const float*)d_in[9];
    const float* score_w  = (const float*)d_in[10];
    const float* pose_w   = (const float*)d_in[11];
    const float* pose_b   = (const float*)d_in[12];
    const float* gru_w_ih = (const float*)d_in[13];
    const float* gru_w_hh = (const float*)d_in[14];
    const float* gru_b_ih = (const float*)d_in[15];
    const float* gru_b_hh = (const float*)d_in[16];
    const float* char_emb = (const float*)d_in[17];
    const float* gen_w    = (const float*)d_in[18];
    const float* gen_b    = (const float*)d_in[19];
    float* out = (float*)d_out;

    dim3 g1(2, 256);
    fp_gemm<<<g1, 256>>>(feats, i2h_w);

    decode_kernel<<<NCTA, 256>>>(feats, pose, pyr0, pyr1, pyr2, text,
                                 h2h_w, h2h_b, score_w, pose_w, pose_b,
                                 gru_w_ih, gru_w_hh, gru_b_ih, gru_b_hh,
                                 char_emb, gen_w, gen_b, out);
}

// round 6
// speedup vs baseline: 1.5211x; 1.1274x over previous
#include <cuda_runtime.h>
#include <cuda_fp16.h>
#include <math.h>

#define NT 128
#define NB 256
#define NC 512
#define HID 256
#define EMB 128
#define NCLS 37
#define NSTEPS 25
#define POSE 256
#define RNN_IN 1472
#define GRU3 768
#define NCTA 592
#define NWARP (NCTA * 8)

// ---------------- scratch ----------------
__device__ __align__(16) __half g_fp16[NT * NB * HID];
__device__ __half2 g_feats16[NT * NB * NC / 2];
__device__ __half  g_pose16T[NT * NB * POSE];
__device__ float g_hp[NB * HID];
__device__ float g_ghp[2][NB * GRU3];
__device__ float g_e[NB * NT];
__device__ float g_x[NB * RNN_IN];
__device__ float g_gip[11][NB * GRU3];
__device__ float g_hidden[NB * HID];
__device__ float g_hs[NSTEPS * NB * HID];

// barrier state
__device__ unsigned g_cnt[17 * 32];
__device__ unsigned g_rel[16 * 32];

// ---------------- barrier primitives ----------------
__device__ __forceinline__ unsigned ld_acq(const unsigned* p) {
    unsigned v;
    asm volatile("ld.acquire.gpu.global.u32 %0,[%1];" : "=r"(v) : "l"(p) : "memory");
    return v;
}
__device__ __forceinline__ unsigned atom_inc_rel(unsigned* p) {
    unsigned v;
    asm volatile("atom.release.gpu.global.add.u32 %0,[%1],1;" : "=r"(v) : "l"(p) : "memory");
    return v;
}
__device__ __forceinline__ void st_rel(unsigned* p, unsigned v) {
    asm volatile("st.release.gpu.global.u32 [%0],%1;" :: "l"(p), "r"(v) : "memory");
}
__device__ __forceinline__ void gbar() {
    __syncthreads();
    if (threadIdx.x == 0) {
        int g = blockIdx.x / 37;
        unsigned* cnt = &g_cnt[g * 32];
        unsigned* rel = &g_rel[g * 32];
        unsigned gen = ld_acq(rel);
        if (atom_inc_rel(cnt) == 36u) {
            *(volatile unsigned*)cnt = 0u;
            if (atom_inc_rel(&g_cnt[16 * 32]) == 15u) {
                *(volatile unsigned*)&g_cnt[16 * 32] = 0u;
#pragma unroll
                for (int i = 0; i < 16; i++) st_rel(&g_rel[i * 32], gen + 1u);
            } else {
                while (ld_acq(rel) == gen) __nanosleep(32);
            }
        } else {
            while (ld_acq(rel) == gen) __nanosleep(32);
        }
    }
    __syncthreads();
}

// ---------------- f32x2 helpers ----------------
__device__ __forceinline__ unsigned long long pk2(float lo, float hi) {
    unsigned long long r;
    asm("mov.b64 %0,{%1,%2};" : "=l"(r) : "f"(lo), "f"(hi));
    return r;
}
__device__ __forceinline__ void fma2(unsigned long long& d, unsigned long long a,
                                     unsigned long long b) {
    asm("fma.rn.f32x2 %0,%1,%2,%0;" : "+l"(d) : "l"(a), "l"(b));
}
__device__ __forceinline__ void up2(unsigned long long v, float& a, float& b) {
    asm("mov.b64 {%0,%1},%2;" : "=f"(a), "=f"(b) : "l"(v));
}

// ---------------- fast transcendentals ----------------
__device__ __forceinline__ float fsig(float x) {
    return __fdividef(1.f, 1.f + __expf(-x));
}
__device__ __forceinline__ float ftanh(float x) {
    float r;
    asm("tanh.approx.f32 %0,%1;" : "=f"(r) : "f"(x));
    return r;
}
__device__ __forceinline__ __half2 htanh2(__half2 x) {
    __half2 r;
    asm("tanh.approx.f16x2 %0,%1;" : "=r"(*(unsigned*)&r) : "r"(*(unsigned*)&x));
    return r;
}

// ---------------- 64x64 tile GEMM, C = A@B^T (no bias), f32x2, short-K ----------------
__device__ __forceinline__ void gemm64(const float* __restrict__ A, int lda,
                                       const float* __restrict__ B, int ldb,
                                       float* __restrict__ C, int ldc,
                                       int m0, int n0, int kbase, int kiters,
                                       float* sm, int tid)
{
    float* As = sm;          // [32][68]
    float* Bs = sm + 2176;   // [32][68]
    const int ty = tid >> 4, tx = tid & 15;
    unsigned long long acc[4][2] = {};
    const int row = tid >> 2;           // 0..63
    const int kk = (tid & 3) * 8;       // 0,8,16,24
    const float* Ag = A + (size_t)(m0 + row) * lda + kbase + kk;
    const float* Bg = B + (size_t)(n0 + row) * ldb + kbase + kk;
    for (int kc = 0; kc < kiters; kc++) {
        float4 a0 = __ldcg((const float4*)(Ag + kc * 32));
        float4 a1 = __ldcg((const float4*)(Ag + kc * 32 + 4));
        float4 b0 = __ldg((const float4*)(Bg + kc * 32));
        float4 b1 = __ldg((const float4*)(Bg + kc * 32 + 4));
        As[(kk + 0) * 68 + row] = a0.x; As[(kk + 1) * 68 + row] = a0.y;
        As[(kk + 2) * 68 + row] = a0.z; As[(kk + 3) * 68 + row] = a0.w;
        As[(kk + 4) * 68 + row] = a1.x; As[(kk + 5) * 68 + row] = a1.y;
        As[(kk + 6) * 68 + row] = a1.z; As[(kk + 7) * 68 + row] = a1.w;
        Bs[(kk + 0) * 68 + row] = b0.x; Bs[(kk + 1) * 68 + row] = b0.y;
        Bs[(kk + 2) * 68 + row] = b0.z; Bs[(kk + 3) * 68 + row] = b0.w;
        Bs[(kk + 4) * 68 + row] = b1.x; Bs[(kk + 5) * 68 + row] = b1.y;
        Bs[(kk + 6) * 68 + row] = b1.z; Bs[(kk + 7) * 68 + row] = b1.w;
        __syncthreads();
#pragma unroll
        for (int k = 0; k < 32; k++) {
            float4 a = *(const float4*)&As[k * 68 + ty * 4];
            ulonglong2 pb = *(const ulonglong2*)&Bs[k * 68 + tx * 4];
            float av[4] = {a.x, a.y, a.z, a.w};
#pragma unroll
            for (int i = 0; i < 4; i++) {
                unsigned long long pa = pk2(av[i], av[i]);
                fma2(acc[i][0], pa, pb.x);
                fma2(acc[i][1], pa, pb.y);
            }
        }
        __syncthreads();
    }
#pragma unroll
    for (int i = 0; i < 4; i++) {
        int gm = m0 + ty * 4 + i;
        float v0, v1, v2, v3;
        up2(acc[i][0], v0, v1);
        up2(acc[i][1], v2, v3);
        float4 v = {v0, v1, v2, v3};
        *(float4*)(C + (size_t)gm * ldc + n0 + tx * 4) = v;
    }
}

// ---------------- feats_proj GEMM -> fp16 ----------------
__global__ __launch_bounds__(256) void fp_gemm(const float* __restrict__ A,
                                               const float* __restrict__ B)
{
    __shared__ __align__(16) float As[16 * 132];
    __shared__ __align__(16) float Bs[16 * 132];
    const int tid = threadIdx.x;
    const int m0 = blockIdx.y * 128;
    const int n0 = blockIdx.x * 128;
    const int ty = tid >> 4, tx = tid & 15;
    unsigned long long acc[8][4];
#pragma unroll
    for (int i = 0; i < 8; i++)
#pragma unroll
        for (int j = 0; j < 4; j++) acc[i][j] = 0ull;

    for (int k0 = 0; k0 < NC; k0 += 16) {
#pragma unroll
        for (int p = 0; p < 8; p++) {
            int i = p * 256 + tid;
            int kk = i & 15, mm = i >> 4;
            As[kk * 132 + mm] = A[(size_t)(m0 + mm) * NC + k0 + kk];
            Bs[kk * 132 + mm] = B[(size_t)(n0 + mm) * NC + k0 + kk];
        }
        __syncthreads();
#pragma unroll
        for (int k = 0; k < 16; k++) {
            float4 x0 = *(const float4*)&As[k * 132 + ty * 8];
            float4 x1 = *(const float4*)&As[k * 132 + ty * 8 + 4];
            ulonglong2 q0 = *(const ulonglong2*)&Bs[k * 132 + tx * 8];
            ulonglong2 q1 = *(const ulonglong2*)&Bs[k * 132 + tx * 8 + 4];
            float av[8] = {x0.x, x0.y, x0.z, x0.w, x1.x, x1.y, x1.z, x1.w};
            unsigned long long pb[4] = {q0.x, q0.y, q1.x, q1.y};
#pragma unroll
            for (int i = 0; i < 8; i++) {
                unsigned long long pa = pk2(av[i], av[i]);
#pragma unroll
                for (int j = 0; j < 4; j++) fma2(acc[i][j], pa, pb[j]);
            }
        }
        __syncthreads();
    }
#pragma unroll
    for (int i = 0; i < 8; i++) {
        int gm = m0 + ty * 8 + i;
#pragma unroll
        for (int j = 0; j < 4; j++) {
            float lo, hi;
            up2(acc[i][j], lo, hi);
            *(__half2*)(g_fp16 + (size_t)gm * HID + n0 + tx * 8 + 2 * j) =
                __floats2half2_rn(lo, hi);
        }
    }
}

// ---------------- persistent decode kernel ----------------
__global__ __launch_bounds__(256, 4) void decode_kernel(
    const float* __restrict__ feats,
    const float* __restrict__ pose,
    const float* __restrict__ pyr0,
    const float* __restrict__ pyr1,
    const float* __restrict__ pyr2,
    const int*   __restrict__ text,
    const float* __restrict__ h2h_w,    const float* __restrict__ h2h_b,
    const float* __restrict__ score_w,
    const float* __restrict__ pose_w,   const float* __restrict__ pose_b,
    const float* __restrict__ gru_w_ih, const float* __restrict__ gru_w_hh,
    const float* __restrict__ gru_b_ih, const float* __restrict__ gru_b_hh,
    const float* __restrict__ char_emb,
    const float* __restrict__ gen_w,    const float* __restrict__ gen_b,
    float* __restrict__ out)
{
    __shared__ __align__(16) float sm[4352];
    __shared__ float s_coord[4];
    __shared__ float s_ly[3][2], s_lx[3][2];
    __shared__ int   s_y0[3][2], s_y1[3][2], s_x0[3][2], s_x1[3][2];
    __shared__ int   s_vy[3][2], s_vx[3][2];

    const int tid = threadIdx.x;
    const int bid = blockIdx.x;
    const int lane = tid & 31;
    const int wid = tid >> 5;

    // ---- prologue: hidden=0, hp=bias, step-0 emb, fp16 copies ----
    if (bid < 256) {
        g_hidden[bid * 256 + tid] = 0.f;
        g_hp[bid * 256 + tid] = __ldg(h2h_b + tid);
        if (tid < EMB) g_x[(size_t)bid * RNN_IN + 768 + tid] = __ldg(char_emb + tid);
    }
    {
        const float2* fsrc = (const float2*)feats;
        for (int i = bid * 256 + tid; i < NT * NB * NC / 2; i += NCTA * 256) {
            float2 v = __ldg(fsrc + i);
            g_feats16[i] = __floats2half2_rn(v.x, v.y);
        }
    }
    for (int job = bid; job < NB * 32; job += NCTA) {
        int b = job >> 5;
        int r = job & 31;
        int t0 = (r & 3) * 32;
        int p0 = (r >> 2) * 32;
        int y = tid >> 5, x = tid & 31;
#pragma unroll
        for (int q = 0; q < 4; q++) {
            int yy = y + q * 8;
            sm[yy * 33 + x] = __ldg(pose + ((size_t)b * POSE + (p0 + yy)) * NT + (t0 + x));
        }
        __syncthreads();
#pragma unroll
        for (int q = 0; q < 4; q++) {
            int yy = y + q * 8;
            g_pose16T[((size_t)(t0 + yy) * NB + b) * POSE + (p0 + x)] =
                __float2half(sm[x * 33 + yy]);
        }
        __syncthreads();
    }
    gbar();

    for (int step = 0; step < NSTEPS; step++) {
        // ===== P1: energy (256 CTAs) + gh GEMM (96) + gi_emb GEMM (48) =====
        if (bid < 256) {
            int gw = bid * 8 + wid;          // 0..2047
            int b = gw >> 3;
            int tg = gw & 7;
            float4 hpa = __ldcg((const float4*)(g_hp + (size_t)b * HID + lane * 8));
            float4 hpb = __ldcg((const float4*)(g_hp + (size_t)b * HID + lane * 8 + 4));
            __half2 hph[4] = {
                __floats2half2_rn(hpa.x, hpa.y), __floats2half2_rn(hpa.z, hpa.w),
                __floats2half2_rn(hpb.x, hpb.y), __floats2half2_rn(hpb.z, hpb.w)};
            float4 swa = __ldg((const float4*)(score_w + lane * 8));
            float4 swb = __ldg((const float4*)(score_w + lane * 8 + 4));
            float swf[8] = {swa.x, swa.y, swa.z, swa.w, swb.x, swb.y, swb.z, swb.w};
#pragma unroll
            for (int i = 0; i < 16; i++) {
                int t = tg * 16 + i;
                uint4 fv = __ldg((const uint4*)(g_fp16 + ((size_t)t * NB + b) * HID + lane * 8));
                __half2 v0 = *(__half2*)&fv.x, v1 = *(__half2*)&fv.y;
                __half2 v2 = *(__half2*)&fv.z, v3 = *(__half2*)&fv.w;
                float2 t0 = __half22float2(htanh2(__hadd2(v0, hph[0])));
                float2 t1 = __half22float2(htanh2(__hadd2(v1, hph[1])));
                float2 t2 = __half22float2(htanh2(__hadd2(v2, hph[2])));
                float2 t3 = __half22float2(htanh2(__hadd2(v3, hph[3])));
                float s = t0.x * swf[0] + t0.y * swf[1] + t1.x * swf[2] + t1.y * swf[3]
                        + t2.x * swf[4] + t2.y * swf[5] + t3.x * swf[6] + t3.y * swf[7];
#pragma unroll
                for (int o = 16; o; o >>= 1) s += __shfl_xor_sync(~0u, s, o);
                if (!lane) g_e[b * NT + t] = s;
            }
        } else if (bid < 352) {
            int jj = bid - 256;
            int ks = jj / 48, j = jj % 48;
            gemm64(g_hidden, HID, gru_w_hh, HID, g_ghp[ks], GRU3,
                   (j / 12) * 64, (j % 12) * 64, ks * 128, 4, sm, tid);
        } else if (bid < 400) {
            int j = bid - 352;
            gemm64(g_x, RNN_IN, gru_w_ih, RNN_IN, g_gip[10], GRU3,
                   (j / 12) * 64, (j % 12) * 64, 768, 4, sm, tid);
        }
        gbar();

        // ===== P2: per-b softmax (1 warp) + ctx + coord + crops =====
        if (bid < NB) {
            int b = bid;
            float* al = sm;
            float* ctx_s = sm + 128;
            if (wid == 0) {
                float ev[4];
#pragma unroll
                for (int q = 0; q < 4; q++) ev[q] = __ldcg(g_e + b * NT + lane + 32 * q);
                float mx = fmaxf(fmaxf(ev[0], ev[1]), fmaxf(ev[2], ev[3]));
#pragma unroll
                for (int o = 16; o; o >>= 1) mx = fmaxf(mx, __shfl_xor_sync(~0u, mx, o));
                float ex[4], ssum = 0.f;
#pragma unroll
                for (int q = 0; q < 4; q++) { ex[q] = __expf(ev[q] - mx); ssum += ex[q]; }
#pragma unroll
                for (int o = 16; o; o >>= 1) ssum += __shfl_xor_sync(~0u, ssum, o);
                float inv = __fdividef(1.f, ssum);
#pragma unroll
                for (int q = 0; q < 4; q++) al[lane + 32 * q] = ex[q] * inv;
            }
            __syncthreads();
            // ctx: feats (2 ch/thread) + pose (1 ch/thread)
            {
                const __half2* f2 = g_feats16 + (size_t)b * (NC / 2) + tid;
                float2 acc = {0.f, 0.f};
#pragma unroll 16
                for (int t = 0; t < NT; t++) {
                    float2 vf = __half22float2(__ldg(f2 + (size_t)t * NB * (NC / 2)));
                    float a = al[t];
                    acc.x = fmaf(a, vf.x, acc.x);
                    acc.y = fmaf(a, vf.y, acc.y);
                }
                ctx_s[2 * tid] = acc.x;
                ctx_s[2 * tid + 1] = acc.y;
                *(float2*)(g_x + (size_t)b * RNN_IN + 2 * tid) = acc;
            }
            {
                const __half* pp = g_pose16T + (size_t)b * POSE + tid;
                float acc = 0.f;
#pragma unroll 16
                for (int t = 0; t < NT; t++)
                    acc = fmaf(al[t], __half2float(__ldg(pp + (size_t)t * NB * POSE)), acc);
                ctx_s[NC + tid] = acc;
                g_x[(size_t)b * RNN_IN + NC + tid] = acc;
            }
            __syncthreads();
            if (wid < 4) {
                const float* pw = pose_w + wid * 768;
                float s = 0.f;
#pragma unroll
                for (int q = 0; q < 24; q++) { int c = lane + q * 32; s += ctx_s[c] * __ldg(pw + c); }
#pragma unroll
                for (int o = 16; o; o >>= 1) s += __shfl_xor_sync(~0u, s, o);
                if (!lane) s_coord[wid] = fsig(s + __ldg(pose_b + wid));
            }
            __syncthreads();
            if (tid == 0) {
                const int Hs[3] = {16, 8, 4};
                const int Ws[3] = {128, 64, 65};
                float c0 = s_coord[0], c1 = s_coord[1], c2 = s_coord[2], c3 = s_coord[3];
                for (int p = 0; p < 3; p++) {
                    float Hf = (float)Hs[p], Wf = (float)Ws[p];
                    c0 *= Hf; c1 *= Wf; c2 *= Hf; c3 *= Wf;
                    float x1 = c0, y1 = c1, x2 = c2, y2 = c3;
                    float bw = fmaxf(x2 - x1, 1.f) * 0.5f;
                    float bh = fmaxf(y2 - y1, 1.f) * 0.5f;
#pragma unroll
                    for (int i = 0; i < 2; i++) {
                        float ys = y1 + (0.5f + (float)i) * bh;
                        s_vy[p][i] = (ys >= -1.f && ys <= Hf) ? 1 : 0;
                        float y = fminf(fmaxf(ys, 0.f), Hf - 1.f);
                        float y0f = floorf(y);
                        int y0i = (int)y0f;
                        s_y0[p][i] = y0i;
                        s_y1[p][i] = min(y0i + 1, Hs[p] - 1);
                        s_ly[p][i] = y - y0f;
                        float xs = x1 + (0.5f + (float)i) * bw;
                        s_vx[p][i] = (xs >= -1.f && xs <= Wf) ? 1 : 0;
                        float x = fminf(fmaxf(xs, 0.f), Wf - 1.f);
                        float x0f = floorf(x);
                        int x0i = (int)x0f;
                        s_x0[p][i] = x0i;
                        s_x1[p][i] = min(x0i + 1, Ws[p] - 1);
                        s_lx[p][i] = x - x0f;
                    }
                }
            }
            __syncthreads();
            for (int o = tid; o < 576; o += 256) {
                int p, local;
                if (o < 64)       { p = 0; local = o; }
                else if (o < 320) { p = 1; local = o - 64; }
                else              { p = 2; local = o - 320; }
                int c = local >> 2;
                int ij = local & 3;
                int i = ij >> 1, j = ij & 1;
                float val = 0.f;
                if (s_vy[p][i] && s_vx[p][j]) {
                    float ly = s_ly[p][i], lx = s_lx[p][j];
                    float hy = 1.f - ly, hx = 1.f - lx;
                    int y0 = s_y0[p][i], y1 = s_y1[p][i];
                    int x0 = s_x0[p][j], x1 = s_x1[p][j];
                    const float* f; int W, HW;
                    if (p == 0)      { f = pyr0; W = 128; HW = 16 * 128; }
                    else if (p == 1) { f = pyr1; W = 64;  HW = 8 * 64;  }
                    else             { f = pyr2; W = 65;  HW = 4 * 65;  }
                    const float* fc = f + (size_t)c * HW;
                    val = fc[y0 * W + x0] * (hy * hx)
                        + fc[y0 * W + x1] * (hy * lx)
                        + fc[y1 * W + x0] * (ly * hx)
                        + fc[y1 * W + x1] * (ly * lx);
                }
                g_x[(size_t)b * RNN_IN + 896 + o] = val;
            }
        }
        gbar();

        // ===== P3: gi GEMMs — ctx K split6 (288 jobs) + crops K split4 (192 jobs)
        if (bid < 288) {
            int ks = bid / 48, j = bid % 48;
            gemm64(g_x, RNN_IN, gru_w_ih, RNN_IN, g_gip[ks], GRU3,
                   (j / 12) * 64, (j % 12) * 64, ks * 128, 4, sm, tid);
        } else if (bid < 480) {
            int jj = bid - 288;
            int ks = jj / 48, j = jj % 48;
            int kb = (ks < 2) ? (896 + ks * 128) : (1152 + (ks - 2) * 160);
            int ki = (ks < 2) ? 4 : 5;
            gemm64(g_x, RNN_IN, gru_w_ih, RNN_IN, g_gip[6 + ks], GRU3,
                   (j / 12) * 64, (j % 12) * 64, kb, ki, sm, tid);
        }
        gbar();

        // ===== P4: GRU reduce + fused hp matvec + next emb (64 CTAs) =====
        if (bid < 64) {
            float* hn_s = sm;  // [4][260]
            int h = tid;
#pragma unroll
            for (int bb = 0; bb < 4; bb++) {
                int b = bid * 4 + bb;
                size_t base = (size_t)b * GRU3;
                float ir = __ldg(gru_b_ih + h);
                float iz = __ldg(gru_b_ih + HID + h);
                float in = __ldg(gru_b_ih + 2 * HID + h);
#pragma unroll
                for (int p = 0; p < 11; p++) {
                    ir += __ldcg(&g_gip[p][base + h]);
                    iz += __ldcg(&g_gip[p][base + HID + h]);
                    in += __ldcg(&g_gip[p][base + 2 * HID + h]);
                }
                float hr = __ldg(gru_b_hh + h)           + __ldcg(&g_ghp[0][base + h])           + __ldcg(&g_ghp[1][base + h]);
                float hz = __ldg(gru_b_hh + HID + h)     + __ldcg(&g_ghp[0][base + HID + h])     + __ldcg(&g_ghp[1][base + HID + h]);
                float hn = __ldg(gru_b_hh + 2 * HID + h) + __ldcg(&g_ghp[0][base + 2 * HID + h]) + __ldcg(&g_ghp[1][base + 2 * HID + h]);
                float rr = fsig(ir + hr);
                float zz = fsig(iz + hz);
                float nn = ftanh(in + rr * hn);
                float hold = __ldcg(&g_hidden[(size_t)b * HID + h]);
                float hnew = (1.f - zz) * nn + zz * hold;
                g_hidden[(size_t)b * HID + h] = hnew;
                g_hs[((size_t)b * NSTEPS + step) * HID + h] = hnew;
                hn_s[bb * 260 + h] = hnew;
            }
            __syncthreads();
            // hp[b][n] = hnew[b] . h2h_w[n] + h2h_b[n], n = tid
            {
                int n = tid;
                float acc0 = 0.f, acc1 = 0.f, acc2 = 0.f, acc3 = 0.f;
                const float4* w4 = (const float4*)(h2h_w + (size_t)n * HID);
#pragma unroll 8
                for (int hq = 0; hq < 64; hq++) {
                    float4 w = __ldg(w4 + hq);
                    int hh = hq * 4;
                    acc0 += w.x * hn_s[0 * 260 + hh] + w.y * hn_s[0 * 260 + hh + 1]
                          + w.z * hn_s[0 * 260 + hh + 2] + w.w * hn_s[0 * 260 + hh + 3];
                    acc1 += w.x * hn_s[1 * 260 + hh] + w.y * hn_s[1 * 260 + hh + 1]
                          + w.z * hn_s[1 * 260 + hh + 2] + w.w * hn_s[1 * 260 + hh + 3];
                    acc2 += w.x * hn_s[2 * 260 + hh] + w.y * hn_s[2 * 260 + hh + 1]
                          + w.z * hn_s[2 * 260 + hh + 2] + w.w * hn_s[2 * 260 + hh + 3];
                    acc3 += w.x * hn_s[3 * 260 + hh] + w.y * hn_s[3 * 260 + hh + 1]
                          + w.z * hn_s[3 * 260 + hh + 2] + w.w * hn_s[3 * 260 + hh + 3];
                }
                float bb0 = __ldg(h2h_b + n);
                g_hp[(size_t)(bid * 4 + 0) * HID + n] = acc0 + bb0;
                g_hp[(size_t)(bid * 4 + 1) * HID + n] = acc1 + bb0;
                g_hp[(size_t)(bid * 4 + 2) * HID + n] = acc2 + bb0;
                g_hp[(size_t)(bid * 4 + 3) * HID + n] = acc3 + bb0;
            }
            // next-step embedding
            if (step + 1 < NSTEPS && tid < EMB) {
#pragma unroll
                for (int bb = 0; bb < 4; bb++) {
                    int b = bid * 4 + bb;
                    int tgt = __ldg(text + b * NSTEPS + step) + 1;
                    g_x[(size_t)b * RNN_IN + 768 + tid] = __ldg(char_emb + (size_t)tgt * EMB + tid);
                }
            }
        }
        gbar();
    }

    // ===== final classifier =====
    {
        int gw = bid * 8 + wid;
        for (int m = gw; m < NB * NSTEPS; m += NWARP) {
            const float* hrow = g_hs + (size_t)m * HID;
            float a[8];
#pragma unroll
            for (int q = 0; q < 8; q++) a[q] = __ldcg(hrow + lane + q * 32);
            for (int n = 0; n < NCLS; n++) {
                const float* w = gen_w + (size_t)n * HID;
                float s = 0.f;
#pragma unroll
                for (int q = 0; q < 8; q++) s += a[q] * __ldg(w + lane + q * 32);
#pragma unroll
                for (int o = 16; o; o >>= 1) s += __shfl_xor_sync(~0u, s, o);
                if (!lane) out[(size_t)m * NCLS + n] = s + gen_b[n];
            }
        }
    }
}

// ---------------- driver ----------------
extern "C" void kernel_launch(void* const* d_in, const int* in_sizes, int n_in,
                              void* d_out, int out_size)
{
    const float* feats    = (const float*)d_in[0];
    const float* pose     = (const float*)d_in[1];
    const float* pyr0     = (const float*)d_in[2];
    const float* pyr1     = (const float*)d_in[3];
    const float* pyr2     = (const float*)d_in[4];
    const int*   text     = (const int*)  d_in[6];
    const float* i2h_w    = (const float*)d_in[7];
    const float* h2h_w    = (const float*)d_in[8];
    const float* h2h_b    = (const float*)d_in[9];
    const float* score_w  = (const float*)d_in[10];
    const float* pose_w   = (const float*)d_in[11];
    const float* pose_b   = (const float*)d_in[12];
    const float* gru_w_ih = (const float*)d_in[13];
    const float* gru_w_hh = (const float*)d_in[14];
    const float* gru_b_ih = (const float*)d_in[15];
    const float* gru_b_hh = (const float*)d_in[16];
    const float* char_emb = (const float*)d_in[17];
    const float* gen_w    = (const float*)d_in[18];
    const float* gen_b    = (const float*)d_in[19];
    float* out = (float*)d_out;

    dim3 g1(2, 256);
    fp_gemm<<<g1, 256>>>(feats, i2h_w);

    decode_kernel<<<NCTA, 256>>>(feats, pose, pyr0, pyr1, pyr2, text,
                                 h2h_w, h2h_b, score_w, pose_w, pose_b,
                                 gru_w_ih, gru_w_hh, gru_b_ih, gru_b_hh,
                                 char_emb, gen_w, gen_b, out);
}

// round 7
// speedup vs baseline: 1.8292x; 1.2026x over previous
#include <cuda_runtime.h>
#include <cuda_fp16.h>
#include <math.h>

#define NT 128
#define NB 256
#define NC 512
#define HID 256
#define EMB 128
#define NCLS 37
#define NSTEPS 25
#define POSE 256
#define RNN_IN 1472
#define GRU3 768
#define NCTA 592
#define NWARP (NCTA * 8)

// ---------------- scratch ----------------
__device__ __align__(16) __half g_fp16[NT * NB * HID];
__device__ __half2 g_feats16[NT * NB * NC / 2];
__device__ __half  g_pose16T[NT * NB * POSE];
__device__ __align__(16) __half g_h2h16[HID * HID];
__device__ float g_gh[NB * GRU3];
__device__ float g_x[NB * RNN_IN];
__device__ float g_gip[11][NB * GRU3];
__device__ float g_hidden[NB * HID];
__device__ float g_hs[NSTEPS * NB * HID];

// barrier state
__device__ unsigned g_cnt[17 * 32];
__device__ unsigned g_rel[16 * 32];

// ---------------- barrier primitives ----------------
__device__ __forceinline__ unsigned ld_acq(const unsigned* p) {
    unsigned v;
    asm volatile("ld.acquire.gpu.global.u32 %0,[%1];" : "=r"(v) : "l"(p) : "memory");
    return v;
}
__device__ __forceinline__ unsigned atom_inc_rel(unsigned* p) {
    unsigned v;
    asm volatile("atom.release.gpu.global.add.u32 %0,[%1],1;" : "=r"(v) : "l"(p) : "memory");
    return v;
}
__device__ __forceinline__ void st_rel(unsigned* p, unsigned v) {
    asm volatile("st.release.gpu.global.u32 [%0],%1;" :: "l"(p), "r"(v) : "memory");
}
__device__ __forceinline__ void gbar() {
    __syncthreads();
    if (threadIdx.x == 0) {
        int g = blockIdx.x / 37;
        unsigned* cnt = &g_cnt[g * 32];
        unsigned* rel = &g_rel[g * 32];
        unsigned gen = ld_acq(rel);
        if (atom_inc_rel(cnt) == 36u) {
            *(volatile unsigned*)cnt = 0u;
            if (atom_inc_rel(&g_cnt[16 * 32]) == 15u) {
                *(volatile unsigned*)&g_cnt[16 * 32] = 0u;
#pragma unroll
                for (int i = 0; i < 16; i++) st_rel(&g_rel[i * 32], gen + 1u);
            } else {
                while (ld_acq(rel) == gen) __nanosleep(32);
            }
        } else {
            while (ld_acq(rel) == gen) __nanosleep(32);
        }
    }
    __syncthreads();
}

// ---------------- f32x2 helpers ----------------
__device__ __forceinline__ unsigned long long pk2(float lo, float hi) {
    unsigned long long r;
    asm("mov.b64 %0,{%1,%2};" : "=l"(r) : "f"(lo), "f"(hi));
    return r;
}
__device__ __forceinline__ void fma2(unsigned long long& d, unsigned long long a,
                                     unsigned long long b) {
    asm("fma.rn.f32x2 %0,%1,%2,%0;" : "+l"(d) : "l"(a), "l"(b));
}
__device__ __forceinline__ void up2(unsigned long long v, float& a, float& b) {
    asm("mov.b64 {%0,%1},%2;" : "=f"(a), "=f"(b) : "l"(v));
}

// ---------------- fast transcendentals ----------------
__device__ __forceinline__ float fsig(float x) {
    return __fdividef(1.f, 1.f + __expf(-x));
}
__device__ __forceinline__ float ftanh(float x) {
    float r;
    asm("tanh.approx.f32 %0,%1;" : "=f"(r) : "f"(x));
    return r;
}
__device__ __forceinline__ __half2 htanh2(__half2 x) {
    __half2 r;
    asm("tanh.approx.f16x2 %0,%1;" : "=r"(*(unsigned*)&r) : "r"(*(unsigned*)&x));
    return r;
}

// ---------------- 64x64 tile GEMM, C = A@B^T, f32x2 ----------------
__device__ __forceinline__ void gemm64(const float* __restrict__ A, int lda,
                                       const float* __restrict__ B, int ldb,
                                       float* __restrict__ C, int ldc,
                                       int m0, int n0, int kbase, int kiters,
                                       float* sm, int tid)
{
    float* As = sm;          // [32][68]
    float* Bs = sm + 2176;   // [32][68]
    const int ty = tid >> 4, tx = tid & 15;
    unsigned long long acc[4][2] = {};
    const int row = tid >> 2;
    const int kk = (tid & 3) * 8;
    const float* Ag = A + (size_t)(m0 + row) * lda + kbase + kk;
    const float* Bg = B + (size_t)(n0 + row) * ldb + kbase + kk;
    for (int kc = 0; kc < kiters; kc++) {
        float4 a0 = __ldcg((const float4*)(Ag + kc * 32));
        float4 a1 = __ldcg((const float4*)(Ag + kc * 32 + 4));
        float4 b0 = __ldg((const float4*)(Bg + kc * 32));
        float4 b1 = __ldg((const float4*)(Bg + kc * 32 + 4));
        As[(kk + 0) * 68 + row] = a0.x; As[(kk + 1) * 68 + row] = a0.y;
        As[(kk + 2) * 68 + row] = a0.z; As[(kk + 3) * 68 + row] = a0.w;
        As[(kk + 4) * 68 + row] = a1.x; As[(kk + 5) * 68 + row] = a1.y;
        As[(kk + 6) * 68 + row] = a1.z; As[(kk + 7) * 68 + row] = a1.w;
        Bs[(kk + 0) * 68 + row] = b0.x; Bs[(kk + 1) * 68 + row] = b0.y;
        Bs[(kk + 2) * 68 + row] = b0.z; Bs[(kk + 3) * 68 + row] = b0.w;
        Bs[(kk + 4) * 68 + row] = b1.x; Bs[(kk + 5) * 68 + row] = b1.y;
        Bs[(kk + 6) * 68 + row] = b1.z; Bs[(kk + 7) * 68 + row] = b1.w;
        __syncthreads();
#pragma unroll
        for (int k = 0; k < 32; k++) {
            float4 a = *(const float4*)&As[k * 68 + ty * 4];
            ulonglong2 pb = *(const ulonglong2*)&Bs[k * 68 + tx * 4];
            float av[4] = {a.x, a.y, a.z, a.w};
#pragma unroll
            for (int i = 0; i < 4; i++) {
                unsigned long long pa = pk2(av[i], av[i]);
                fma2(acc[i][0], pa, pb.x);
                fma2(acc[i][1], pa, pb.y);
            }
        }
        __syncthreads();
    }
#pragma unroll
    for (int i = 0; i < 4; i++) {
        int gm = m0 + ty * 4 + i;
        float v0, v1, v2, v3;
        up2(acc[i][0], v0, v1);
        up2(acc[i][1], v2, v3);
        float4 v = {v0, v1, v2, v3};
        *(float4*)(C + (size_t)gm * ldc + n0 + tx * 4) = v;
    }
}

// ---------------- feats_proj GEMM -> fp16 ----------------
__global__ __launch_bounds__(256) void fp_gemm(const float* __restrict__ A,
                                               const float* __restrict__ B)
{
    __shared__ __align__(16) float As[16 * 132];
    __shared__ __align__(16) float Bs[16 * 132];
    const int tid = threadIdx.x;
    const int m0 = blockIdx.y * 128;
    const int n0 = blockIdx.x * 128;
    const int ty = tid >> 4, tx = tid & 15;
    unsigned long long acc[8][4];
#pragma unroll
    for (int i = 0; i < 8; i++)
#pragma unroll
        for (int j = 0; j < 4; j++) acc[i][j] = 0ull;

    for (int k0 = 0; k0 < NC; k0 += 16) {
#pragma unroll
        for (int p = 0; p < 8; p++) {
            int i = p * 256 + tid;
            int kk = i & 15, mm = i >> 4;
            As[kk * 132 + mm] = A[(size_t)(m0 + mm) * NC + k0 + kk];
            Bs[kk * 132 + mm] = B[(size_t)(n0 + mm) * NC + k0 + kk];
        }
        __syncthreads();
#pragma unroll
        for (int k = 0; k < 16; k++) {
            float4 x0 = *(const float4*)&As[k * 132 + ty * 8];
            float4 x1 = *(const float4*)&As[k * 132 + ty * 8 + 4];
            ulonglong2 q0 = *(const ulonglong2*)&Bs[k * 132 + tx * 8];
            ulonglong2 q1 = *(const ulonglong2*)&Bs[k * 132 + tx * 8 + 4];
            float av[8] = {x0.x, x0.y, x0.z, x0.w, x1.x, x1.y, x1.z, x1.w};
            unsigned long long pb[4] = {q0.x, q0.y, q1.x, q1.y};
#pragma unroll
            for (int i = 0; i < 8; i++) {
                unsigned long long pa = pk2(av[i], av[i]);
#pragma unroll
                for (int j = 0; j < 4; j++) fma2(acc[i][j], pa, pb[j]);
            }
        }
        __syncthreads();
    }
#pragma unroll
    for (int i = 0; i < 8; i++) {
        int gm = m0 + ty * 8 + i;
#pragma unroll
        for (int j = 0; j < 4; j++) {
            float lo, hi;
            up2(acc[i][j], lo, hi);
            *(__half2*)(g_fp16 + (size_t)gm * HID + n0 + tx * 8 + 2 * j) =
                __floats2half2_rn(lo, hi);
        }
    }
}

// ---------------- GRU update (per-b CTA; tid = h) ----------------
__device__ __forceinline__ float gru_one(int b, int h,
                                         const float* __restrict__ gru_b_ih,
                                         const float* __restrict__ gru_b_hh)
{
    size_t base = (size_t)b * GRU3;
    float ir = __ldg(gru_b_ih + h);
    float iz = __ldg(gru_b_ih + HID + h);
    float in = __ldg(gru_b_ih + 2 * HID + h);
#pragma unroll
    for (int p = 0; p < 11; p++) {
        ir += __ldcg(&g_gip[p][base + h]);
        iz += __ldcg(&g_gip[p][base + HID + h]);
        in += __ldcg(&g_gip[p][base + 2 * HID + h]);
    }
    float hr = __ldg(gru_b_hh + h)           + __ldcg(&g_gh[base + h]);
    float hz = __ldg(gru_b_hh + HID + h)     + __ldcg(&g_gh[base + HID + h]);
    float hn = __ldg(gru_b_hh + 2 * HID + h) + __ldcg(&g_gh[base + 2 * HID + h]);
    float rr = fsig(ir + hr);
    float zz = fsig(iz + hz);
    float nn = ftanh(in + rr * hn);
    float hold = __ldcg(&g_hidden[(size_t)b * HID + h]);
    return (1.f - zz) * nn + zz * hold;
}

// ---------------- persistent decode kernel ----------------
__global__ __launch_bounds__(256, 4) void decode_kernel(
    const float* __restrict__ feats,
    const float* __restrict__ pose,
    const float* __restrict__ pyr0,
    const float* __restrict__ pyr1,
    const float* __restrict__ pyr2,
    const int*   __restrict__ text,
    const float* __restrict__ h2h_w,    const float* __restrict__ h2h_b,
    const float* __restrict__ score_w,
    const float* __restrict__ pose_w,   const float* __restrict__ pose_b,
    const float* __restrict__ gru_w_ih, const float* __restrict__ gru_w_hh,
    const float* __restrict__ gru_b_ih, const float* __restrict__ gru_b_hh,
    const float* __restrict__ char_emb,
    const float* __restrict__ gen_w,    const float* __restrict__ gen_b,
    float* __restrict__ out)
{
    __shared__ __align__(16) float sm[4352];
    __shared__ float s_coord[4];
    __shared__ float s_ly[3][2], s_lx[3][2];
    __shared__ int   s_y0[3][2], s_y1[3][2], s_x0[3][2], s_x1[3][2];
    __shared__ int   s_vy[3][2], s_vx[3][2];

    const int tid = threadIdx.x;
    const int bid = blockIdx.x;
    const int lane = tid & 31;
    const int wid = tid >> 5;

    float* h_s   = sm;          // 256
    float* hp_s  = sm + 256;    // 256
    float* al    = sm + 512;    // 128 (energies then alphas)
    float* ctx_s = sm + 640;    // 768

    // ---- prologue ----
    if (bid < 256) g_hidden[bid * 256 + tid] = 0.f;
    {
        const float2* fsrc = (const float2*)feats;
        for (int i = bid * 256 + tid; i < NT * NB * NC / 2; i += NCTA * 256) {
            float2 v = __ldg(fsrc + i);
            g_feats16[i] = __floats2half2_rn(v.x, v.y);
        }
    }
    for (int i = bid * 256 + tid; i < HID * HID; i += NCTA * 256)
        g_h2h16[i] = __float2half(__ldg(h2h_w + i));
    for (int job = bid; job < NB * 32; job += NCTA) {
        int b = job >> 5;
        int r = job & 31;
        int t0 = (r & 3) * 32;
        int p0 = (r >> 2) * 32;
        int y = tid >> 5, x = tid & 31;
#pragma unroll
        for (int q = 0; q < 4; q++) {
            int yy = y + q * 8;
            sm[yy * 33 + x] = __ldg(pose + ((size_t)b * POSE + (p0 + yy)) * NT + (t0 + x));
        }
        __syncthreads();
#pragma unroll
        for (int q = 0; q < 4; q++) {
            int yy = y + q * 8;
            g_pose16T[((size_t)(t0 + yy) * NB + b) * POSE + (p0 + x)] =
                __float2half(sm[x * 33 + yy]);
        }
        __syncthreads();
    }
    gbar();

    for (int step = 0; step < NSTEPS; step++) {
        // ================= A: per-b CTA (256); others idle =================
        if (bid < NB) {
            int b = bid;
            // emb for this step
            int tgt = (step == 0) ? 0 : (__ldg(text + b * NSTEPS + step - 1) + 1);
            if (tid < EMB)
                g_x[(size_t)b * RNN_IN + 768 + tid] = __ldg(char_emb + (size_t)tgt * EMB + tid);

            if (step > 0) {
                // GRU for step-1 -> hidden
                float hnew = gru_one(b, tid, gru_b_ih, gru_b_hh);
                g_hidden[(size_t)b * HID + tid] = hnew;
                g_hs[((size_t)b * NSTEPS + step - 1) * HID + tid] = hnew;
                h_s[tid] = hnew;
                __syncthreads();
                // hp matvec (fp16 weights, fp32 accum), n = tid
                {
                    const uint4* w4 = (const uint4*)(g_h2h16 + (size_t)tid * HID);
                    float acc = 0.f;
#pragma unroll 8
                    for (int q = 0; q < 32; q++) {
                        uint4 u = __ldg(w4 + q);
                        const __half2* hh = (const __half2*)&u;
                        int bb = q * 8;
                        float2 f0 = __half22float2(hh[0]);
                        float2 f1 = __half22float2(hh[1]);
                        float2 f2 = __half22float2(hh[2]);
                        float2 f3 = __half22float2(hh[3]);
                        acc += f0.x * h_s[bb]     + f0.y * h_s[bb + 1]
                             + f1.x * h_s[bb + 2] + f1.y * h_s[bb + 3]
                             + f2.x * h_s[bb + 4] + f2.y * h_s[bb + 5]
                             + f3.x * h_s[bb + 6] + f3.y * h_s[bb + 7];
                    }
                    hp_s[tid] = acc + __ldg(h2h_b + tid);
                }
            } else {
                hp_s[tid] = __ldg(h2h_b + tid);
            }
            __syncthreads();

            // energy: warp wid handles t = wid*16 .. +15 ; h = lane*8..+7
            {
                float4 hpa = *(const float4*)&hp_s[lane * 8];
                float4 hpb = *(const float4*)&hp_s[lane * 8 + 4];
                __half2 hph[4] = {
                    __floats2half2_rn(hpa.x, hpa.y), __floats2half2_rn(hpa.z, hpa.w),
                    __floats2half2_rn(hpb.x, hpb.y), __floats2half2_rn(hpb.z, hpb.w)};
                float4 swa = __ldg((const float4*)(score_w + lane * 8));
                float4 swb = __ldg((const float4*)(score_w + lane * 8 + 4));
                float swf[8] = {swa.x, swa.y, swa.z, swa.w, swb.x, swb.y, swb.z, swb.w};
#pragma unroll
                for (int i = 0; i < 16; i++) {
                    int t = wid * 16 + i;
                    uint4 fv = __ldg((const uint4*)(g_fp16 + ((size_t)t * NB + b) * HID + lane * 8));
                    __half2 v0 = *(__half2*)&fv.x, v1 = *(__half2*)&fv.y;
                    __half2 v2 = *(__half2*)&fv.z, v3 = *(__half2*)&fv.w;
                    float2 t0 = __half22float2(htanh2(__hadd2(v0, hph[0])));
                    float2 t1 = __half22float2(htanh2(__hadd2(v1, hph[1])));
                    float2 t2 = __half22float2(htanh2(__hadd2(v2, hph[2])));
                    float2 t3 = __half22float2(htanh2(__hadd2(v3, hph[3])));
                    float s = t0.x * swf[0] + t0.y * swf[1] + t1.x * swf[2] + t1.y * swf[3]
                            + t2.x * swf[4] + t2.y * swf[5] + t3.x * swf[6] + t3.y * swf[7];
#pragma unroll
                    for (int o = 16; o; o >>= 1) s += __shfl_xor_sync(~0u, s, o);
                    if (!lane) al[t] = s;
                }
            }
            __syncthreads();
            // softmax (warp 0)
            if (wid == 0) {
                float ev[4];
#pragma unroll
                for (int q = 0; q < 4; q++) ev[q] = al[lane + 32 * q];
                float mx = fmaxf(fmaxf(ev[0], ev[1]), fmaxf(ev[2], ev[3]));
#pragma unroll
                for (int o = 16; o; o >>= 1) mx = fmaxf(mx, __shfl_xor_sync(~0u, mx, o));
                float ex[4], ssum = 0.f;
#pragma unroll
                for (int q = 0; q < 4; q++) { ex[q] = __expf(ev[q] - mx); ssum += ex[q]; }
#pragma unroll
                for (int o = 16; o; o >>= 1) ssum += __shfl_xor_sync(~0u, ssum, o);
                float inv = __fdividef(1.f, ssum);
#pragma unroll
                for (int q = 0; q < 4; q++) al[lane + 32 * q] = ex[q] * inv;
            }
            __syncthreads();
            // ctx
            {
                const __half2* f2 = g_feats16 + (size_t)b * (NC / 2) + tid;
                float2 acc = {0.f, 0.f};
#pragma unroll 16
                for (int t = 0; t < NT; t++) {
                    float2 vf = __half22float2(__ldg(f2 + (size_t)t * NB * (NC / 2)));
                    float a = al[t];
                    acc.x = fmaf(a, vf.x, acc.x);
                    acc.y = fmaf(a, vf.y, acc.y);
                }
                ctx_s[2 * tid] = acc.x;
                ctx_s[2 * tid + 1] = acc.y;
                *(float2*)(g_x + (size_t)b * RNN_IN + 2 * tid) = acc;
            }
            {
                const __half* pp = g_pose16T + (size_t)b * POSE + tid;
                float acc = 0.f;
#pragma unroll 16
                for (int t = 0; t < NT; t++)
                    acc = fmaf(al[t], __half2float(__ldg(pp + (size_t)t * NB * POSE)), acc);
                ctx_s[NC + tid] = acc;
                g_x[(size_t)b * RNN_IN + NC + tid] = acc;
            }
            __syncthreads();
            // coord
            if (wid < 4) {
                const float* pw = pose_w + wid * 768;
                float s = 0.f;
#pragma unroll
                for (int q = 0; q < 24; q++) { int c = lane + q * 32; s += ctx_s[c] * __ldg(pw + c); }
#pragma unroll
                for (int o = 16; o; o >>= 1) s += __shfl_xor_sync(~0u, s, o);
                if (!lane) s_coord[wid] = fsig(s + __ldg(pose_b + wid));
            }
            __syncthreads();
            if (tid == 0) {
                const int Hs[3] = {16, 8, 4};
                const int Ws[3] = {128, 64, 65};
                float c0 = s_coord[0], c1 = s_coord[1], c2 = s_coord[2], c3 = s_coord[3];
                for (int p = 0; p < 3; p++) {
                    float Hf = (float)Hs[p], Wf = (float)Ws[p];
                    c0 *= Hf; c1 *= Wf; c2 *= Hf; c3 *= Wf;
                    float x1 = c0, y1 = c1, x2 = c2, y2 = c3;
                    float bw = fmaxf(x2 - x1, 1.f) * 0.5f;
                    float bh = fmaxf(y2 - y1, 1.f) * 0.5f;
#pragma unroll
                    for (int i = 0; i < 2; i++) {
                        float ys = y1 + (0.5f + (float)i) * bh;
                        s_vy[p][i] = (ys >= -1.f && ys <= Hf) ? 1 : 0;
                        float y = fminf(fmaxf(ys, 0.f), Hf - 1.f);
                        float y0f = floorf(y);
                        int y0i = (int)y0f;
                        s_y0[p][i] = y0i;
                        s_y1[p][i] = min(y0i + 1, Hs[p] - 1);
                        s_ly[p][i] = y - y0f;
                        float xs = x1 + (0.5f + (float)i) * bw;
                        s_vx[p][i] = (xs >= -1.f && xs <= Wf) ? 1 : 0;
                        float x = fminf(fmaxf(xs, 0.f), Wf - 1.f);
                        float x0f = floorf(x);
                        int x0i = (int)x0f;
                        s_x0[p][i] = x0i;
                        s_x1[p][i] = min(x0i + 1, Ws[p] - 1);
                        s_lx[p][i] = x - x0f;
                    }
                }
            }
            __syncthreads();
            for (int o = tid; o < 576; o += 256) {
                int p, local;
                if (o < 64)       { p = 0; local = o; }
                else if (o < 320) { p = 1; local = o - 64; }
                else              { p = 2; local = o - 320; }
                int c = local >> 2;
                int ij = local & 3;
                int i = ij >> 1, j = ij & 1;
                float val = 0.f;
                if (s_vy[p][i] && s_vx[p][j]) {
                    float ly = s_ly[p][i], lx = s_lx[p][j];
                    float hy = 1.f - ly, hx = 1.f - lx;
                    int y0 = s_y0[p][i], y1 = s_y1[p][i];
                    int x0 = s_x0[p][j], x1 = s_x1[p][j];
                    const float* f; int W, HW;
                    if (p == 0)      { f = pyr0; W = 128; HW = 16 * 128; }
                    else if (p == 1) { f = pyr1; W = 64;  HW = 8 * 64;  }
                    else             { f = pyr2; W = 65;  HW = 4 * 65;  }
                    const float* fc = f + (size_t)c * HW;
                    val = fc[y0 * W + x0] * (hy * hx)
                        + fc[y0 * W + x1] * (hy * lx)
                        + fc[y1 * W + x0] * (ly * hx)
                        + fc[y1 * W + x1] * (ly * lx);
                }
                g_x[(size_t)b * RNN_IN + 896 + o] = val;
            }
        }
        gbar();

        // ================= B: GEMMs (576 jobs) =================
        if (bid < 336) {
            int ks = bid / 48, j = bid % 48;
            gemm64(g_x, RNN_IN, gru_w_ih, RNN_IN, g_gip[ks], GRU3,
                   (j / 12) * 64, (j % 12) * 64, ks * 128, 4, sm, tid);
        } else if (bid < 528) {
            int jj = bid - 336;
            int ks = jj / 48, j = jj % 48;
            int kb = (ks == 0) ? 896 : (ks == 1) ? 1056 : (ks == 2) ? 1216 : 1344;
            int ki = (ks < 2) ? 5 : 4;
            gemm64(g_x, RNN_IN, gru_w_ih, RNN_IN, g_gip[7 + ks], GRU3,
                   (j / 12) * 64, (j % 12) * 64, kb, ki, sm, tid);
        } else if (bid < 576) {
            int j = bid - 528;
            gemm64(g_hidden, HID, gru_w_hh, HID, g_gh, GRU3,
                   (j / 12) * 64, (j % 12) * 64, 0, 8, sm, tid);
        }
        gbar();
    }

    // ===== epilogue: final GRU (step 24) =====
    if (bid < NB) {
        float hnew = gru_one(bid, tid, gru_b_ih, gru_b_hh);
        g_hs[((size_t)bid * NSTEPS + NSTEPS - 1) * HID + tid] = hnew;
    }
    gbar();

    // ===== final classifier =====
    {
        int gw = bid * 8 + wid;
        for (int m = gw; m < NB * NSTEPS; m += NWARP) {
            const float* hrow = g_hs + (size_t)m * HID;
            float a[8];
#pragma unroll
            for (int q = 0; q < 8; q++) a[q] = __ldcg(hrow + lane + q * 32);
            for (int n = 0; n < NCLS; n++) {
                const float* w = gen_w + (size_t)n * HID;
                float s = 0.f;
#pragma unroll
                for (int q = 0; q < 8; q++) s += a[q] * __ldg(w + lane + q * 32);
#pragma unroll
                for (int o = 16; o; o >>= 1) s += __shfl_xor_sync(~0u, s, o);
                if (!lane) out[(size_t)m * NCLS + n] = s + gen_b[n];
            }
        }
    }
}

// ---------------- driver ----------------
extern "C" void kernel_launch(void* const* d_in, const int* in_sizes, int n_in,
                              void* d_out, int out_size)
{
    const float* feats    = (const float*)d_in[0];
    const float* pose     = (const float*)d_in[1];
    const float* pyr0     = (const float*)d_in[2];
    const float* pyr1     = (const float*)d_in[3];
    const float* pyr2     = (const float*)d_in[4];
    const int*   text     = (const int*)  d_in[6];
    const float* i2h_w    = (const float*)d_in[7];
    const float* h2h_w    = (const float*)d_in[8];
    const float* h2h_b    = (const float*)d_in[9];
    const float* score_w  = (const float*)d_in[10];
    const float* pose_w   = (const float*)d_in[11];
    const float* pose_b   = (const float*)d_in[12];
    const float* gru_w_ih = (const float*)d_in[13];
    const float* gru_w_hh = (const float*)d_in[14];
    const float* gru_b_ih = (const float*)d_in[15];
    const float* gru_b_hh = (const float*)d_in[16];
    const float* char_emb = (const float*)d_in[17];
    const float* gen_w    = (const float*)d_in[18];
    const float* gen_b    = (const float*)d_in[19];
    float* out = (float*)d_out;

    dim3 g1(2, 256);
    fp_gemm<<<g1, 256>>>(feats, i2h_w);

    decode_kernel<<<NCTA, 256>>>(feats, pose, pyr0, pyr1, pyr2, text,
                                 h2h_w, h2h_b, score_w, pose_w, pose_b,
                                 gru_w_ih, gru_w_hh, gru_b_ih, gru_b_hh,
                                 char_emb, gen_w, gen_b, out);
}

// round 8
// speedup vs baseline: 2.0967x; 1.1462x over previous
#include <cuda_runtime.h>
#include <cuda_fp16.h>
#include <math.h>

#define NT 128
#define NB 256
#define NC 512
#define HID 256
#define EMB 128
#define NCLS 37
#define NSTEPS 25
#define POSE 256
#define RNN_IN 1472
#define GRU3 768
#define NCTA 592
#define NWARP (NCTA * 8)

// ---------------- scratch ----------------
__device__ __align__(16) __half g_fp16[NT * NB * HID];
__device__ __align__(16) __half2 g_feats16[NT * NB * NC / 2];
__device__ __align__(16) __half  g_pose16T[NT * NB * POSE];
__device__ __align__(16) __half g_h2h16[HID * HID];
__device__ __align__(16) __half g_i2h16[HID * NC];
__device__ float g_gh[2][NB * GRU3];
__device__ float g_x[NB * RNN_IN];
__device__ float g_gip[10][NB * GRU3];
__device__ float g_hidden[NB * HID];
__device__ float g_hs[NSTEPS * NB * HID];

// barrier state
__device__ unsigned g_cnt[17 * 32];
__device__ unsigned g_rel[16 * 32];

// ---------------- barrier primitives ----------------
__device__ __forceinline__ unsigned ld_acq(const unsigned* p) {
    unsigned v;
    asm volatile("ld.acquire.gpu.global.u32 %0,[%1];" : "=r"(v) : "l"(p) : "memory");
    return v;
}
__device__ __forceinline__ unsigned atom_inc_rel(unsigned* p) {
    unsigned v;
    asm volatile("atom.release.gpu.global.add.u32 %0,[%1],1;" : "=r"(v) : "l"(p) : "memory");
    return v;
}
__device__ __forceinline__ void st_rel(unsigned* p, unsigned v) {
    asm volatile("st.release.gpu.global.u32 [%0],%1;" :: "l"(p), "r"(v) : "memory");
}
__device__ __forceinline__ void gbar() {
    __syncthreads();
    if (threadIdx.x == 0) {
        int g = blockIdx.x / 37;
        unsigned* cnt = &g_cnt[g * 32];
        unsigned* rel = &g_rel[g * 32];
        unsigned gen = ld_acq(rel);
        if (atom_inc_rel(cnt) == 36u) {
            *(volatile unsigned*)cnt = 0u;
            if (atom_inc_rel(&g_cnt[16 * 32]) == 15u) {
                *(volatile unsigned*)&g_cnt[16 * 32] = 0u;
#pragma unroll
                for (int i = 0; i < 16; i++) st_rel(&g_rel[i * 32], gen + 1u);
            } else {
                while (ld_acq(rel) == gen) __nanosleep(32);
            }
        } else {
            while (ld_acq(rel) == gen) __nanosleep(32);
        }
    }
    __syncthreads();
}

// ---------------- f32x2 helpers ----------------
__device__ __forceinline__ unsigned long long pk2(float lo, float hi) {
    unsigned long long r;
    asm("mov.b64 %0,{%1,%2};" : "=l"(r) : "f"(lo), "f"(hi));
    return r;
}
__device__ __forceinline__ void fma2(unsigned long long& d, unsigned long long a,
                                     unsigned long long b) {
    asm("fma.rn.f32x2 %0,%1,%2,%0;" : "+l"(d) : "l"(a), "l"(b));
}
__device__ __forceinline__ void up2(unsigned long long v, float& a, float& b) {
    asm("mov.b64 {%0,%1},%2;" : "=f"(a), "=f"(b) : "l"(v));
}

// ---------------- fast transcendentals ----------------
__device__ __forceinline__ float fsig(float x) {
    return __fdividef(1.f, 1.f + __expf(-x));
}
__device__ __forceinline__ float ftanh(float x) {
    float r;
    asm("tanh.approx.f32 %0,%1;" : "=f"(r) : "f"(x));
    return r;
}
__device__ __forceinline__ __half2 htanh2(__half2 x) {
    __half2 r;
    asm("tanh.approx.f16x2 %0,%1;" : "=r"(*(unsigned*)&r) : "r"(*(unsigned*)&x));
    return r;
}

// ---------------- 64x64 tile GEMM, C = A@B^T, f32x2 ----------------
__device__ __forceinline__ void gemm64(const float* __restrict__ A, int lda,
                                       const float* __restrict__ B, int ldb,
                                       float* __restrict__ C, int ldc,
                                       int m0, int n0, int kbase, int kiters,
                                       float* sm, int tid)
{
    float* As = sm;          // [32][68]
    float* Bs = sm + 2176;   // [32][68]
    const int ty = tid >> 4, tx = tid & 15;
    unsigned long long acc[4][2] = {};
    const int row = tid >> 2;
    const int kk = (tid & 3) * 8;
    const float* Ag = A + (size_t)(m0 + row) * lda + kbase + kk;
    const float* Bg = B + (size_t)(n0 + row) * ldb + kbase + kk;
    for (int kc = 0; kc < kiters; kc++) {
        float4 a0 = __ldcg((const float4*)(Ag + kc * 32));
        float4 a1 = __ldcg((const float4*)(Ag + kc * 32 + 4));
        float4 b0 = __ldg((const float4*)(Bg + kc * 32));
        float4 b1 = __ldg((const float4*)(Bg + kc * 32 + 4));
        As[(kk + 0) * 68 + row] = a0.x; As[(kk + 1) * 68 + row] = a0.y;
        As[(kk + 2) * 68 + row] = a0.z; As[(kk + 3) * 68 + row] = a0.w;
        As[(kk + 4) * 68 + row] = a1.x; As[(kk + 5) * 68 + row] = a1.y;
        As[(kk + 6) * 68 + row] = a1.z; As[(kk + 7) * 68 + row] = a1.w;
        Bs[(kk + 0) * 68 + row] = b0.x; Bs[(kk + 1) * 68 + row] = b0.y;
        Bs[(kk + 2) * 68 + row] = b0.z; Bs[(kk + 3) * 68 + row] = b0.w;
        Bs[(kk + 4) * 68 + row] = b1.x; Bs[(kk + 5) * 68 + row] = b1.y;
        Bs[(kk + 6) * 68 + row] = b1.z; Bs[(kk + 7) * 68 + row] = b1.w;
        __syncthreads();
#pragma unroll
        for (int k = 0; k < 32; k++) {
            float4 a = *(const float4*)&As[k * 68 + ty * 4];
            ulonglong2 pb = *(const ulonglong2*)&Bs[k * 68 + tx * 4];
            float av[4] = {a.x, a.y, a.z, a.w};
#pragma unroll
            for (int i = 0; i < 4; i++) {
                unsigned long long pa = pk2(av[i], av[i]);
                fma2(acc[i][0], pa, pb.x);
                fma2(acc[i][1], pa, pb.y);
            }
        }
        __syncthreads();
    }
#pragma unroll
    for (int i = 0; i < 4; i++) {
        int gm = m0 + ty * 4 + i;
        float v0, v1, v2, v3;
        up2(acc[i][0], v0, v1);
        up2(acc[i][1], v2, v3);
        float4 v = {v0, v1, v2, v3};
        *(float4*)(C + (size_t)gm * ldc + n0 + tx * 4) = v;
    }
}

// ---------------- convert inputs to fp16 ----------------
__global__ __launch_bounds__(256) void convert_kernel(const float* __restrict__ feats,
                                                      const float* __restrict__ i2h_w,
                                                      const float* __restrict__ h2h_w)
{
    int i = blockIdx.x * 256 + threadIdx.x;
    int stride = gridDim.x * 256;
    const float2* fs = (const float2*)feats;
    for (int j = i; j < NT * NB * NC / 2; j += stride) {
        float2 v = __ldg(fs + j);
        g_feats16[j] = __floats2half2_rn(v.x, v.y);
    }
    for (int j = i; j < HID * NC; j += stride)
        g_i2h16[j] = __float2half(__ldg(i2h_w + j));
    for (int j = i; j < HID * HID; j += stride)
        g_h2h16[j] = __float2half(__ldg(h2h_w + j));
}

// ---------------- feats_proj via HMMA (mma.sync m16n8k16) ----------------
// g_fp16[32768, 256] = feats16[32768, 512] @ i2h16[256, 512]^T
__global__ __launch_bounds__(256) void fp_gemm_hmma()
{
    const int tid = threadIdx.x;
    const int wid = tid >> 5, lane = tid & 31;
    const int g = lane >> 2, ig2 = (lane & 3) * 2;
    const int warp_m = wid >> 1, warp_n = wid & 1;
    const int mbase = blockIdx.y * 128 + warp_m * 32;
    const int nbase = blockIdx.x * 128 + warp_n * 64;
    const __half* A = (const __half*)g_feats16;

    float d[2][8][4] = {};
    for (int k0 = 0; k0 < NC; k0 += 16) {
        unsigned a[2][4], b[8][2];
#pragma unroll
        for (int mi = 0; mi < 2; mi++) {
            const __half* ap = A + (size_t)(mbase + mi * 16 + g) * NC + k0 + ig2;
            a[mi][0] = *(const unsigned*)ap;
            a[mi][1] = *(const unsigned*)(ap + 8 * NC);
            a[mi][2] = *(const unsigned*)(ap + 8);
            a[mi][3] = *(const unsigned*)(ap + 8 * NC + 8);
        }
#pragma unroll
        for (int nj = 0; nj < 8; nj++) {
            const __half* bp = g_i2h16 + (size_t)(nbase + nj * 8 + g) * NC + k0 + ig2;
            b[nj][0] = *(const unsigned*)bp;
            b[nj][1] = *(const unsigned*)(bp + 8);
        }
#pragma unroll
        for (int mi = 0; mi < 2; mi++)
#pragma unroll
            for (int nj = 0; nj < 8; nj++)
                asm volatile(
                    "mma.sync.aligned.m16n8k16.row.col.f32.f16.f16.f32 "
                    "{%0,%1,%2,%3},{%4,%5,%6,%7},{%8,%9},{%0,%1,%2,%3};"
                    : "+f"(d[mi][nj][0]), "+f"(d[mi][nj][1]),
                      "+f"(d[mi][nj][2]), "+f"(d[mi][nj][3])
                    : "r"(a[mi][0]), "r"(a[mi][1]), "r"(a[mi][2]), "r"(a[mi][3]),
                      "r"(b[nj][0]), "r"(b[nj][1]));
    }
#pragma unroll
    for (int mi = 0; mi < 2; mi++) {
        int r = mbase + mi * 16 + g;
#pragma unroll
        for (int nj = 0; nj < 8; nj++) {
            int c = nbase + nj * 8 + ig2;
            *(__half2*)(g_fp16 + (size_t)r * HID + c) =
                __floats2half2_rn(d[mi][nj][0], d[mi][nj][1]);
            *(__half2*)(g_fp16 + (size_t)(r + 8) * HID + c) =
                __floats2half2_rn(d[mi][nj][2], d[mi][nj][3]);
        }
    }
}

// ---------------- GRU update (per-b CTA; tid = h) ----------------
__device__ __forceinline__ float gru_one(int b, int h,
                                         const float* __restrict__ gru_b_ih,
                                         const float* __restrict__ gru_b_hh)
{
    size_t base = (size_t)b * GRU3;
    float ir = __ldg(gru_b_ih + h);
    float iz = __ldg(gru_b_ih + HID + h);
    float in = __ldg(gru_b_ih + 2 * HID + h);
#pragma unroll
    for (int p = 0; p < 10; p++) {
        ir += __ldcg(&g_gip[p][base + h]);
        iz += __ldcg(&g_gip[p][base + HID + h]);
        in += __ldcg(&g_gip[p][base + 2 * HID + h]);
    }
    float hr = __ldg(gru_b_hh + h)           + __ldcg(&g_gh[0][base + h])           + __ldcg(&g_gh[1][base + h]);
    float hz = __ldg(gru_b_hh + HID + h)     + __ldcg(&g_gh[0][base + HID + h])     + __ldcg(&g_gh[1][base + HID + h]);
    float hn = __ldg(gru_b_hh + 2 * HID + h) + __ldcg(&g_gh[0][base + 2 * HID + h]) + __ldcg(&g_gh[1][base + 2 * HID + h]);
    float rr = fsig(ir + hr);
    float zz = fsig(iz + hz);
    float nn = ftanh(in + rr * hn);
    float hold = __ldcg(&g_hidden[(size_t)b * HID + h]);
    return (1.f - zz) * nn + zz * hold;
}

// ---------------- persistent decode kernel ----------------
__global__ __launch_bounds__(256, 4) void decode_kernel(
    const float* __restrict__ pose,
    const float* __restrict__ pyr0,
    const float* __restrict__ pyr1,
    const float* __restrict__ pyr2,
    const int*   __restrict__ text,
    const float* __restrict__ h2h_b,
    const float* __restrict__ score_w,
    const float* __restrict__ pose_w,   const float* __restrict__ pose_b,
    const float* __restrict__ gru_w_ih, const float* __restrict__ gru_w_hh,
    const float* __restrict__ gru_b_ih, const float* __restrict__ gru_b_hh,
    const float* __restrict__ char_emb,
    const float* __restrict__ gen_w,    const float* __restrict__ gen_b,
    float* __restrict__ out)
{
    __shared__ __align__(16) float sm[4352];
    __shared__ float s_coord[4];
    __shared__ float s_ly[3][2], s_lx[3][2];
    __shared__ int   s_y0[3][2], s_y1[3][2], s_x0[3][2], s_x1[3][2];
    __shared__ int   s_vy[3][2], s_vx[3][2];

    const int tid = threadIdx.x;
    const int bid = blockIdx.x;
    const int lane = tid & 31;
    const int wid = tid >> 5;

    float* h_s   = sm;          // 256
    float* hp_s  = sm + 256;    // 256
    float* al    = sm + 512;    // 128
    float* ctx_s = sm + 640;    // 768
    float* red   = sm + 1408;   // 2048

    // ---- prologue: hidden init, pose transpose ----
    if (bid < 256) g_hidden[bid * 256 + tid] = 0.f;
    for (int job = bid; job < NB * 32; job += NCTA) {
        int b = job >> 5;
        int r = job & 31;
        int t0 = (r & 3) * 32;
        int p0 = (r >> 2) * 32;
        int y = tid >> 5, x = tid & 31;
#pragma unroll
        for (int q = 0; q < 4; q++) {
            int yy = y + q * 8;
            sm[yy * 33 + x] = __ldg(pose + ((size_t)b * POSE + (p0 + yy)) * NT + (t0 + x));
        }
        __syncthreads();
#pragma unroll
        for (int q = 0; q < 4; q++) {
            int yy = y + q * 8;
            g_pose16T[((size_t)(t0 + yy) * NB + b) * POSE + (p0 + x)] =
                __float2half(sm[x * 33 + yy]);
        }
        __syncthreads();
    }
    gbar();

    for (int step = 0; step < NSTEPS; step++) {
        // ================= A: per-b CTA (256) =================
        if (bid < NB) {
            int b = bid;
            int tgt = (step == 0) ? 0 : (__ldg(text + b * NSTEPS + step - 1) + 1);
            if (tid < EMB)
                g_x[(size_t)b * RNN_IN + 768 + tid] = __ldg(char_emb + (size_t)tgt * EMB + tid);

            if (step > 0) {
                float hnew = gru_one(b, tid, gru_b_ih, gru_b_hh);
                g_hidden[(size_t)b * HID + tid] = hnew;
                g_hs[((size_t)b * NSTEPS + step - 1) * HID + tid] = hnew;
                h_s[tid] = hnew;
                __syncthreads();
                // hp matvec (fp16 weights)
                const uint4* w4 = (const uint4*)(g_h2h16 + (size_t)tid * HID);
                float acc = 0.f;
#pragma unroll 8
                for (int q = 0; q < 32; q++) {
                    uint4 u = __ldg(w4 + q);
                    const __half2* hh = (const __half2*)&u;
                    int bb = q * 8;
                    float2 f0 = __half22float2(hh[0]);
                    float2 f1 = __half22float2(hh[1]);
                    float2 f2 = __half22float2(hh[2]);
                    float2 f3 = __half22float2(hh[3]);
                    acc += f0.x * h_s[bb]     + f0.y * h_s[bb + 1]
                         + f1.x * h_s[bb + 2] + f1.y * h_s[bb + 3]
                         + f2.x * h_s[bb + 4] + f2.y * h_s[bb + 5]
                         + f3.x * h_s[bb + 6] + f3.y * h_s[bb + 7];
                }
                hp_s[tid] = acc + __ldg(h2h_b + tid);
            } else {
                hp_s[tid] = __ldg(h2h_b + tid);
            }
            __syncthreads();

            // energy: warp wid -> t = wid*16..+15 ; h = lane*8..+7
            {
                float4 hpa = *(const float4*)&hp_s[lane * 8];
                float4 hpb = *(const float4*)&hp_s[lane * 8 + 4];
                __half2 hph[4] = {
                    __floats2half2_rn(hpa.x, hpa.y), __floats2half2_rn(hpa.z, hpa.w),
                    __floats2half2_rn(hpb.x, hpb.y), __floats2half2_rn(hpb.z, hpb.w)};
                float4 swa = __ldg((const float4*)(score_w + lane * 8));
                float4 swb = __ldg((const float4*)(score_w + lane * 8 + 4));
                float swf[8] = {swa.x, swa.y, swa.z, swa.w, swb.x, swb.y, swb.z, swb.w};
#pragma unroll
                for (int i = 0; i < 16; i++) {
                    int t = wid * 16 + i;
                    uint4 fv = __ldg((const uint4*)(g_fp16 + ((size_t)t * NB + b) * HID + lane * 8));
                    __half2 v0 = *(__half2*)&fv.x, v1 = *(__half2*)&fv.y;
                    __half2 v2 = *(__half2*)&fv.z, v3 = *(__half2*)&fv.w;
                    float2 t0 = __half22float2(htanh2(__hadd2(v0, hph[0])));
                    float2 t1 = __half22float2(htanh2(__hadd2(v1, hph[1])));
                    float2 t2 = __half22float2(htanh2(__hadd2(v2, hph[2])));
                    float2 t3 = __half22float2(htanh2(__hadd2(v3, hph[3])));
                    float s = t0.x * swf[0] + t0.y * swf[1] + t1.x * swf[2] + t1.y * swf[3]
                            + t2.x * swf[4] + t2.y * swf[5] + t3.x * swf[6] + t3.y * swf[7];
#pragma unroll
                    for (int o = 16; o; o >>= 1) s += __shfl_xor_sync(~0u, s, o);
                    if (!lane) al[t] = s;
                }
            }
            __syncthreads();
            // softmax (warp 0)
            if (wid == 0) {
                float ev[4];
#pragma unroll
                for (int q = 0; q < 4; q++) ev[q] = al[lane + 32 * q];
                float mx = fmaxf(fmaxf(ev[0], ev[1]), fmaxf(ev[2], ev[3]));
#pragma unroll
                for (int o = 16; o; o >>= 1) mx = fmaxf(mx, __shfl_xor_sync(~0u, mx, o));
                float ex[4], ssum = 0.f;
#pragma unroll
                for (int q = 0; q < 4; q++) { ex[q] = __expf(ev[q] - mx); ssum += ex[q]; }
#pragma unroll
                for (int o = 16; o; o >>= 1) ssum += __shfl_xor_sync(~0u, ssum, o);
                float inv = __fdividef(1.f, ssum);
#pragma unroll
                for (int q = 0; q < 4; q++) al[lane + 32 * q] = ex[q] * inv;
            }
            __syncthreads();
            // ctx feats: tq = t-quarter, cg = 8-channel group, uint4 loads
            {
                int tq = tid >> 6, cg = tid & 63;
                float acc[8] = {};
                int t0 = tq * 32;
#pragma unroll 8
                for (int i = 0; i < 32; i++) {
                    int t = t0 + i;
                    uint4 u = __ldg((const uint4*)(g_feats16 + ((size_t)t * NB + b) * (NC / 2)) + cg);
                    float a = al[t];
                    const __half2* h2 = (const __half2*)&u;
#pragma unroll
                    for (int q = 0; q < 4; q++) {
                        float2 f = __half22float2(h2[q]);
                        acc[2 * q]     = fmaf(a, f.x, acc[2 * q]);
                        acc[2 * q + 1] = fmaf(a, f.y, acc[2 * q + 1]);
                    }
                }
#pragma unroll
                for (int q = 0; q < 8; q++) red[tq * 512 + cg * 8 + q] = acc[q];
            }
            __syncthreads();
            {
                int c = tid * 2;
                float s0 = red[c] + red[512 + c] + red[1024 + c] + red[1536 + c];
                float s1 = red[c + 1] + red[512 + c + 1] + red[1024 + c + 1] + red[1536 + c + 1];
                ctx_s[c] = s0; ctx_s[c + 1] = s1;
                float2 v = {s0, s1};
                *(float2*)(g_x + (size_t)b * RNN_IN + c) = v;
            }
            __syncthreads();
            // ctx pose: tq2 = t-eighth, cg2 = 8-channel group
            {
                int tq2 = tid >> 5, cg2 = tid & 31;
                float acc[8] = {};
                int t0 = tq2 * 16;
#pragma unroll 8
                for (int i = 0; i < 16; i++) {
                    int t = t0 + i;
                    uint4 u = __ldg((const uint4*)(g_pose16T + ((size_t)t * NB + b) * POSE) + cg2);
                    float a = al[t];
                    const __half2* h2 = (const __half2*)&u;
#pragma unroll
                    for (int q = 0; q < 4; q++) {
                        float2 f = __half22float2(h2[q]);
                        acc[2 * q]     = fmaf(a, f.x, acc[2 * q]);
                        acc[2 * q + 1] = fmaf(a, f.y, acc[2 * q + 1]);
                    }
                }
#pragma unroll
                for (int q = 0; q < 8; q++) red[tq2 * 256 + cg2 * 8 + q] = acc[q];
            }
            __syncthreads();
            {
                int c = tid;
                float s = 0.f;
#pragma unroll
                for (int q = 0; q < 8; q++) s += red[q * 256 + c];
                ctx_s[NC + c] = s;
                g_x[(size_t)b * RNN_IN + NC + c] = s;
            }
            __syncthreads();
            // coord
            if (wid < 4) {
                const float* pw = pose_w + wid * 768;
                float s = 0.f;
#pragma unroll
                for (int q = 0; q < 24; q++) { int c = lane + q * 32; s += ctx_s[c] * __ldg(pw + c); }
#pragma unroll
                for (int o = 16; o; o >>= 1) s += __shfl_xor_sync(~0u, s, o);
                if (!lane) s_coord[wid] = fsig(s + __ldg(pose_b + wid));
            }
            __syncthreads();
            if (tid == 0) {
                const int Hs[3] = {16, 8, 4};
                const int Ws[3] = {128, 64, 65};
                float c0 = s_coord[0], c1 = s_coord[1], c2 = s_coord[2], c3 = s_coord[3];
                for (int p = 0; p < 3; p++) {
                    float Hf = (float)Hs[p], Wf = (float)Ws[p];
                    c0 *= Hf; c1 *= Wf; c2 *= Hf; c3 *= Wf;
                    float x1 = c0, y1 = c1, x2 = c2, y2 = c3;
                    float bw = fmaxf(x2 - x1, 1.f) * 0.5f;
                    float bh = fmaxf(y2 - y1, 1.f) * 0.5f;
#pragma unroll
                    for (int i = 0; i < 2; i++) {
                        float ys = y1 + (0.5f + (float)i) * bh;
                        s_vy[p][i] = (ys >= -1.f && ys <= Hf) ? 1 : 0;
                        float y = fminf(fmaxf(ys, 0.f), Hf - 1.f);
                        float y0f = floorf(y);
                        int y0i = (int)y0f;
                        s_y0[p][i] = y0i;
                        s_y1[p][i] = min(y0i + 1, Hs[p] - 1);
                        s_ly[p][i] = y - y0f;
                        float xs = x1 + (0.5f + (float)i) * bw;
                        s_vx[p][i] = (xs >= -1.f && xs <= Wf) ? 1 : 0;
                        float x = fminf(fmaxf(xs, 0.f), Wf - 1.f);
                        float x0f = floorf(x);
                        int x0i = (int)x0f;
                        s_x0[p][i] = x0i;
                        s_x1[p][i] = min(x0i + 1, Ws[p] - 1);
                        s_lx[p][i] = x - x0f;
                    }
                }
            }
            __syncthreads();
            for (int o = tid; o < 576; o += 256) {
                int p, local;
                if (o < 64)       { p = 0; local = o; }
                else if (o < 320) { p = 1; local = o - 64; }
                else              { p = 2; local = o - 320; }
                int c = local >> 2;
                int ij = local & 3;
                int i = ij >> 1, j = ij & 1;
                float val = 0.f;
                if (s_vy[p][i] && s_vx[p][j]) {
                    float ly = s_ly[p][i], lx = s_lx[p][j];
                    float hy = 1.f - ly, hx = 1.f - lx;
                    int y0 = s_y0[p][i], y1 = s_y1[p][i];
                    int x0 = s_x0[p][j], x1 = s_x1[p][j];
                    const float* f; int W, HW;
                    if (p == 0)      { f = pyr0; W = 128; HW = 16 * 128; }
                    else if (p == 1) { f = pyr1; W = 64;  HW = 8 * 64;  }
                    else             { f = pyr2; W = 65;  HW = 4 * 65;  }
                    const float* fc = f + (size_t)c * HW;
                    val = fc[y0 * W + x0] * (hy * hx)
                        + fc[y0 * W + x1] * (hy * lx)
                        + fc[y1 * W + x0] * (ly * hx)
                        + fc[y1 * W + x1] * (ly * lx);
                }
                g_x[(size_t)b * RNN_IN + 896 + o] = val;
            }
        }
        gbar();

        // ================= B: GEMMs (576 jobs, max kiters 5) =================
        if (bid < 480) {
            const int kb[10] = {0, 160, 320, 480, 640, 768, 896, 1056, 1216, 1344};
            const int ki[10] = {5, 5, 5, 5, 4, 4, 5, 5, 4, 4};
            int ks = bid / 48, j = bid % 48;
            gemm64(g_x, RNN_IN, gru_w_ih, RNN_IN, g_gip[ks], GRU3,
                   (j / 12) * 64, (j % 12) * 64, kb[ks], ki[ks], sm, tid);
        } else if (bid < 576) {
            int jj = bid - 480;
            int ks = jj / 48, j = jj % 48;
            gemm64(g_hidden, HID, gru_w_hh, HID, g_gh[ks], GRU3,
                   (j / 12) * 64, (j % 12) * 64, ks * 128, 4, sm, tid);
        }
        gbar();
    }

    // ===== epilogue: final GRU (step 24) =====
    if (bid < NB) {
        float hnew = gru_one(bid, tid, gru_b_ih, gru_b_hh);
        g_hs[((size_t)bid * NSTEPS + NSTEPS - 1) * HID + tid] = hnew;
    }
    gbar();

    // ===== final classifier =====
    {
        int gw = bid * 8 + wid;
        for (int m = gw; m < NB * NSTEPS; m += NWARP) {
            const float* hrow = g_hs + (size_t)m * HID;
            float a[8];
#pragma unroll
            for (int q = 0; q < 8; q++) a[q] = __ldcg(hrow + lane + q * 32);
            for (int n = 0; n < NCLS; n++) {
                const float* w = gen_w + (size_t)n * HID;
                float s = 0.f;
#pragma unroll
                for (int q = 0; q < 8; q++) s += a[q] * __ldg(w + lane + q * 32);
#pragma unroll
                for (int o = 16; o; o >>= 1) s += __shfl_xor_sync(~0u, s, o);
                if (!lane) out[(size_t)m * NCLS + n] = s + gen_b[n];
            }
        }
    }
}

// ---------------- driver ----------------
extern "C" void kernel_launch(void* const* d_in, const int* in_sizes, int n_in,
                              void* d_out, int out_size)
{
    const float* feats    = (const float*)d_in[0];
    const float* pose     = (const float*)d_in[1];
    const float* pyr0     = (const float*)d_in[2];
    const float* pyr1     = (const float*)d_in[3];
    const float* pyr2     = (const float*)d_in[4];
    const int*   text     = (const int*)  d_in[6];
    const float* i2h_w    = (const float*)d_in[7];
    const float* h2h_w    = (const float*)d_in[8];
    const float* h2h_b    = (const float*)d_in[9];
    const float* score_w  = (const float*)d_in[10];
    const float* pose_w   = (const float*)d_in[11];
    const float* pose_b   = (const float*)d_in[12];
    const float* gru_w_ih = (const float*)d_in[13];
    const float* gru_w_hh = (const float*)d_in[14];
    const float* gru_b_ih = (const float*)d_in[15];
    const float* gru_b_hh = (const float*)d_in[16];
    const float* char_emb = (const float*)d_in[17];
    const float* gen_w    = (const float*)d_in[18];
    const float* gen_b    = (const float*)d_in[19];
    float* out = (float*)d_out;

    convert_kernel<<<1024, 256>>>(feats, i2h_w, h2h_w);

    dim3 g1(2, 256);
    fp_gemm_hmma<<<g1, 256>>>();

    decode_kernel<<<NCTA, 256>>>(pose, pyr0, pyr1, pyr2, text,
                                 h2h_b, score_w, pose_w, pose_b,
                                 gru_w_ih, gru_w_hh, gru_b_ih, gru_b_hh,
                                 char_emb, gen_w, gen_b, out);
}

// round 9
// speedup vs baseline: 2.4521x; 1.1695x over previous
#include <cuda_runtime.h>
#include <cuda_fp16.h>
#include <math.h>

#define NT 128
#define NB 256
#define NC 512
#define HID 256
#define EMB 128
#define NCLS 37
#define NSTEPS 25
#define POSE 256
#define RNN_IN 1472
#define GRU3 768
#define NCTA 592
#define NWARP (NCTA * 8)

// ---------------- scratch ----------------
__device__ __align__(16) __half g_fp16[NT * NB * HID];
__device__ __align__(16) __half2 g_feats16[NT * NB * NC / 2];
__device__ __align__(16) __half  g_pose16T[NT * NB * POSE];
__device__ __align__(16) __half g_h2h16[HID * HID];
__device__ __align__(16) __half g_i2h16[HID * NC];
__device__ __align__(16) __half g_wih16[GRU3 * RNN_IN];
__device__ __align__(16) __half g_whh16[GRU3 * HID];
__device__ __align__(16) __half g_x16[NB * RNN_IN];
__device__ __align__(16) __half g_hidden16[NB * HID];
__device__ float g_gh[2][NB * GRU3];
__device__ float g_gip[10][NB * GRU3];
__device__ float g_hidden[NB * HID];
__device__ float g_hs[NSTEPS * NB * HID];

// barrier state
__device__ unsigned g_cnt[17 * 32];
__device__ unsigned g_rel[16 * 32];

// ---------------- barrier primitives ----------------
__device__ __forceinline__ unsigned ld_acq(const unsigned* p) {
    unsigned v;
    asm volatile("ld.acquire.gpu.global.u32 %0,[%1];" : "=r"(v) : "l"(p) : "memory");
    return v;
}
__device__ __forceinline__ unsigned atom_inc_rel(unsigned* p) {
    unsigned v;
    asm volatile("atom.release.gpu.global.add.u32 %0,[%1],1;" : "=r"(v) : "l"(p) : "memory");
    return v;
}
__device__ __forceinline__ void st_rel(unsigned* p, unsigned v) {
    asm volatile("st.release.gpu.global.u32 [%0],%1;" :: "l"(p), "r"(v) : "memory");
}
__device__ __forceinline__ void gbar() {
    __syncthreads();
    if (threadIdx.x == 0) {
        int g = blockIdx.x / 37;
        unsigned* cnt = &g_cnt[g * 32];
        unsigned* rel = &g_rel[g * 32];
        unsigned gen = ld_acq(rel);
        if (atom_inc_rel(cnt) == 36u) {
            *(volatile unsigned*)cnt = 0u;
            if (atom_inc_rel(&g_cnt[16 * 32]) == 15u) {
                *(volatile unsigned*)&g_cnt[16 * 32] = 0u;
#pragma unroll
                for (int i = 0; i < 16; i++) st_rel(&g_rel[i * 32], gen + 1u);
            } else {
                while (ld_acq(rel) == gen) __nanosleep(32);
            }
        } else {
            while (ld_acq(rel) == gen) __nanosleep(32);
        }
    }
    __syncthreads();
}

// ---------------- f32x2 helpers (fp_gemm fallback removed) ----------------
__device__ __forceinline__ float fsig(float x) {
    return __fdividef(1.f, 1.f + __expf(-x));
}
__device__ __forceinline__ float ftanh(float x) {
    float r;
    asm("tanh.approx.f32 %0,%1;" : "=f"(r) : "f"(x));
    return r;
}
__device__ __forceinline__ __half2 htanh2(__half2 x) {
    __half2 r;
    asm("tanh.approx.f16x2 %0,%1;" : "=r"(*(unsigned*)&r) : "r"(*(unsigned*)&x));
    return r;
}

// ---------------- HMMA 64x64 tile: C(f32) = A(f16)@B(f16)^T ----------------
// 8 warps: warp_m = wid>>2 (2 x m32), warp_n = wid&3 (4 x n16).
// A rows are mutable per-step data -> ld.cg ; B rows are weights -> ld (L1).
__device__ __forceinline__ void gemm64h(const __half* __restrict__ A, int lda,
                                        const __half* __restrict__ B, int ldb,
                                        float* __restrict__ C, int ldc,
                                        int m0, int n0, int kbase, int ksteps,
                                        int tid)
{
    const int wid = tid >> 5, lane = tid & 31;
    const int g = lane >> 2, ig2 = (lane & 3) * 2;
    const int mb = m0 + (wid >> 2) * 32;
    const int nb = n0 + (wid & 3) * 16;
    float d[2][2][4] = {};
    for (int ks = 0; ks < ksteps; ks++) {
        int k0 = kbase + ks * 16;
        unsigned a[2][4], bf[2][2];
#pragma unroll
        for (int mi = 0; mi < 2; mi++) {
            const __half* ap = A + (size_t)(mb + mi * 16 + g) * lda + k0 + ig2;
            a[mi][0] = __ldcg((const unsigned*)ap);
            a[mi][1] = __ldcg((const unsigned*)(ap + 8 * lda));
            a[mi][2] = __ldcg((const unsigned*)(ap + 8));
            a[mi][3] = __ldcg((const unsigned*)(ap + 8 * lda + 8));
        }
#pragma unroll
        for (int nj = 0; nj < 2; nj++) {
            const __half* bp = B + (size_t)(nb + nj * 8 + g) * ldb + k0 + ig2;
            bf[nj][0] = __ldg((const unsigned*)bp);
            bf[nj][1] = __ldg((const unsigned*)(bp + 8));
        }
#pragma unroll
        for (int mi = 0; mi < 2; mi++)
#pragma unroll
            for (int nj = 0; nj < 2; nj++)
                asm volatile(
                    "mma.sync.aligned.m16n8k16.row.col.f32.f16.f16.f32 "
                    "{%0,%1,%2,%3},{%4,%5,%6,%7},{%8,%9},{%0,%1,%2,%3};"
                    : "+f"(d[mi][nj][0]), "+f"(d[mi][nj][1]),
                      "+f"(d[mi][nj][2]), "+f"(d[mi][nj][3])
                    : "r"(a[mi][0]), "r"(a[mi][1]), "r"(a[mi][2]), "r"(a[mi][3]),
                      "r"(bf[nj][0]), "r"(bf[nj][1]));
    }
#pragma unroll
    for (int mi = 0; mi < 2; mi++) {
        int r = mb + mi * 16 + g;
#pragma unroll
        for (int nj = 0; nj < 2; nj++) {
            int c = nb + nj * 8 + ig2;
            float2 v0 = {d[mi][nj][0], d[mi][nj][1]};
            float2 v1 = {d[mi][nj][2], d[mi][nj][3]};
            *(float2*)(C + (size_t)r * ldc + c) = v0;
            *(float2*)(C + (size_t)(r + 8) * ldc + c) = v1;
        }
    }
}

// ---------------- convert inputs to fp16 ----------------
__global__ __launch_bounds__(256) void convert_kernel(const float* __restrict__ feats,
                                                      const float* __restrict__ i2h_w,
                                                      const float* __restrict__ h2h_w,
                                                      const float* __restrict__ gru_w_ih,
                                                      const float* __restrict__ gru_w_hh)
{
    int i = blockIdx.x * 256 + threadIdx.x;
    int stride = gridDim.x * 256;
    const float2* fs = (const float2*)feats;
    for (int j = i; j < NT * NB * NC / 2; j += stride) {
        float2 v = __ldg(fs + j);
        g_feats16[j] = __floats2half2_rn(v.x, v.y);
    }
    for (int j = i; j < HID * NC; j += stride)
        g_i2h16[j] = __float2half(__ldg(i2h_w + j));
    for (int j = i; j < HID * HID; j += stride)
        g_h2h16[j] = __float2half(__ldg(h2h_w + j));
    for (int j = i; j < GRU3 * RNN_IN; j += stride)
        g_wih16[j] = __float2half(__ldg(gru_w_ih + j));
    for (int j = i; j < GRU3 * HID; j += stride)
        g_whh16[j] = __float2half(__ldg(gru_w_hh + j));
}

// ---------------- feats_proj via HMMA ----------------
__global__ __launch_bounds__(256) void fp_gemm_hmma()
{
    const int tid = threadIdx.x;
    const int wid = tid >> 5, lane = tid & 31;
    const int g = lane >> 2, ig2 = (lane & 3) * 2;
    const int warp_m = wid >> 1, warp_n = wid & 1;
    const int mbase = blockIdx.y * 128 + warp_m * 32;
    const int nbase = blockIdx.x * 128 + warp_n * 64;
    const __half* A = (const __half*)g_feats16;

    float d[2][8][4] = {};
    for (int k0 = 0; k0 < NC; k0 += 16) {
        unsigned a[2][4], b[8][2];
#pragma unroll
        for (int mi = 0; mi < 2; mi++) {
            const __half* ap = A + (size_t)(mbase + mi * 16 + g) * NC + k0 + ig2;
            a[mi][0] = *(const unsigned*)ap;
            a[mi][1] = *(const unsigned*)(ap + 8 * NC);
            a[mi][2] = *(const unsigned*)(ap + 8);
            a[mi][3] = *(const unsigned*)(ap + 8 * NC + 8);
        }
#pragma unroll
        for (int nj = 0; nj < 8; nj++) {
            const __half* bp = g_i2h16 + (size_t)(nbase + nj * 8 + g) * NC + k0 + ig2;
            b[nj][0] = *(const unsigned*)bp;
            b[nj][1] = *(const unsigned*)(bp + 8);
        }
#pragma unroll
        for (int mi = 0; mi < 2; mi++)
#pragma unroll
            for (int nj = 0; nj < 8; nj++)
                asm volatile(
                    "mma.sync.aligned.m16n8k16.row.col.f32.f16.f16.f32 "
                    "{%0,%1,%2,%3},{%4,%5,%6,%7},{%8,%9},{%0,%1,%2,%3};"
                    : "+f"(d[mi][nj][0]), "+f"(d[mi][nj][1]),
                      "+f"(d[mi][nj][2]), "+f"(d[mi][nj][3])
                    : "r"(a[mi][0]), "r"(a[mi][1]), "r"(a[mi][2]), "r"(a[mi][3]),
                      "r"(b[nj][0]), "r"(b[nj][1]));
    }
#pragma unroll
    for (int mi = 0; mi < 2; mi++) {
        int r = mbase + mi * 16 + g;
#pragma unroll
        for (int nj = 0; nj < 8; nj++) {
            int c = nbase + nj * 8 + ig2;
            *(__half2*)(g_fp16 + (size_t)r * HID + c) =
                __floats2half2_rn(d[mi][nj][0], d[mi][nj][1]);
            *(__half2*)(g_fp16 + (size_t)(r + 8) * HID + c) =
                __floats2half2_rn(d[mi][nj][2], d[mi][nj][3]);
        }
    }
}

// ---------------- GRU update (per-b CTA; tid = h) ----------------
__device__ __forceinline__ float gru_one(int b, int h,
                                         const float* __restrict__ gru_b_ih,
                                         const float* __restrict__ gru_b_hh)
{
    size_t base = (size_t)b * GRU3;
    float ir = __ldg(gru_b_ih + h);
    float iz = __ldg(gru_b_ih + HID + h);
    float in = __ldg(gru_b_ih + 2 * HID + h);
#pragma unroll
    for (int p = 0; p < 10; p++) {
        ir += __ldcg(&g_gip[p][base + h]);
        iz += __ldcg(&g_gip[p][base + HID + h]);
        in += __ldcg(&g_gip[p][base + 2 * HID + h]);
    }
    float hr = __ldg(gru_b_hh + h)           + __ldcg(&g_gh[0][base + h])           + __ldcg(&g_gh[1][base + h]);
    float hz = __ldg(gru_b_hh + HID + h)     + __ldcg(&g_gh[0][base + HID + h])     + __ldcg(&g_gh[1][base + HID + h]);
    float hn = __ldg(gru_b_hh + 2 * HID + h) + __ldcg(&g_gh[0][base + 2 * HID + h]) + __ldcg(&g_gh[1][base + 2 * HID + h]);
    float rr = fsig(ir + hr);
    float zz = fsig(iz + hz);
    float nn = ftanh(in + rr * hn);
    float hold = __ldcg(&g_hidden[(size_t)b * HID + h]);
    return (1.f - zz) * nn + zz * hold;
}

// ---------------- persistent decode kernel ----------------
__global__ __launch_bounds__(256, 4) void decode_kernel(
    const float* __restrict__ pose,
    const float* __restrict__ pyr0,
    const float* __restrict__ pyr1,
    const float* __restrict__ pyr2,
    const int*   __restrict__ text,
    const float* __restrict__ h2h_b,
    const float* __restrict__ score_w,
    const float* __restrict__ pose_w,   const float* __restrict__ pose_b,
    const float* __restrict__ gru_b_ih, const float* __restrict__ gru_b_hh,
    const float* __restrict__ char_emb,
    const float* __restrict__ gen_w,    const float* __restrict__ gen_b,
    float* __restrict__ out)
{
    __shared__ __align__(16) float sm[4352];
    __shared__ float s_coord[4];
    __shared__ float s_ly[3][2], s_lx[3][2];
    __shared__ int   s_y0[3][2], s_y1[3][2], s_x0[3][2], s_x1[3][2];
    __shared__ int   s_vy[3][2], s_vx[3][2];

    const int tid = threadIdx.x;
    const int bid = blockIdx.x;
    const int lane = tid & 31;
    const int wid = tid >> 5;

    float* h_s   = sm;          // 256
    float* hp_s  = sm + 256;    // 256
    float* al    = sm + 512;    // 128
    float* ctx_s = sm + 640;    // 768
    float* red   = sm + 1408;   // 2048

    // ---- prologue: hidden init, pose transpose ----
    if (bid < 256) {
        g_hidden[bid * 256 + tid] = 0.f;
        g_hidden16[bid * 256 + tid] = __float2half(0.f);
    }
    for (int job = bid; job < NB * 32; job += NCTA) {
        int b = job >> 5;
        int r = job & 31;
        int t0 = (r & 3) * 32;
        int p0 = (r >> 2) * 32;
        int y = tid >> 5, x = tid & 31;
#pragma unroll
        for (int q = 0; q < 4; q++) {
            int yy = y + q * 8;
            sm[yy * 33 + x] = __ldg(pose + ((size_t)b * POSE + (p0 + yy)) * NT + (t0 + x));
        }
        __syncthreads();
#pragma unroll
        for (int q = 0; q < 4; q++) {
            int yy = y + q * 8;
            g_pose16T[((size_t)(t0 + yy) * NB + b) * POSE + (p0 + x)] =
                __float2half(sm[x * 33 + yy]);
        }
        __syncthreads();
    }
    gbar();

    for (int step = 0; step < NSTEPS; step++) {
        // ================= A: per-b CTA (256) =================
        if (bid < NB) {
            int b = bid;
            int tgt = (step == 0) ? 0 : (__ldg(text + b * NSTEPS + step - 1) + 1);
            if (tid < EMB)
                g_x16[(size_t)b * RNN_IN + 768 + tid] =
                    __float2half(__ldg(char_emb + (size_t)tgt * EMB + tid));

            if (step > 0) {
                float hnew = gru_one(b, tid, gru_b_ih, gru_b_hh);
                g_hidden[(size_t)b * HID + tid] = hnew;
                g_hidden16[(size_t)b * HID + tid] = __float2half(hnew);
                g_hs[((size_t)b * NSTEPS + step - 1) * HID + tid] = hnew;
                h_s[tid] = hnew;
                __syncthreads();
                const uint4* w4 = (const uint4*)(g_h2h16 + (size_t)tid * HID);
                float acc = 0.f;
#pragma unroll 8
                for (int q = 0; q < 32; q++) {
                    uint4 u = __ldg(w4 + q);
                    const __half2* hh = (const __half2*)&u;
                    int bb = q * 8;
                    float2 f0 = __half22float2(hh[0]);
                    float2 f1 = __half22float2(hh[1]);
                    float2 f2 = __half22float2(hh[2]);
                    float2 f3 = __half22float2(hh[3]);
                    acc += f0.x * h_s[bb]     + f0.y * h_s[bb + 1]
                         + f1.x * h_s[bb + 2] + f1.y * h_s[bb + 3]
                         + f2.x * h_s[bb + 4] + f2.y * h_s[bb + 5]
                         + f3.x * h_s[bb + 6] + f3.y * h_s[bb + 7];
                }
                hp_s[tid] = acc + __ldg(h2h_b + tid);
            } else {
                hp_s[tid] = __ldg(h2h_b + tid);
            }
            __syncthreads();

            // energy
            {
                float4 hpa = *(const float4*)&hp_s[lane * 8];
                float4 hpb = *(const float4*)&hp_s[lane * 8 + 4];
                __half2 hph[4] = {
                    __floats2half2_rn(hpa.x, hpa.y), __floats2half2_rn(hpa.z, hpa.w),
                    __floats2half2_rn(hpb.x, hpb.y), __floats2half2_rn(hpb.z, hpb.w)};
                float4 swa = __ldg((const float4*)(score_w + lane * 8));
                float4 swb = __ldg((const float4*)(score_w + lane * 8 + 4));
                float swf[8] = {swa.x, swa.y, swa.z, swa.w, swb.x, swb.y, swb.z, swb.w};
#pragma unroll
                for (int i = 0; i < 16; i++) {
                    int t = wid * 16 + i;
                    uint4 fv = __ldg((const uint4*)(g_fp16 + ((size_t)t * NB + b) * HID + lane * 8));
                    __half2 v0 = *(__half2*)&fv.x, v1 = *(__half2*)&fv.y;
                    __half2 v2 = *(__half2*)&fv.z, v3 = *(__half2*)&fv.w;
                    float2 t0 = __half22float2(htanh2(__hadd2(v0, hph[0])));
                    float2 t1 = __half22float2(htanh2(__hadd2(v1, hph[1])));
                    float2 t2 = __half22float2(htanh2(__hadd2(v2, hph[2])));
                    float2 t3 = __half22float2(htanh2(__hadd2(v3, hph[3])));
                    float s = t0.x * swf[0] + t0.y * swf[1] + t1.x * swf[2] + t1.y * swf[3]
                            + t2.x * swf[4] + t2.y * swf[5] + t3.x * swf[6] + t3.y * swf[7];
#pragma unroll
                    for (int o = 16; o; o >>= 1) s += __shfl_xor_sync(~0u, s, o);
                    if (!lane) al[t] = s;
                }
            }
            __syncthreads();
            if (wid == 0) {
                float ev[4];
#pragma unroll
                for (int q = 0; q < 4; q++) ev[q] = al[lane + 32 * q];
                float mx = fmaxf(fmaxf(ev[0], ev[1]), fmaxf(ev[2], ev[3]));
#pragma unroll
                for (int o = 16; o; o >>= 1) mx = fmaxf(mx, __shfl_xor_sync(~0u, mx, o));
                float ex[4], ssum = 0.f;
#pragma unroll
                for (int q = 0; q < 4; q++) { ex[q] = __expf(ev[q] - mx); ssum += ex[q]; }
#pragma unroll
                for (int o = 16; o; o >>= 1) ssum += __shfl_xor_sync(~0u, ssum, o);
                float inv = __fdividef(1.f, ssum);
#pragma unroll
                for (int q = 0; q < 4; q++) al[lane + 32 * q] = ex[q] * inv;
            }
            __syncthreads();
            // ctx feats
            {
                int tq = tid >> 6, cg = tid & 63;
                float acc[8] = {};
                int t0 = tq * 32;
#pragma unroll 8
                for (int i = 0; i < 32; i++) {
                    int t = t0 + i;
                    uint4 u = __ldg((const uint4*)(g_feats16 + ((size_t)t * NB + b) * (NC / 2)) + cg);
                    float a = al[t];
                    const __half2* h2 = (const __half2*)&u;
#pragma unroll
                    for (int q = 0; q < 4; q++) {
                        float2 f = __half22float2(h2[q]);
                        acc[2 * q]     = fmaf(a, f.x, acc[2 * q]);
                        acc[2 * q + 1] = fmaf(a, f.y, acc[2 * q + 1]);
                    }
                }
#pragma unroll
                for (int q = 0; q < 8; q++) red[tq * 512 + cg * 8 + q] = acc[q];
            }
            __syncthreads();
            {
                int c = tid * 2;
                float s0 = red[c] + red[512 + c] + red[1024 + c] + red[1536 + c];
                float s1 = red[c + 1] + red[512 + c + 1] + red[1024 + c + 1] + red[1536 + c + 1];
                ctx_s[c] = s0; ctx_s[c + 1] = s1;
                *(__half2*)(g_x16 + (size_t)b * RNN_IN + c) = __floats2half2_rn(s0, s1);
            }
            __syncthreads();
            // ctx pose
            {
                int tq2 = tid >> 5, cg2 = tid & 31;
                float acc[8] = {};
                int t0 = tq2 * 16;
#pragma unroll 8
                for (int i = 0; i < 16; i++) {
                    int t = t0 + i;
                    uint4 u = __ldg((const uint4*)(g_pose16T + ((size_t)t * NB + b) * POSE) + cg2);
                    float a = al[t];
                    const __half2* h2 = (const __half2*)&u;
#pragma unroll
                    for (int q = 0; q < 4; q++) {
                        float2 f = __half22float2(h2[q]);
                        acc[2 * q]     = fmaf(a, f.x, acc[2 * q]);
                        acc[2 * q + 1] = fmaf(a, f.y, acc[2 * q + 1]);
                    }
                }
#pragma unroll
                for (int q = 0; q < 8; q++) red[tq2 * 256 + cg2 * 8 + q] = acc[q];
            }
            __syncthreads();
            {
                int c = tid;
                float s = 0.f;
#pragma unroll
                for (int q = 0; q < 8; q++) s += red[q * 256 + c];
                ctx_s[NC + c] = s;
                g_x16[(size_t)b * RNN_IN + NC + c] = __float2half(s);
            }
            __syncthreads();
            // coord
            if (wid < 4) {
                const float* pw = pose_w + wid * 768;
                float s = 0.f;
#pragma unroll
                for (int q = 0; q < 24; q++) { int c = lane + q * 32; s += ctx_s[c] * __ldg(pw + c); }
#pragma unroll
                for (int o = 16; o; o >>= 1) s += __shfl_xor_sync(~0u, s, o);
                if (!lane) s_coord[wid] = fsig(s + __ldg(pose_b + wid));
            }
            __syncthreads();
            if (tid == 0) {
                const int Hs[3] = {16, 8, 4};
                const int Ws[3] = {128, 64, 65};
                float c0 = s_coord[0], c1 = s_coord[1], c2 = s_coord[2], c3 = s_coord[3];
                for (int p = 0; p < 3; p++) {
                    float Hf = (float)Hs[p], Wf = (float)Ws[p];
                    c0 *= Hf; c1 *= Wf; c2 *= Hf; c3 *= Wf;
                    float x1 = c0, y1 = c1, x2 = c2, y2 = c3;
                    float bw = fmaxf(x2 - x1, 1.f) * 0.5f;
                    float bh = fmaxf(y2 - y1, 1.f) * 0.5f;
#pragma unroll
                    for (int i = 0; i < 2; i++) {
                        float ys = y1 + (0.5f + (float)i) * bh;
                        s_vy[p][i] = (ys >= -1.f && ys <= Hf) ? 1 : 0;
                        float y = fminf(fmaxf(ys, 0.f), Hf - 1.f);
                        float y0f = floorf(y);
                        int y0i = (int)y0f;
                        s_y0[p][i] = y0i;
                        s_y1[p][i] = min(y0i + 1, Hs[p] - 1);
                        s_ly[p][i] = y - y0f;
                        float xs = x1 + (0.5f + (float)i) * bw;
                        s_vx[p][i] = (xs >= -1.f && xs <= Wf) ? 1 : 0;
                        float x = fminf(fmaxf(xs, 0.f), Wf - 1.f);
                        float x0f = floorf(x);
                        int x0i = (int)x0f;
                        s_x0[p][i] = x0i;
                        s_x1[p][i] = min(x0i + 1, Ws[p] - 1);
                        s_lx[p][i] = x - x0f;
                    }
                }
            }
            __syncthreads();
            for (int o = tid; o < 576; o += 256) {
                int p, local;
                if (o < 64)       { p = 0; local = o; }
                else if (o < 320) { p = 1; local = o - 64; }
                else              { p = 2; local = o - 320; }
                int c = local >> 2;
                int ij = local & 3;
                int i = ij >> 1, j = ij & 1;
                float val = 0.f;
                if (s_vy[p][i] && s_vx[p][j]) {
                    float ly = s_ly[p][i], lx = s_lx[p][j];
                    float hy = 1.f - ly, hx = 1.f - lx;
                    int y0 = s_y0[p][i], y1 = s_y1[p][i];
                    int x0 = s_x0[p][j], x1 = s_x1[p][j];
                    const float* f; int W, HW;
                    if (p == 0)      { f = pyr0; W = 128; HW = 16 * 128; }
                    else if (p == 1) { f = pyr1; W = 64;  HW = 8 * 64;  }
                    else             { f = pyr2; W = 65;  HW = 4 * 65;  }
                    const float* fc = f + (size_t)c * HW;
                    val = fc[y0 * W + x0] * (hy * hx)
                        + fc[y0 * W + x1] * (hy * lx)
                        + fc[y1 * W + x0] * (ly * hx)
                        + fc[y1 * W + x1] * (ly * lx);
                }
                g_x16[(size_t)b * RNN_IN + 896 + o] = __float2half(val);
            }
        }
        gbar();

        // ================= B: HMMA GEMMs (576 jobs) =================
        if (bid < 480) {
            const int kb[10] = {0, 160, 320, 480, 640, 768, 896, 1056, 1216, 1344};
            const int ki[10] = {5, 5, 5, 5, 4, 4, 5, 5, 4, 4};
            int ks = bid / 48, j = bid % 48;
            gemm64h(g_x16, RNN_IN, g_wih16, RNN_IN, g_gip[ks], GRU3,
                    (j / 12) * 64, (j % 12) * 64, kb[ks], ki[ks] * 2, tid);
        } else if (bid < 576) {
            int jj = bid - 480;
            int ks = jj / 48, j = jj % 48;
            gemm64h(g_hidden16, HID, g_whh16, HID, g_gh[ks], GRU3,
                    (j / 12) * 64, (j % 12) * 64, ks * 128, 8, tid);
        }
        gbar();
    }

    // ===== epilogue: final GRU =====
    if (bid < NB) {
        float hnew = gru_one(bid, tid, gru_b_ih, gru_b_hh);
        g_hs[((size_t)bid * NSTEPS + NSTEPS - 1) * HID + tid] = hnew;
    }
    gbar();

    // ===== final classifier =====
    {
        int gw = bid * 8 + wid;
        for (int m = gw; m < NB * NSTEPS; m += NWARP) {
            const float* hrow = g_hs + (size_t)m * HID;
            float a[8];
#pragma unroll
            for (int q = 0; q < 8; q++) a[q] = __ldcg(hrow + lane + q * 32);
            for (int n = 0; n < NCLS; n++) {
                const float* w = gen_w + (size_t)n * HID;
                float s = 0.f;
#pragma unroll
                for (int q = 0; q < 8; q++) s += a[q] * __ldg(w + lane + q * 32);
#pragma unroll
                for (int o = 16; o; o >>= 1) s += __shfl_xor_sync(~0u, s, o);
                if (!lane) out[(size_t)m * NCLS + n] = s + gen_b[n];
            }
        }
    }
}

// ---------------- driver ----------------
extern "C" void kernel_launch(void* const* d_in, const int* in_sizes, int n_in,
                              void* d_out, int out_size)
{
    const float* feats    = (const float*)d_in[0];
    const float* pose     = (const float*)d_in[1];
    const float* pyr0     = (const float*)d_in[2];
    const float* pyr1     = (const float*)d_in[3];
    const float* pyr2     = (const float*)d_in[4];
    const int*   text     = (const int*)  d_in[6];
    const float* i2h_w    = (const float*)d_in[7];
    const float* h2h_w    = (const float*)d_in[8];
    const float* h2h_b    = (const float*)d_in[9];
    const float* score_w  = (const float*)d_in[10];
    const float* pose_w   = (const float*)d_in[11];
    const float* pose_b   = (const float*)d_in[12];
    const float* gru_w_ih = (const float*)d_in[13];
    const float* gru_w_hh = (const float*)d_in[14];
    const float* gru_b_ih = (const float*)d_in[15];
    const float* gru_b_hh = (const float*)d_in[16];
    const float* char_emb = (const float*)d_in[17];
    const float* gen_w    = (const float*)d_in[18];
    const float* gen_b    = (const float*)d_in[19];
    float* out = (float*)d_out;

    convert_kernel<<<1024, 256>>>(feats, i2h_w, h2h_w, gru_w_ih, gru_w_hh);

    dim3 g1(2, 256);
    fp_gemm_hmma<<<g1, 256>>>();

    decode_kernel<<<NCTA, 256>>>(pose, pyr0, pyr1, pyr2, text,
                                 h2h_b, score_w, pose_w, pose_b,
                                 gru_b_ih, gru_b_hh,
                                 char_emb, gen_w, gen_b, out);
}

// round 10
// speedup vs baseline: 2.5500x; 1.0399x over previous
#include <cuda_runtime.h>
#include <cuda_fp16.h>
#include <math.h>

#define NT 128
#define NB 256
#define NC 512
#define HID 256
#define EMB 128
#define NCLS 37
#define NSTEPS 25
#define POSE 256
#define RNN_IN 1472
#define GRU3 768
#define NCTA 592
#define NWARP (NCTA * 8)

// ---------------- scratch ----------------
__device__ __align__(16) __half g_fp16[NT * NB * HID];
__device__ __align__(16) __half2 g_feats16[NT * NB * NC / 2];
__device__ __align__(16) __half  g_pose16T[NT * NB * POSE];
__device__ __align__(16) __half g_h2h16[HID * HID];
__device__ __align__(16) __half g_i2h16[HID * NC];
__device__ __align__(16) __half g_wih16[GRU3 * RNN_IN];
__device__ __align__(16) __half g_whh16[GRU3 * HID];
__device__ __align__(16) __half g_x16[NB * RNN_IN];
__device__ __align__(16) __half g_hidden16[NB * HID];
__device__ float g_gh[2][NB * GRU3];
__device__ float g_gip[10][NB * GRU3];
__device__ float g_hidden[NB * HID];
__device__ float g_hs[NSTEPS * NB * HID];

// barrier + dataflow counters (each counter on its own 128B line)
__device__ unsigned g_cnt[17 * 32];
__device__ unsigned g_rel[16 * 32];
__device__ unsigned g_rdy_h[4 * 32];
__device__ unsigned g_rdy_x[4 * 32];
__device__ unsigned g_rdy_gi[4 * 32];

// ---------------- sync primitives ----------------
__device__ __forceinline__ unsigned ld_acq(const unsigned* p) {
    unsigned v;
    asm volatile("ld.acquire.gpu.global.u32 %0,[%1];" : "=r"(v) : "l"(p) : "memory");
    return v;
}
__device__ __forceinline__ unsigned atom_inc_rel(unsigned* p) {
    unsigned v;
    asm volatile("atom.release.gpu.global.add.u32 %0,[%1],1;" : "=r"(v) : "l"(p) : "memory");
    return v;
}
__device__ __forceinline__ void st_rel(unsigned* p, unsigned v) {
    asm volatile("st.release.gpu.global.u32 [%0],%1;" :: "l"(p), "r"(v) : "memory");
}
__device__ __forceinline__ void spin_ge(const unsigned* p, unsigned tgt) {
    unsigned v = ld_acq(p);
    while ((int)(v - tgt) < 0) { __nanosleep(64); v = ld_acq(p); }
}
__device__ __forceinline__ void gbar() {
    __syncthreads();
    if (threadIdx.x == 0) {
        int g = blockIdx.x / 37;
        unsigned* cnt = &g_cnt[g * 32];
        unsigned* rel = &g_rel[g * 32];
        unsigned gen = ld_acq(rel);
        if (atom_inc_rel(cnt) == 36u) {
            *(volatile unsigned*)cnt = 0u;
            if (atom_inc_rel(&g_cnt[16 * 32]) == 15u) {
                *(volatile unsigned*)&g_cnt[16 * 32] = 0u;
#pragma unroll
                for (int i = 0; i < 16; i++) st_rel(&g_rel[i * 32], gen + 1u);
            } else {
                while (ld_acq(rel) == gen) __nanosleep(32);
            }
        } else {
            while (ld_acq(rel) == gen) __nanosleep(32);
        }
    }
    __syncthreads();
}

// ---------------- fast transcendentals ----------------
__device__ __forceinline__ float fsig(float x) {
    return __fdividef(1.f, 1.f + __expf(-x));
}
__device__ __forceinline__ float ftanh(float x) {
    float r;
    asm("tanh.approx.f32 %0,%1;" : "=f"(r) : "f"(x));
    return r;
}
__device__ __forceinline__ __half2 htanh2(__half2 x) {
    __half2 r;
    asm("tanh.approx.f16x2 %0,%1;" : "=r"(*(unsigned*)&r) : "r"(*(unsigned*)&x));
    return r;
}
__device__ __forceinline__ unsigned h2u(__half2 h) { return *(unsigned*)&h; }

// ---------------- HMMA 64x64 tile: C(f32) = A(f16)@B(f16)^T ----------------
__device__ __forceinline__ void gemm64h(const __half* __restrict__ A, int lda,
                                        const __half* __restrict__ B, int ldb,
                                        float* __restrict__ C, int ldc,
                                        int m0, int n0, int kbase, int ksteps,
                                        int tid)
{
    const int wid = tid >> 5, lane = tid & 31;
    const int g = lane >> 2, ig2 = (lane & 3) * 2;
    const int mb = m0 + (wid >> 2) * 32;
    const int nb = n0 + (wid & 3) * 16;
    float d[2][2][4] = {};
    for (int ks = 0; ks < ksteps; ks++) {
        int k0 = kbase + ks * 16;
        unsigned a[2][4], bf[2][2];
#pragma unroll
        for (int mi = 0; mi < 2; mi++) {
            const __half* ap = A + (size_t)(mb + mi * 16 + g) * lda + k0 + ig2;
            a[mi][0] = __ldcg((const unsigned*)ap);
            a[mi][1] = __ldcg((const unsigned*)(ap + 8 * lda));
            a[mi][2] = __ldcg((const unsigned*)(ap + 8));
            a[mi][3] = __ldcg((const unsigned*)(ap + 8 * lda + 8));
        }
#pragma unroll
        for (int nj = 0; nj < 2; nj++) {
            const __half* bp = B + (size_t)(nb + nj * 8 + g) * ldb + k0 + ig2;
            bf[nj][0] = __ldg((const unsigned*)bp);
            bf[nj][1] = __ldg((const unsigned*)(bp + 8));
        }
#pragma unroll
        for (int mi = 0; mi < 2; mi++)
#pragma unroll
            for (int nj = 0; nj < 2; nj++)
                asm volatile(
                    "mma.sync.aligned.m16n8k16.row.col.f32.f16.f16.f32 "
                    "{%0,%1,%2,%3},{%4,%5,%6,%7},{%8,%9},{%0,%1,%2,%3};"
                    : "+f"(d[mi][nj][0]), "+f"(d[mi][nj][1]),
                      "+f"(d[mi][nj][2]), "+f"(d[mi][nj][3])
                    : "r"(a[mi][0]), "r"(a[mi][1]), "r"(a[mi][2]), "r"(a[mi][3]),
                      "r"(bf[nj][0]), "r"(bf[nj][1]));
    }
#pragma unroll
    for (int mi = 0; mi < 2; mi++) {
        int r = mb + mi * 16 + g;
#pragma unroll
        for (int nj = 0; nj < 2; nj++) {
            int c = nb + nj * 8 + ig2;
            float2 v0 = {d[mi][nj][0], d[mi][nj][1]};
            float2 v1 = {d[mi][nj][2], d[mi][nj][3]};
            *(float2*)(C + (size_t)r * ldc + c) = v0;
            *(float2*)(C + (size_t)(r + 8) * ldc + c) = v1;
        }
    }
}

// ---------------- convert inputs to fp16 (vectorized) ----------------
__device__ __forceinline__ void cvt4(const float* __restrict__ src,
                                     __half* __restrict__ dst, int n4,
                                     int i, int stride)
{
    const float4* s4 = (const float4*)src;
    uint2* d2 = (uint2*)dst;
    for (int j = i; j < n4; j += stride) {
        float4 v = __ldg(s4 + j);
        uint2 u;
        u.x = h2u(__floats2half2_rn(v.x, v.y));
        u.y = h2u(__floats2half2_rn(v.z, v.w));
        d2[j] = u;
    }
}
__global__ __launch_bounds__(256) void convert_kernel(const float* __restrict__ feats,
                                                      const float* __restrict__ i2h_w,
                                                      const float* __restrict__ h2h_w,
                                                      const float* __restrict__ gru_w_ih,
                                                      const float* __restrict__ gru_w_hh)
{
    int i = blockIdx.x * 256 + threadIdx.x;
    int stride = gridDim.x * 256;
    cvt4(feats, (__half*)g_feats16, NT * NB * NC / 4, i, stride);
    cvt4(i2h_w, g_i2h16, HID * NC / 4, i, stride);
    cvt4(h2h_w, g_h2h16, HID * HID / 4, i, stride);
    cvt4(gru_w_ih, g_wih16, GRU3 * RNN_IN / 4, i, stride);
    cvt4(gru_w_hh, g_whh16, GRU3 * HID / 4, i, stride);
}

// ---------------- feats_proj via HMMA ----------------
__global__ __launch_bounds__(256) void fp_gemm_hmma()
{
    const int tid = threadIdx.x;
    const int wid = tid >> 5, lane = tid & 31;
    const int g = lane >> 2, ig2 = (lane & 3) * 2;
    const int warp_m = wid >> 1, warp_n = wid & 1;
    const int mbase = blockIdx.y * 128 + warp_m * 32;
    const int nbase = blockIdx.x * 128 + warp_n * 64;
    const __half* A = (const __half*)g_feats16;

    float d[2][8][4] = {};
    for (int k0 = 0; k0 < NC; k0 += 16) {
        unsigned a[2][4], b[8][2];
#pragma unroll
        for (int mi = 0; mi < 2; mi++) {
            const __half* ap = A + (size_t)(mbase + mi * 16 + g) * NC + k0 + ig2;
            a[mi][0] = *(const unsigned*)ap;
            a[mi][1] = *(const unsigned*)(ap + 8 * NC);
            a[mi][2] = *(const unsigned*)(ap + 8);
            a[mi][3] = *(const unsigned*)(ap + 8 * NC + 8);
        }
#pragma unroll
        for (int nj = 0; nj < 8; nj++) {
            const __half* bp = g_i2h16 + (size_t)(nbase + nj * 8 + g) * NC + k0 + ig2;
            b[nj][0] = *(const unsigned*)bp;
            b[nj][1] = *(const unsigned*)(bp + 8);
        }
#pragma unroll
        for (int mi = 0; mi < 2; mi++)
#pragma unroll
            for (int nj = 0; nj < 8; nj++)
                asm volatile(
                    "mma.sync.aligned.m16n8k16.row.col.f32.f16.f16.f32 "
                    "{%0,%1,%2,%3},{%4,%5,%6,%7},{%8,%9},{%0,%1,%2,%3};"
                    : "+f"(d[mi][nj][0]), "+f"(d[mi][nj][1]),
                      "+f"(d[mi][nj][2]), "+f"(d[mi][nj][3])
                    : "r"(a[mi][0]), "r"(a[mi][1]), "r"(a[mi][2]), "r"(a[mi][3]),
                      "r"(b[nj][0]), "r"(b[nj][1]));
    }
#pragma unroll
    for (int mi = 0; mi < 2; mi++) {
        int r = mbase + mi * 16 + g;
#pragma unroll
        for (int nj = 0; nj < 8; nj++) {
            int c = nbase + nj * 8 + ig2;
            *(__half2*)(g_fp16 + (size_t)r * HID + c) =
                __floats2half2_rn(d[mi][nj][0], d[mi][nj][1]);
            *(__half2*)(g_fp16 + (size_t)(r + 8) * HID + c) =
                __floats2half2_rn(d[mi][nj][2], d[mi][nj][3]);
        }
    }
}

// ---------------- GRU update (per-b CTA; tid = h) ----------------
__device__ __forceinline__ float gru_one(int b, int h,
                                         const float* __restrict__ gru_b_ih,
                                         const float* __restrict__ gru_b_hh)
{
    size_t base = (size_t)b * GRU3;
    float ir = __ldg(gru_b_ih + h);
    float iz = __ldg(gru_b_ih + HID + h);
    float in = __ldg(gru_b_ih + 2 * HID + h);
#pragma unroll
    for (int p = 0; p < 10; p++) {
        ir += __ldcg(&g_gip[p][base + h]);
        iz += __ldcg(&g_gip[p][base + HID + h]);
        in += __ldcg(&g_gip[p][base + 2 * HID + h]);
    }
    float hr = __ldg(gru_b_hh + h)           + __ldcg(&g_gh[0][base + h])           + __ldcg(&g_gh[1][base + h]);
    float hz = __ldg(gru_b_hh + HID + h)     + __ldcg(&g_gh[0][base + HID + h])     + __ldcg(&g_gh[1][base + HID + h]);
    float hn = __ldg(gru_b_hh + 2 * HID + h) + __ldcg(&g_gh[0][base + 2 * HID + h]) + __ldcg(&g_gh[1][base + 2 * HID + h]);
    float rr = fsig(ir + hr);
    float zz = fsig(iz + hz);
    float nn = ftanh(in + rr * hn);
    float hold = __ldcg(&g_hidden[(size_t)b * HID + h]);
    return (1.f - zz) * nn + zz * hold;
}

// ---------------- B-CTA GEMM job ----------------
__device__ __forceinline__ void run_job(int j, int step, int tid)
{
    if (j < 480) {
        const int kb[10] = {0, 160, 320, 480, 640, 768, 896, 1056, 1216, 1344};
        const int ki[10] = {10, 10, 10, 10, 8, 8, 10, 10, 8, 8};
        int ks = j / 48, r = j % 48, mt = r / 12, nt = r % 12;
        if (tid == 0) spin_ge(&g_rdy_x[mt * 32], 64u * (step + 1));
        __syncthreads();
        gemm64h(g_x16, RNN_IN, g_wih16, RNN_IN, g_gip[ks], GRU3,
                mt * 64, nt * 64, kb[ks], ki[ks], tid);
        __syncthreads();
        if (tid == 0) atom_inc_rel(&g_rdy_gi[mt * 32]);
    } else {
        int jj = j - 480;
        int ks = jj / 48, r = jj % 48, mt = r / 12, nt = r % 12;
        if (tid == 0) spin_ge(&g_rdy_h[mt * 32], 64u * (step + 1));
        __syncthreads();
        gemm64h(g_hidden16, HID, g_whh16, HID, g_gh[ks], GRU3,
                mt * 64, nt * 64, ks * 128, 8, tid);
        __syncthreads();
        if (tid == 0) atom_inc_rel(&g_rdy_gi[mt * 32]);
    }
}

// ---------------- persistent decode kernel ----------------
__global__ __launch_bounds__(256, 4) void decode_kernel(
    const float* __restrict__ pose,
    const float* __restrict__ pyr0,
    const float* __restrict__ pyr1,
    const float* __restrict__ pyr2,
    const int*   __restrict__ text,
    const float* __restrict__ h2h_b,
    const float* __restrict__ score_w,
    const float* __restrict__ pose_w,   const float* __restrict__ pose_b,
    const float* __restrict__ gru_b_ih, const float* __restrict__ gru_b_hh,
    const float* __restrict__ char_emb,
    const float* __restrict__ gen_w,    const float* __restrict__ gen_b,
    float* __restrict__ out)
{
    __shared__ __align__(16) float sm[4352];
    __shared__ float s_coord[4];
    __shared__ float s_ly[3][2], s_lx[3][2];
    __shared__ int   s_y0[3][2], s_y1[3][2], s_x0[3][2], s_x1[3][2];
    __shared__ int   s_vy[3][2], s_vx[3][2];

    const int tid = threadIdx.x;
    const int bid = blockIdx.x;
    const int lane = tid & 31;
    const int wid = tid >> 5;

    float* h_s   = sm;
    float* hp_s  = sm + 256;
    float* al    = sm + 512;
    float* ctx_s = sm + 640;
    float* red   = sm + 1408;

    // ---- prologue: counters, hidden init, pose transpose ----
    if (bid == 0) {
        for (int i = tid; i < 4 * 32; i += 256) {
            g_rdy_h[i] = 0u; g_rdy_x[i] = 0u; g_rdy_gi[i] = 0u;
        }
    }
    if (bid < 256) {
        g_hidden[bid * 256 + tid] = 0.f;
        g_hidden16[bid * 256 + tid] = __float2half(0.f);
    }
    for (int job = bid; job < NB * 32; job += NCTA) {
        int b = job >> 5;
        int r = job & 31;
        int t0 = (r & 3) * 32;
        int p0 = (r >> 2) * 32;
        int y = tid >> 5, x = tid & 31;
#pragma unroll
        for (int q = 0; q < 4; q++) {
            int yy = y + q * 8;
            sm[yy * 33 + x] = __ldg(pose + ((size_t)b * POSE + (p0 + yy)) * NT + (t0 + x));
        }
        __syncthreads();
#pragma unroll
        for (int q = 0; q < 4; q++) {
            int yy = y + q * 8;
            g_pose16T[((size_t)(t0 + yy) * NB + b) * POSE + (p0 + x)] =
                __float2half(sm[x * 33 + yy]);
        }
        __syncthreads();
    }
    gbar();

    if (bid < NB) {
        // ================= A-CTA: full recurrence for b = bid =================
        const int b = bid;
        const int mt = b >> 6;
        for (int step = 0; step < NSTEPS; step++) {
            if (step > 0) {
                if (tid == 0) spin_ge(&g_rdy_gi[mt * 32], 144u * (unsigned)step);
                __syncthreads();
                float hnew = gru_one(b, tid, gru_b_ih, gru_b_hh);
                g_hidden[(size_t)b * HID + tid] = hnew;
                g_hidden16[(size_t)b * HID + tid] = __float2half(hnew);
                g_hs[((size_t)b * NSTEPS + step - 1) * HID + tid] = hnew;
                h_s[tid] = hnew;
                __syncthreads();
                if (tid == 0) atom_inc_rel(&g_rdy_h[mt * 32]);
                const uint4* w4 = (const uint4*)(g_h2h16 + (size_t)tid * HID);
                float acc = 0.f;
#pragma unroll 8
                for (int q = 0; q < 32; q++) {
                    uint4 u = __ldg(w4 + q);
                    const __half2* hh = (const __half2*)&u;
                    int bb = q * 8;
                    float2 f0 = __half22float2(hh[0]);
                    float2 f1 = __half22float2(hh[1]);
                    float2 f2 = __half22float2(hh[2]);
                    float2 f3 = __half22float2(hh[3]);
                    acc += f0.x * h_s[bb]     + f0.y * h_s[bb + 1]
                         + f1.x * h_s[bb + 2] + f1.y * h_s[bb + 3]
                         + f2.x * h_s[bb + 4] + f2.y * h_s[bb + 5]
                         + f3.x * h_s[bb + 6] + f3.y * h_s[bb + 7];
                }
                hp_s[tid] = acc + __ldg(h2h_b + tid);
            } else {
                hp_s[tid] = __ldg(h2h_b + tid);
                if (tid == 0) atom_inc_rel(&g_rdy_h[mt * 32]);
            }
            __syncthreads();

            // emb (safe: previous-step consumers finished per gi-counter spin)
            int tgt = (step == 0) ? 0 : (__ldg(text + b * NSTEPS + step - 1) + 1);
            if (tid < EMB)
                g_x16[(size_t)b * RNN_IN + 768 + tid] =
                    __float2half(__ldg(char_emb + (size_t)tgt * EMB + tid));

            // energy
            {
                float4 hpa = *(const float4*)&hp_s[lane * 8];
                float4 hpb = *(const float4*)&hp_s[lane * 8 + 4];
                __half2 hph[4] = {
                    __floats2half2_rn(hpa.x, hpa.y), __floats2half2_rn(hpa.z, hpa.w),
                    __floats2half2_rn(hpb.x, hpb.y), __floats2half2_rn(hpb.z, hpb.w)};
                float4 swa = __ldg((const float4*)(score_w + lane * 8));
                float4 swb = __ldg((const float4*)(score_w + lane * 8 + 4));
                float swf[8] = {swa.x, swa.y, swa.z, swa.w, swb.x, swb.y, swb.z, swb.w};
#pragma unroll
                for (int i = 0; i < 16; i++) {
                    int t = wid * 16 + i;
                    uint4 fv = __ldg((const uint4*)(g_fp16 + ((size_t)t * NB + b) * HID + lane * 8));
                    __half2 v0 = *(__half2*)&fv.x, v1 = *(__half2*)&fv.y;
                    __half2 v2 = *(__half2*)&fv.z, v3 = *(__half2*)&fv.w;
                    float2 t0 = __half22float2(htanh2(__hadd2(v0, hph[0])));
                    float2 t1 = __half22float2(htanh2(__hadd2(v1, hph[1])));
                    float2 t2 = __half22float2(htanh2(__hadd2(v2, hph[2])));
                    float2 t3 = __half22float2(htanh2(__hadd2(v3, hph[3])));
                    float s = t0.x * swf[0] + t0.y * swf[1] + t1.x * swf[2] + t1.y * swf[3]
                            + t2.x * swf[4] + t2.y * swf[5] + t3.x * swf[6] + t3.y * swf[7];
#pragma unroll
                    for (int o = 16; o; o >>= 1) s += __shfl_xor_sync(~0u, s, o);
                    if (!lane) al[t] = s;
                }
            }
            __syncthreads();
            if (wid == 0) {
                float ev[4];
#pragma unroll
                for (int q = 0; q < 4; q++) ev[q] = al[lane + 32 * q];
                float mx = fmaxf(fmaxf(ev[0], ev[1]), fmaxf(ev[2], ev[3]));
#pragma unroll
                for (int o = 16; o; o >>= 1) mx = fmaxf(mx, __shfl_xor_sync(~0u, mx, o));
                float ex[4], ssum = 0.f;
#pragma unroll
                for (int q = 0; q < 4; q++) { ex[q] = __expf(ev[q] - mx); ssum += ex[q]; }
#pragma unroll
                for (int o = 16; o; o >>= 1) ssum += __shfl_xor_sync(~0u, ssum, o);
                float inv = __fdividef(1.f, ssum);
#pragma unroll
                for (int q = 0; q < 4; q++) al[lane + 32 * q] = ex[q] * inv;
            }
            __syncthreads();
            // ctx feats
            {
                int tq = tid >> 6, cg = tid & 63;
                float acc[8] = {};
                int t0 = tq * 32;
#pragma unroll 8
                for (int i = 0; i < 32; i++) {
                    int t = t0 + i;
                    uint4 u = __ldg((const uint4*)(g_feats16 + ((size_t)t * NB + b) * (NC / 2)) + cg);
                    float a = al[t];
                    const __half2* h2 = (const __half2*)&u;
#pragma unroll
                    for (int q = 0; q < 4; q++) {
                        float2 f = __half22float2(h2[q]);
                        acc[2 * q]     = fmaf(a, f.x, acc[2 * q]);
                        acc[2 * q + 1] = fmaf(a, f.y, acc[2 * q + 1]);
                    }
                }
#pragma unroll
                for (int q = 0; q < 8; q++) red[tq * 512 + cg * 8 + q] = acc[q];
            }
            __syncthreads();
            {
                int c = tid * 2;
                float s0 = red[c] + red[512 + c] + red[1024 + c] + red[1536 + c];
                float s1 = red[c + 1] + red[512 + c + 1] + red[1024 + c + 1] + red[1536 + c + 1];
                ctx_s[c] = s0; ctx_s[c + 1] = s1;
                *(__half2*)(g_x16 + (size_t)b * RNN_IN + c) = __floats2half2_rn(s0, s1);
            }
            __syncthreads();
            // ctx pose
            {
                int tq2 = tid >> 5, cg2 = tid & 31;
                float acc[8] = {};
                int t0 = tq2 * 16;
#pragma unroll 8
                for (int i = 0; i < 16; i++) {
                    int t = t0 + i;
                    uint4 u = __ldg((const uint4*)(g_pose16T + ((size_t)t * NB + b) * POSE) + cg2);
                    float a = al[t];
                    const __half2* h2 = (const __half2*)&u;
#pragma unroll
                    for (int q = 0; q < 4; q++) {
                        float2 f = __half22float2(h2[q]);
                        acc[2 * q]     = fmaf(a, f.x, acc[2 * q]);
                        acc[2 * q + 1] = fmaf(a, f.y, acc[2 * q + 1]);
                    }
                }
#pragma unroll
                for (int q = 0; q < 8; q++) red[tq2 * 256 + cg2 * 8 + q] = acc[q];
            }
            __syncthreads();
            {
                int c = tid;
                float s = 0.f;
#pragma unroll
                for (int q = 0; q < 8; q++) s += red[q * 256 + c];
                ctx_s[NC + c] = s;
                g_x16[(size_t)b * RNN_IN + NC + c] = __float2half(s);
            }
            __syncthreads();
            // coord
            if (wid < 4) {
                const float* pw = pose_w + wid * 768;
                float s = 0.f;
#pragma unroll
                for (int q = 0; q < 24; q++) { int c = lane + q * 32; s += ctx_s[c] * __ldg(pw + c); }
#pragma unroll
                for (int o = 16; o; o >>= 1) s += __shfl_xor_sync(~0u, s, o);
                if (!lane) s_coord[wid] = fsig(s + __ldg(pose_b + wid));
            }
            __syncthreads();
            if (tid == 0) {
                const int Hs[3] = {16, 8, 4};
                const int Ws[3] = {128, 64, 65};
                float c0 = s_coord[0], c1 = s_coord[1], c2 = s_coord[2], c3 = s_coord[3];
                for (int p = 0; p < 3; p++) {
                    float Hf = (float)Hs[p], Wf = (float)Ws[p];
                    c0 *= Hf; c1 *= Wf; c2 *= Hf; c3 *= Wf;
                    float x1 = c0, y1 = c1, x2 = c2, y2 = c3;
                    float bw = fmaxf(x2 - x1, 1.f) * 0.5f;
                    float bh = fmaxf(y2 - y1, 1.f) * 0.5f;
#pragma unroll
                    for (int i = 0; i < 2; i++) {
                        float ys = y1 + (0.5f + (float)i) * bh;
                        s_vy[p][i] = (ys >= -1.f && ys <= Hf) ? 1 : 0;
                        float y = fminf(fmaxf(ys, 0.f), Hf - 1.f);
                        float y0f = floorf(y);
                        int y0i = (int)y0f;
                        s_y0[p][i] = y0i;
                        s_y1[p][i] = min(y0i + 1, Hs[p] - 1);
                        s_ly[p][i] = y - y0f;
                        float xs = x1 + (0.5f + (float)i) * bw;
                        s_vx[p][i] = (xs >= -1.f && xs <= Wf) ? 1 : 0;
                        float x = fminf(fmaxf(xs, 0.f), Wf - 1.f);
                        float x0f = floorf(x);
                        int x0i = (int)x0f;
                        s_x0[p][i] = x0i;
                        s_x1[p][i] = min(x0i + 1, Ws[p] - 1);
                        s_lx[p][i] = x - x0f;
                    }
                }
            }
            __syncthreads();
            for (int o = tid; o < 576; o += 256) {
                int p, local;
                if (o < 64)       { p = 0; local = o; }
                else if (o < 320) { p = 1; local = o - 64; }
                else              { p = 2; local = o - 320; }
                int c = local >> 2;
                int ij = local & 3;
                int i = ij >> 1, j = ij & 1;
                float val = 0.f;
                if (s_vy[p][i] && s_vx[p][j]) {
                    float ly = s_ly[p][i], lx = s_lx[p][j];
                    float hy = 1.f - ly, hx = 1.f - lx;
                    int y0 = s_y0[p][i], y1 = s_y1[p][i];
                    int x0 = s_x0[p][j], x1 = s_x1[p][j];
                    const float* f; int W, HW;
                    if (p == 0)      { f = pyr0; W = 128; HW = 16 * 128; }
                    else if (p == 1) { f = pyr1; W = 64;  HW = 8 * 64;  }
                    else             { f = pyr2; W = 65;  HW = 4 * 65;  }
                    const float* fc = f + (size_t)c * HW;
                    val = fc[y0 * W + x0] * (hy * hx)
                        + fc[y0 * W + x1] * (hy * lx)
                        + fc[y1 * W + x0] * (ly * hx)
                        + fc[y1 * W + x1] * (ly * lx);
                }
                g_x16[(size_t)b * RNN_IN + 896 + o] = __float2half(val);
            }
            __syncthreads();
            if (tid == 0) atom_inc_rel(&g_rdy_x[mt * 32]);
        }
        // final GRU
        if (tid == 0) spin_ge(&g_rdy_gi[mt * 32], 144u * NSTEPS);
        __syncthreads();
        float hnew = gru_one(b, tid, gru_b_ih, gru_b_hh);
        g_hs[((size_t)b * NSTEPS + NSTEPS - 1) * HID + tid] = hnew;
    } else {
        // ================= B-CTA: 1-2 GEMM tiles per step =================
        int j1 = bid - 256;
        int j2 = j1 + 336;
        bool has2 = (j2 < 576);
        int ja = j1, jb = has2 ? j2 : -1;
        if (has2 && j2 >= 480) { ja = j2; jb = j1; }  // gh first (ready earlier)
        for (int step = 0; step < NSTEPS; step++) {
            run_job(ja, step, tid);
            if (jb >= 0) run_job(jb, step, tid);
        }
    }
    gbar();

    // ===== final classifier =====
    {
        int gw = bid * 8 + wid;
        for (int m = gw; m < NB * NSTEPS; m += NWARP) {
            const float* hrow = g_hs + (size_t)m * HID;
            float a[8];
#pragma unroll
            for (int q = 0; q < 8; q++) a[q] = __ldcg(hrow + lane + q * 32);
            for (int n = 0; n < NCLS; n++) {
                const float* w = gen_w + (size_t)n * HID;
                float s = 0.f;
#pragma unroll
                for (int q = 0; q < 8; q++) s += a[q] * __ldg(w + lane + q * 32);
#pragma unroll
                for (int o = 16; o; o >>= 1) s += __shfl_xor_sync(~0u, s, o);
                if (!lane) out[(size_t)m * NCLS + n] = s + gen_b[n];
            }
        }
    }
}

// ---------------- driver ----------------
extern "C" void kernel_launch(void* const* d_in, const int* in_sizes, int n_in,
                              void* d_out, int out_size)
{
    const float* feats    = (const float*)d_in[0];
    const float* pose     = (const float*)d_in[1];
    const float* pyr0     = (const float*)d_in[2];
    const float* pyr1     = (const float*)d_in[3];
    const float* pyr2     = (const float*)d_in[4];
    const int*   text     = (const int*)  d_in[6];
    const float* i2h_w    = (const float*)d_in[7];
    const float* h2h_w    = (const float*)d_in[8];
    const float* h2h_b    = (const float*)d_in[9];
    const float* score_w  = (const float*)d_in[10];
    const float* pose_w   = (const float*)d_in[11];
    const float* pose_b   = (const float*)d_in[12];
    const float* gru_w_ih = (const float*)d_in[13];
    const float* gru_w_hh = (const float*)d_in[14];
    const float* gru_b_ih = (const float*)d_in[15];
    const float* gru_b_hh = (const float*)d_in[16];
    const float* char_emb = (const float*)d_in[17];
    const float* gen_w    = (const float*)d_in[18];
    const float* gen_b    = (const float*)d_in[19];
    float* out = (float*)d_out;

    convert_kernel<<<592, 256>>>(feats, i2h_w, h2h_w, gru_w_ih, gru_w_hh);

    dim3 g1(2, 256);
    fp_gemm_hmma<<<g1, 256>>>();

    decode_kernel<<<NCTA, 256>>>(pose, pyr0, pyr1, pyr2, text,
                                 h2h_b, score_w, pose_w, pose_b,
                                 gru_b_ih, gru_b_hh,
                                 char_emb, gen_w, gen_b, out);
}